// round 1
// baseline (speedup 1.0000x reference)
#include <cuda_runtime.h>
#include <math.h>

#define N_NEWS  30000
#define N_INTER 60000
#define HID 128
#define NH  8
#define HD  16

// ---------------- scratch (static device globals; no allocation) ----------------
__device__ float g_h_news [N_NEWS  * HID];
__device__ float g_h_inter[N_INTER * HID];
__device__ float g_out_nn [N_NEWS  * HID];
__device__ float g_out_in [N_NEWS  * HID];
__device__ float g_asrc_nn[N_NEWS  * NH];
__device__ float g_adst_nn[N_NEWS  * NH];
__device__ float g_asrc_in[N_INTER * NH];
__device__ float g_adst_in[N_NEWS  * NH];
__device__ float g_m_nn  [N_NEWS * NH];
__device__ float g_den_nn[N_NEWS * NH];
__device__ float g_m_in  [N_NEWS * NH];
__device__ float g_den_in[N_NEWS * NH];
__device__ float g_accsem[2 * HID];
__device__ float g_beta  [2];

// ---------------- init ----------------
__global__ void fill_kernel(float* __restrict__ p, int n, float v) {
    int i = blockIdx.x * blockDim.x + threadIdx.x;
    if (i < n) p[i] = v;
}

// ---------------- GEMM: C[M,128] = A[M,K] @ W[K,128] (+bias) ----------------
// mode 0: store C row-wise (projection).
// mode 1: semantic epilogue: per-column sum over valid rows of tanh(acc + bias[col]),
//         atomicAdd into C[col] (C points at a 128-float accumulator).
// relu_in: apply max(x,0) to A elements at load (HAN relu on metapath outputs).
__global__ __launch_bounds__(256, 2)
void gemm128(const float* __restrict__ A, const float* __restrict__ W,
             const float* __restrict__ B, float* __restrict__ C,
             int M, int K, int relu_in, int semantic)
{
    __shared__ float As[128][17];
    __shared__ float Ws[16][128];

    const int tid = threadIdx.x;
    const int tx = tid & 15, ty = tid >> 4;
    const int m0 = blockIdx.x * 128;

    float acc[8][8];
#pragma unroll
    for (int i = 0; i < 8; i++)
#pragma unroll
        for (int j = 0; j < 8; j++) acc[i][j] = 0.f;

    for (int k0 = 0; k0 < K; k0 += 16) {
        // load A tile: 128 rows x 16 cols
#pragma unroll
        for (int l = 0; l < 2; l++) {
            int f = tid + 256 * l;
            int row = f >> 2, c4 = f & 3;
            int m = m0 + row;
            float4 v = make_float4(0.f, 0.f, 0.f, 0.f);
            if (m < M)
                v = *reinterpret_cast<const float4*>(A + (size_t)m * K + k0 + c4 * 4);
            if (relu_in) {
                v.x = fmaxf(v.x, 0.f); v.y = fmaxf(v.y, 0.f);
                v.z = fmaxf(v.z, 0.f); v.w = fmaxf(v.w, 0.f);
            }
            As[row][c4 * 4 + 0] = v.x;
            As[row][c4 * 4 + 1] = v.y;
            As[row][c4 * 4 + 2] = v.z;
            As[row][c4 * 4 + 3] = v.w;
        }
        // load W tile: 16 rows x 128 cols
#pragma unroll
        for (int l = 0; l < 2; l++) {
            int f = tid + 256 * l;
            int row = f >> 5, c4 = f & 31;
            *reinterpret_cast<float4*>(&Ws[row][c4 * 4]) =
                *reinterpret_cast<const float4*>(W + (size_t)(k0 + row) * 128 + c4 * 4);
        }
        __syncthreads();
#pragma unroll
        for (int kk = 0; kk < 16; kk++) {
            float a[8], w[8];
#pragma unroll
            for (int i = 0; i < 8; i++) a[i] = As[ty * 8 + i][kk];
#pragma unroll
            for (int j = 0; j < 8; j++) w[j] = Ws[kk][tx + 16 * j];
#pragma unroll
            for (int i = 0; i < 8; i++)
#pragma unroll
                for (int j = 0; j < 8; j++) acc[i][j] += a[i] * w[j];
        }
        __syncthreads();
    }

    if (!semantic) {
#pragma unroll
        for (int i = 0; i < 8; i++) {
            int m = m0 + ty * 8 + i;
            if (m < M) {
#pragma unroll
                for (int j = 0; j < 8; j++) {
                    int c = tx + 16 * j;
                    C[(size_t)m * 128 + c] = acc[i][j] + B[c];
                }
            }
        }
    } else {
        float part[8];
#pragma unroll
        for (int j = 0; j < 8; j++) part[j] = 0.f;
#pragma unroll
        for (int i = 0; i < 8; i++) {
            if (m0 + ty * 8 + i < M) {
#pragma unroll
                for (int j = 0; j < 8; j++)
                    part[j] += tanhf(acc[i][j] + B[tx + 16 * j]);
            }
        }
        __syncthreads();   // done reading Ws from main loop
#pragma unroll
        for (int j = 0; j < 8; j++) Ws[ty][tx + 16 * j] = part[j];
        __syncthreads();
        if (tid < 128) {
            float s = 0.f;
#pragma unroll
            for (int r = 0; r < 16; r++) s += Ws[r][tid];
            atomicAdd(&C[tid], s);
        }
    }
}

// ---------------- per-(node,head) attention dot: out[n,h] = sum_d h[n,h,d]*vec[h,d] ----------------
__global__ void att_dot(const float* __restrict__ h, const float* __restrict__ vec,
                        float* __restrict__ out, int N)
{
    __shared__ float sv[128];
    if (threadIdx.x < 128) sv[threadIdx.x] = vec[threadIdx.x];
    __syncthreads();
    int i = blockIdx.x * blockDim.x + threadIdx.x;
    if (i < N * NH) {
        int n = i >> 3, hh = i & 7;
        const float* hp = h + (size_t)n * HID + hh * HD;
        float s = 0.f;
#pragma unroll
        for (int d = 0; d < HD; d++) s += hp[d] * sv[hh * HD + d];
        out[i] = s;
    }
}

__device__ __forceinline__ float lrelu02(float x) { return x > 0.f ? x : 0.2f * x; }

__device__ __forceinline__ void atomic_max_float(float* addr, float v)
{
    if (v >= 0.f) atomicMax((int*)addr, __float_as_int(v));
    else          atomicMin((unsigned int*)addr, __float_as_uint(v));
}

// ---------------- pass B: segment max ----------------
__global__ void edge_max(const int* __restrict__ edge, int E,
                         const float* __restrict__ asrc, const float* __restrict__ adst,
                         float* __restrict__ m)
{
    int e = blockIdx.x * blockDim.x + threadIdx.x;
    if (e >= E) return;
    int s = edge[e], d = edge[E + e];
    float4 as0 = reinterpret_cast<const float4*>(asrc)[(size_t)s * 2];
    float4 as1 = reinterpret_cast<const float4*>(asrc)[(size_t)s * 2 + 1];
    float4 ad0 = reinterpret_cast<const float4*>(adst)[(size_t)d * 2];
    float4 ad1 = reinterpret_cast<const float4*>(adst)[(size_t)d * 2 + 1];
    float vs[8] = { lrelu02(as0.x + ad0.x), lrelu02(as0.y + ad0.y),
                    lrelu02(as0.z + ad0.z), lrelu02(as0.w + ad0.w),
                    lrelu02(as1.x + ad1.x), lrelu02(as1.y + ad1.y),
                    lrelu02(as1.z + ad1.z), lrelu02(as1.w + ad1.w) };
#pragma unroll
    for (int hh = 0; hh < 8; hh++)
        atomic_max_float(&m[(size_t)d * 8 + hh], vs[hh]);
}

// ---------------- pass C: segment sum of exp ----------------
__global__ void edge_denom(const int* __restrict__ edge, int E,
                           const float* __restrict__ asrc, const float* __restrict__ adst,
                           const float* __restrict__ m, float* __restrict__ den)
{
    int e = blockIdx.x * blockDim.x + threadIdx.x;
    if (e >= E) return;
    int s = edge[e], d = edge[E + e];
    float4 as0 = reinterpret_cast<const float4*>(asrc)[(size_t)s * 2];
    float4 as1 = reinterpret_cast<const float4*>(asrc)[(size_t)s * 2 + 1];
    float4 ad0 = reinterpret_cast<const float4*>(adst)[(size_t)d * 2];
    float4 ad1 = reinterpret_cast<const float4*>(adst)[(size_t)d * 2 + 1];
    float4 m0 = reinterpret_cast<const float4*>(m)[(size_t)d * 2];
    float4 m1 = reinterpret_cast<const float4*>(m)[(size_t)d * 2 + 1];
    float vs[8] = { lrelu02(as0.x + ad0.x), lrelu02(as0.y + ad0.y),
                    lrelu02(as0.z + ad0.z), lrelu02(as0.w + ad0.w),
                    lrelu02(as1.x + ad1.x), lrelu02(as1.y + ad1.y),
                    lrelu02(as1.z + ad1.z), lrelu02(as1.w + ad1.w) };
    float ms[8] = { m0.x, m0.y, m0.z, m0.w, m1.x, m1.y, m1.z, m1.w };
#pragma unroll
    for (int hh = 0; hh < 8; hh++)
        atomicAdd(&den[(size_t)d * 8 + hh], __expf(vs[hh] - ms[hh]));
}

// ---------------- pass D: weighted aggregation (warp per edge) ----------------
__global__ void edge_agg(const int* __restrict__ edge, int E,
                         const float* __restrict__ asrc, const float* __restrict__ adst,
                         const float* __restrict__ m, const float* __restrict__ den,
                         const float* __restrict__ hsrc, float* __restrict__ out)
{
    int gtid = blockIdx.x * blockDim.x + threadIdx.x;
    int warp = gtid >> 5;
    int lane = threadIdx.x & 31;
    if (warp >= E) return;
    int s = edge[warp], d = edge[E + warp];
    int hh = lane >> 2;
    float v = lrelu02(asrc[(size_t)s * 8 + hh] + adst[(size_t)d * 8 + hh]);
    float alpha = __expf(v - m[(size_t)d * 8 + hh]) / (den[(size_t)d * 8 + hh] + 1e-16f);
    float4 hv = reinterpret_cast<const float4*>(hsrc)[(size_t)s * 32 + lane];
    float* o = out + (size_t)d * 128 + lane * 4;
    atomicAdd(o + 0, hv.x * alpha);
    atomicAdd(o + 1, hv.y * alpha);
    atomicAdd(o + 2, hv.z * alpha);
    atomicAdd(o + 3, hv.w * alpha);
}

// ---------------- semantic softmax beta ----------------
__global__ void beta_kernel(const float* __restrict__ acc, const float* __restrict__ q,
                            float* __restrict__ beta)
{
    __shared__ float red[2][4];
    int t = threadIdx.x;  // 128 threads
    float s0 = q[t] * acc[t]       * (1.f / N_NEWS);
    float s1 = q[t] * acc[128 + t] * (1.f / N_NEWS);
#pragma unroll
    for (int off = 16; off; off >>= 1) {
        s0 += __shfl_down_sync(0xffffffffu, s0, off);
        s1 += __shfl_down_sync(0xffffffffu, s1, off);
    }
    if ((t & 31) == 0) { red[0][t >> 5] = s0; red[1][t >> 5] = s1; }
    __syncthreads();
    if (t == 0) {
        float sc0 = red[0][0] + red[0][1] + red[0][2] + red[0][3];
        float sc1 = red[1][0] + red[1][1] + red[1][2] + red[1][3];
        float mx = fmaxf(sc0, sc1);
        float e0 = __expf(sc0 - mx), e1 = __expf(sc1 - mx);
        float inv = 1.f / (e0 + e1);
        beta[0] = e0 * inv;
        beta[1] = e1 * inv;
    }
}

// ---------------- final: fuse + ELU + [128x4] head (warp per node) ----------------
__global__ void final_kernel(const float* __restrict__ onn, const float* __restrict__ oin,
                             const float* __restrict__ beta, const float* __restrict__ Wout,
                             const float* __restrict__ bout, float* __restrict__ y)
{
    __shared__ float sw[HID * 4];
    for (int i = threadIdx.x; i < HID * 4; i += blockDim.x) sw[i] = Wout[i];
    __syncthreads();

    int gtid = blockIdx.x * blockDim.x + threadIdx.x;
    int node = gtid >> 5;
    int lane = threadIdx.x & 31;
    if (node >= N_NEWS) return;

    float b0 = beta[0], b1 = beta[1];
    float4 a = reinterpret_cast<const float4*>(onn)[(size_t)node * 32 + lane];
    float4 b = reinterpret_cast<const float4*>(oin)[(size_t)node * 32 + lane];
    float f[4] = { b0 * fmaxf(a.x, 0.f) + b1 * fmaxf(b.x, 0.f),
                   b0 * fmaxf(a.y, 0.f) + b1 * fmaxf(b.y, 0.f),
                   b0 * fmaxf(a.z, 0.f) + b1 * fmaxf(b.z, 0.f),
                   b0 * fmaxf(a.w, 0.f) + b1 * fmaxf(b.w, 0.f) };
#pragma unroll
    for (int u = 0; u < 4; u++) f[u] = f[u] > 0.f ? f[u] : (__expf(f[u]) - 1.f);

    float p[4] = { 0.f, 0.f, 0.f, 0.f };
#pragma unroll
    for (int u = 0; u < 4; u++) {
        int r = lane * 4 + u;
#pragma unroll
        for (int c = 0; c < 4; c++) p[c] += f[u] * sw[r * 4 + c];
    }
#pragma unroll
    for (int off = 16; off; off >>= 1)
#pragma unroll
        for (int c = 0; c < 4; c++) p[c] += __shfl_down_sync(0xffffffffu, p[c], off);
    if (lane == 0) {
#pragma unroll
        for (int c = 0; c < 4; c++) y[(size_t)node * 4 + c] = p[c] + bout[c];
    }
}

// ---------------- host ----------------
static inline int cdiv(int a, int b) { return (a + b - 1) / b; }

extern "C" void kernel_launch(void* const* d_in, const int* in_sizes, int n_in,
                              void* d_out, int out_size)
{
    const float* x_news   = (const float*)d_in[0];
    const float* x_inter  = (const float*)d_in[1];
    const int*   edge_nn  = (const int*)  d_in[2];
    const int*   edge_in  = (const int*)  d_in[3];
    const float* W_news   = (const float*)d_in[4];
    const float* b_news   = (const float*)d_in[5];
    const float* W_inter  = (const float*)d_in[6];
    const float* b_inter  = (const float*)d_in[7];
    const float* a_src_nn = (const float*)d_in[8];
    const float* a_dst_nn = (const float*)d_in[9];
    const float* a_src_in = (const float*)d_in[10];
    const float* a_dst_in = (const float*)d_in[11];
    const float* Wk       = (const float*)d_in[12];
    const float* bk       = (const float*)d_in[13];
    const float* q        = (const float*)d_in[14];
    const float* W_out    = (const float*)d_in[15];
    const float* b_out    = (const float*)d_in[16];
    float* y = (float*)d_out;

    const int E_nn = in_sizes[2] / 2;
    const int E_in = in_sizes[3] / 2;

    float *h_news, *h_inter, *out_nn, *out_in;
    float *asrc_nn, *adst_nn, *asrc_in, *adst_in;
    float *m_nn, *den_nn, *m_in, *den_in, *accsem, *beta;
    cudaGetSymbolAddress((void**)&h_news,  g_h_news);
    cudaGetSymbolAddress((void**)&h_inter, g_h_inter);
    cudaGetSymbolAddress((void**)&out_nn,  g_out_nn);
    cudaGetSymbolAddress((void**)&out_in,  g_out_in);
    cudaGetSymbolAddress((void**)&asrc_nn, g_asrc_nn);
    cudaGetSymbolAddress((void**)&adst_nn, g_adst_nn);
    cudaGetSymbolAddress((void**)&asrc_in, g_asrc_in);
    cudaGetSymbolAddress((void**)&adst_in, g_adst_in);
    cudaGetSymbolAddress((void**)&m_nn,    g_m_nn);
    cudaGetSymbolAddress((void**)&den_nn,  g_den_nn);
    cudaGetSymbolAddress((void**)&m_in,    g_m_in);
    cudaGetSymbolAddress((void**)&den_in,  g_den_in);
    cudaGetSymbolAddress((void**)&accsem,  g_accsem);
    cudaGetSymbolAddress((void**)&beta,    g_beta);

    const int T = 256;

    // init scratch (graph replays must be deterministic)
    fill_kernel<<<cdiv(N_NEWS * HID, T), T>>>(out_nn, N_NEWS * HID, 0.f);
    fill_kernel<<<cdiv(N_NEWS * HID, T), T>>>(out_in, N_NEWS * HID, 0.f);
    fill_kernel<<<1, T>>>(accsem, 2 * HID, 0.f);
    fill_kernel<<<cdiv(N_NEWS * NH, T), T>>>(m_nn, N_NEWS * NH, -INFINITY);
    fill_kernel<<<cdiv(N_NEWS * NH, T), T>>>(m_in, N_NEWS * NH, -INFINITY);
    fill_kernel<<<cdiv(N_NEWS * NH, T), T>>>(den_nn, N_NEWS * NH, 0.f);
    fill_kernel<<<cdiv(N_NEWS * NH, T), T>>>(den_in, N_NEWS * NH, 0.f);

    // projections
    gemm128<<<cdiv(N_NEWS, 128), 256>>>(x_news,  W_news,  b_news,  h_news,  N_NEWS,  768, 0, 0);
    gemm128<<<cdiv(N_INTER, 128), 256>>>(x_inter, W_inter, b_inter, h_inter, N_INTER, 768, 0, 0);

    // node-level attention coefficients
    att_dot<<<cdiv(N_NEWS  * NH, T), T>>>(h_news,  a_src_nn, asrc_nn, N_NEWS);
    att_dot<<<cdiv(N_NEWS  * NH, T), T>>>(h_news,  a_dst_nn, adst_nn, N_NEWS);
    att_dot<<<cdiv(N_INTER * NH, T), T>>>(h_inter, a_src_in, asrc_in, N_INTER);
    att_dot<<<cdiv(N_NEWS  * NH, T), T>>>(h_news,  a_dst_in, adst_in, N_NEWS);

    // softmax over incoming edges (3 passes per edge type)
    edge_max  <<<cdiv(E_nn, T), T>>>(edge_nn, E_nn, asrc_nn, adst_nn, m_nn);
    edge_max  <<<cdiv(E_in, T), T>>>(edge_in, E_in, asrc_in, adst_in, m_in);
    edge_denom<<<cdiv(E_nn, T), T>>>(edge_nn, E_nn, asrc_nn, adst_nn, m_nn, den_nn);
    edge_denom<<<cdiv(E_in, T), T>>>(edge_in, E_in, asrc_in, adst_in, m_in, den_in);
    edge_agg  <<<cdiv(E_nn * 32, T), T>>>(edge_nn, E_nn, asrc_nn, adst_nn, m_nn, den_nn, h_news,  out_nn);
    edge_agg  <<<cdiv(E_in * 32, T), T>>>(edge_in, E_in, asrc_in, adst_in, m_in, den_in, h_inter, out_in);

    // semantic attention: sum over nodes of tanh(relu(out) @ Wk + bk)
    gemm128<<<cdiv(N_NEWS, 128), 256>>>(out_nn, Wk, bk, accsem,       N_NEWS, 128, 1, 1);
    gemm128<<<cdiv(N_NEWS, 128), 256>>>(out_in, Wk, bk, accsem + 128, N_NEWS, 128, 1, 1);
    beta_kernel<<<1, 128>>>(accsem, q, beta);

    // fuse + ELU + output head
    final_kernel<<<cdiv(N_NEWS * 32, T), T>>>(out_nn, out_in, beta, W_out, b_out, y);
}

// round 3
// speedup vs baseline: 1.3985x; 1.3985x over previous
#include <cuda_runtime.h>
#include <math.h>
#include <stdint.h>

#define N_NEWS  30000
#define N_INTER 60000
#define HID 128
#define NH  8
#define HD  16

// ---------------- scratch (static device globals; no allocation) ----------------
__device__ float g_h_news [N_NEWS  * HID];
__device__ float g_h_inter[N_INTER * HID];
__device__ float g_out_nn [N_NEWS  * HID];
__device__ float g_out_in [N_NEWS  * HID];
__device__ float g_Bt     [HID * 768];       // transposed weight staging [N=128, K<=768]
__device__ float g_asrc_nn[N_NEWS  * NH];
__device__ float g_adst_nn[N_NEWS  * NH];
__device__ float g_asrc_in[N_INTER * NH];
__device__ float g_adst_in[N_NEWS  * NH];
__device__ float g_m_nn  [N_NEWS * NH];
__device__ float g_den_nn[N_NEWS * NH];
__device__ float g_m_in  [N_NEWS * NH];
__device__ float g_den_in[N_NEWS * NH];
__device__ float g_accsem[2 * HID];
__device__ float g_beta  [2];

// ---------------- init ----------------
__global__ void fill_kernel(float* __restrict__ p, int n, float v) {
    int i = blockIdx.x * blockDim.x + threadIdx.x;
    if (i < n) p[i] = v;
}

// ---------------- helpers ----------------
static __device__ __forceinline__ uint32_t smem_u32(const void* p) {
    uint32_t r;
    asm("{ .reg .u64 t; cvta.to.shared.u64 t, %1; cvt.u32.u64 %0, t; }" : "=r"(r) : "l"(p));
    return r;
}
static __device__ __forceinline__ uint32_t f2tf(float x) {
    uint32_t r;
    asm("cvt.rna.tf32.f32 %0, %1;" : "=r"(r) : "f"(x));
    return r;
}
static __device__ __forceinline__ void mma_tf32(float* c, const uint32_t* a, const uint32_t* b) {
    asm volatile(
        "mma.sync.aligned.m16n8k8.row.col.f32.tf32.tf32.f32 "
        "{%0,%1,%2,%3},{%4,%5,%6,%7},{%8,%9},{%0,%1,%2,%3};"
        : "+f"(c[0]), "+f"(c[1]), "+f"(c[2]), "+f"(c[3])
        : "r"(a[0]), "r"(a[1]), "r"(a[2]), "r"(a[3]), "r"(b[0]), "r"(b[1]));
}
static __device__ __forceinline__ void cp16(uint32_t dst, const void* src, int srcsz) {
    asm volatile("cp.async.cg.shared.global [%0], [%1], 16, %2;"
                 :: "r"(dst), "l"(src), "r"(srcsz));
}

// ---------------- transpose W[K,128] -> Wt[128,K] ----------------
__global__ void transpose_w(const float* __restrict__ W, float* __restrict__ Wt, int K) {
    int i = blockIdx.x * blockDim.x + threadIdx.x;
    if (i < K * 128) {
        int k = i >> 7, n = i & 127;
        Wt[(size_t)n * K + k] = W[i];
    }
}

// ---------------- tf32 tensor-core GEMM: C[M,128] = A[M,K] @ Bt^T ----------------
// Bt layout: [128 (N), K], K-major. K multiple of 32.
// semantic=0: C[m,n] = acc + bias[n]
// semantic=1: atomicAdd(C[n], sum_{m<M} tanh(acc + bias[n]))
// relu_in:    apply max(x,0) to A at load (implies synchronous load path).
#define LDT 36              // padded row length (floats): conflict-free
#define BUF_F (128 * LDT)   // floats per (A or B) tile

__global__ __launch_bounds__(256)
void mma_gemm(const float* __restrict__ A, const float* __restrict__ Bt,
              const float* __restrict__ bias, float* __restrict__ C,
              int M, int K, int relu_in, int semantic)
{
    extern __shared__ float smem[];     // [2][A(4608) + B(4608)] floats
    __shared__ float s_bias[128];
    __shared__ float s_col[128];

    const int tid  = threadIdx.x;
    const int warp = tid >> 5;
    const int lane = tid & 31;
    const int group = lane >> 2, tig = lane & 3;
    const int warpM = warp & 3, warpN = warp >> 2;
    const int mbase = warpM * 32, nbase = warpN * 64;
    const int m0 = blockIdx.x * 128;

    if (tid < 128) { s_bias[tid] = bias[tid]; s_col[tid] = 0.f; }

    float acc[2][8][4];
#pragma unroll
    for (int i = 0; i < 2; i++)
#pragma unroll
        for (int j = 0; j < 8; j++)
#pragma unroll
            for (int l = 0; l < 4; l++) acc[i][j][l] = 0.f;

    const int nchunk = K >> 5;
    const uint32_t smem_b = smem_u32(smem);

    if (!relu_in) {
        // -------- pipelined cp.async path --------
        // issue chunk 0
        {
            const int kb = 0;
#pragma unroll
            for (int l = 0; l < 4; l++) {
                int f = tid + 256 * l;
                int row = f >> 3, q = f & 7;
                int m = m0 + row; int ok = m < M; int mc = ok ? m : 0;
                cp16(smem_b + (uint32_t)((row * LDT + q * 4) << 2),
                     A + (size_t)mc * K + kb + q * 4, ok ? 16 : 0);
                cp16(smem_b + (uint32_t)((BUF_F + row * LDT + q * 4) << 2),
                     Bt + (size_t)row * K + kb + q * 4, 16);
            }
            asm volatile("cp.async.commit_group;");
        }
        for (int c = 0; c < nchunk; c++) {
            if (c + 1 < nchunk) {
                const int kb = (c + 1) * 32;
                const uint32_t bufo = (uint32_t)(((c + 1) & 1) * 2 * BUF_F) << 2;
#pragma unroll
                for (int l = 0; l < 4; l++) {
                    int f = tid + 256 * l;
                    int row = f >> 3, q = f & 7;
                    int m = m0 + row; int ok = m < M; int mc = ok ? m : 0;
                    cp16(smem_b + bufo + (uint32_t)((row * LDT + q * 4) << 2),
                         A + (size_t)mc * K + kb + q * 4, ok ? 16 : 0);
                    cp16(smem_b + bufo + (uint32_t)((BUF_F + row * LDT + q * 4) << 2),
                         Bt + (size_t)row * K + kb + q * 4, 16);
                }
                asm volatile("cp.async.commit_group;");
                asm volatile("cp.async.wait_group 1;");
            } else {
                asm volatile("cp.async.wait_group 0;");
            }
            __syncthreads();
            const float* As = smem + (c & 1) * 2 * BUF_F;
            const float* Bs = As + BUF_F;
#pragma unroll
            for (int ks = 0; ks < 4; ks++) {
                const int kk = ks * 8;
                uint32_t af[2][4], bf[8][2];
#pragma unroll
                for (int ma = 0; ma < 2; ma++) {
                    int r0 = mbase + ma * 16 + group;
                    af[ma][0] = f2tf(As[r0 * LDT + kk + tig]);
                    af[ma][1] = f2tf(As[(r0 + 8) * LDT + kk + tig]);
                    af[ma][2] = f2tf(As[r0 * LDT + kk + tig + 4]);
                    af[ma][3] = f2tf(As[(r0 + 8) * LDT + kk + tig + 4]);
                }
#pragma unroll
                for (int na = 0; na < 8; na++) {
                    int col = nbase + na * 8 + group;
                    bf[na][0] = f2tf(Bs[col * LDT + kk + tig]);
                    bf[na][1] = f2tf(Bs[col * LDT + kk + tig + 4]);
                }
#pragma unroll
                for (int ma = 0; ma < 2; ma++)
#pragma unroll
                    for (int na = 0; na < 8; na++)
                        mma_tf32(acc[ma][na], af[ma], bf[na]);
            }
            __syncthreads();
        }
    } else {
        // -------- synchronous path with relu on A load (semantic GEMM, small K) --------
        for (int c = 0; c < nchunk; c++) {
            __syncthreads();
            const int kb = c * 32;
            float* As = smem;
            float* Bs = smem + BUF_F;
#pragma unroll
            for (int l = 0; l < 4; l++) {
                int f = tid + 256 * l;
                int row = f >> 3, q = f & 7;
                int m = m0 + row;
                float4 v = make_float4(0.f, 0.f, 0.f, 0.f);
                if (m < M) v = *reinterpret_cast<const float4*>(A + (size_t)m * K + kb + q * 4);
                v.x = fmaxf(v.x, 0.f); v.y = fmaxf(v.y, 0.f);
                v.z = fmaxf(v.z, 0.f); v.w = fmaxf(v.w, 0.f);
                *reinterpret_cast<float4*>(As + row * LDT + q * 4) = v;
                *reinterpret_cast<float4*>(Bs + row * LDT + q * 4) =
                    *reinterpret_cast<const float4*>(Bt + (size_t)row * K + kb + q * 4);
            }
            __syncthreads();
#pragma unroll
            for (int ks = 0; ks < 4; ks++) {
                const int kk = ks * 8;
                uint32_t af[2][4], bf[8][2];
#pragma unroll
                for (int ma = 0; ma < 2; ma++) {
                    int r0 = mbase + ma * 16 + group;
                    af[ma][0] = f2tf(As[r0 * LDT + kk + tig]);
                    af[ma][1] = f2tf(As[(r0 + 8) * LDT + kk + tig]);
                    af[ma][2] = f2tf(As[r0 * LDT + kk + tig + 4]);
                    af[ma][3] = f2tf(As[(r0 + 8) * LDT + kk + tig + 4]);
                }
#pragma unroll
                for (int na = 0; na < 8; na++) {
                    int col = nbase + na * 8 + group;
                    bf[na][0] = f2tf(Bs[col * LDT + kk + tig]);
                    bf[na][1] = f2tf(Bs[col * LDT + kk + tig + 4]);
                }
#pragma unroll
                for (int ma = 0; ma < 2; ma++)
#pragma unroll
                    for (int na = 0; na < 8; na++)
                        mma_tf32(acc[ma][na], af[ma], bf[na]);
            }
        }
        __syncthreads();
    }

    // -------- epilogue --------
    if (!semantic) {
#pragma unroll
        for (int ma = 0; ma < 2; ma++) {
            int row = m0 + mbase + ma * 16 + group;
#pragma unroll
            for (int na = 0; na < 8; na++) {
                int col = nbase + na * 8 + tig * 2;
                if (row < M) {
                    float2 v = { acc[ma][na][0] + s_bias[col],
                                 acc[ma][na][1] + s_bias[col + 1] };
                    *reinterpret_cast<float2*>(C + (size_t)row * 128 + col) = v;
                }
                if (row + 8 < M) {
                    float2 v = { acc[ma][na][2] + s_bias[col],
                                 acc[ma][na][3] + s_bias[col + 1] };
                    *reinterpret_cast<float2*>(C + (size_t)(row + 8) * 128 + col) = v;
                }
            }
        }
    } else {
#pragma unroll
        for (int na = 0; na < 8; na++) {
            int col = nbase + na * 8 + tig * 2;
            float p0 = 0.f, p1 = 0.f;
#pragma unroll
            for (int ma = 0; ma < 2; ma++) {
                int row = m0 + mbase + ma * 16 + group;
                if (row < M) {
                    p0 += tanhf(acc[ma][na][0] + s_bias[col]);
                    p1 += tanhf(acc[ma][na][1] + s_bias[col + 1]);
                }
                if (row + 8 < M) {
                    p0 += tanhf(acc[ma][na][2] + s_bias[col]);
                    p1 += tanhf(acc[ma][na][3] + s_bias[col + 1]);
                }
            }
            atomicAdd(&s_col[col], p0);
            atomicAdd(&s_col[col + 1], p1);
        }
        __syncthreads();
        if (tid < 128) atomicAdd(&C[tid], s_col[tid]);
    }
}

// ---------------- per-(node,head) attention dot ----------------
__global__ void att_dot(const float* __restrict__ h, const float* __restrict__ vec,
                        float* __restrict__ out, int N)
{
    __shared__ float sv[128];
    if (threadIdx.x < 128) sv[threadIdx.x] = vec[threadIdx.x];
    __syncthreads();
    int i = blockIdx.x * blockDim.x + threadIdx.x;
    if (i < N * NH) {
        int n = i >> 3, hh = i & 7;
        const float* hp = h + (size_t)n * HID + hh * HD;
        float s = 0.f;
#pragma unroll
        for (int d = 0; d < HD; d++) s += hp[d] * sv[hh * HD + d];
        out[i] = s;
    }
}

__device__ __forceinline__ float lrelu02(float x) { return x > 0.f ? x : 0.2f * x; }

__device__ __forceinline__ void atomic_max_float(float* addr, float v)
{
    if (v >= 0.f) atomicMax((int*)addr, __float_as_int(v));
    else          atomicMin((unsigned int*)addr, __float_as_uint(v));
}

// ---------------- pass B: segment max ----------------
__global__ void edge_max(const int* __restrict__ edge, int E,
                         const float* __restrict__ asrc, const float* __restrict__ adst,
                         float* __restrict__ m)
{
    int e = blockIdx.x * blockDim.x + threadIdx.x;
    if (e >= E) return;
    int s = edge[e], d = edge[E + e];
    float4 as0 = reinterpret_cast<const float4*>(asrc)[(size_t)s * 2];
    float4 as1 = reinterpret_cast<const float4*>(asrc)[(size_t)s * 2 + 1];
    float4 ad0 = reinterpret_cast<const float4*>(adst)[(size_t)d * 2];
    float4 ad1 = reinterpret_cast<const float4*>(adst)[(size_t)d * 2 + 1];
    float vs[8] = { lrelu02(as0.x + ad0.x), lrelu02(as0.y + ad0.y),
                    lrelu02(as0.z + ad0.z), lrelu02(as0.w + ad0.w),
                    lrelu02(as1.x + ad1.x), lrelu02(as1.y + ad1.y),
                    lrelu02(as1.z + ad1.z), lrelu02(as1.w + ad1.w) };
#pragma unroll
    for (int hh = 0; hh < 8; hh++)
        atomic_max_float(&m[(size_t)d * 8 + hh], vs[hh]);
}

// ---------------- pass C: segment sum of exp ----------------
__global__ void edge_denom(const int* __restrict__ edge, int E,
                           const float* __restrict__ asrc, const float* __restrict__ adst,
                           const float* __restrict__ m, float* __restrict__ den)
{
    int e = blockIdx.x * blockDim.x + threadIdx.x;
    if (e >= E) return;
    int s = edge[e], d = edge[E + e];
    float4 as0 = reinterpret_cast<const float4*>(asrc)[(size_t)s * 2];
    float4 as1 = reinterpret_cast<const float4*>(asrc)[(size_t)s * 2 + 1];
    float4 ad0 = reinterpret_cast<const float4*>(adst)[(size_t)d * 2];
    float4 ad1 = reinterpret_cast<const float4*>(adst)[(size_t)d * 2 + 1];
    float4 m0 = reinterpret_cast<const float4*>(m)[(size_t)d * 2];
    float4 m1 = reinterpret_cast<const float4*>(m)[(size_t)d * 2 + 1];
    float vs[8] = { lrelu02(as0.x + ad0.x), lrelu02(as0.y + ad0.y),
                    lrelu02(as0.z + ad0.z), lrelu02(as0.w + ad0.w),
                    lrelu02(as1.x + ad1.x), lrelu02(as1.y + ad1.y),
                    lrelu02(as1.z + ad1.z), lrelu02(as1.w + ad1.w) };
    float ms[8] = { m0.x, m0.y, m0.z, m0.w, m1.x, m1.y, m1.z, m1.w };
#pragma unroll
    for (int hh = 0; hh < 8; hh++)
        atomicAdd(&den[(size_t)d * 8 + hh], __expf(vs[hh] - ms[hh]));
}

// ---------------- pass D: weighted aggregation (warp per edge) ----------------
__global__ void edge_agg(const int* __restrict__ edge, int E,
                         const float* __restrict__ asrc, const float* __restrict__ adst,
                         const float* __restrict__ m, const float* __restrict__ den,
                         const float* __restrict__ hsrc, float* __restrict__ out)
{
    int gtid = blockIdx.x * blockDim.x + threadIdx.x;
    int warp = gtid >> 5;
    int lane = threadIdx.x & 31;
    if (warp >= E) return;
    int s = edge[warp], d = edge[E + warp];
    int hh = lane >> 2;
    float v = lrelu02(asrc[(size_t)s * 8 + hh] + adst[(size_t)d * 8 + hh]);
    float alpha = __expf(v - m[(size_t)d * 8 + hh]) / (den[(size_t)d * 8 + hh] + 1e-16f);
    float4 hv = reinterpret_cast<const float4*>(hsrc)[(size_t)s * 32 + lane];
    float* o = out + (size_t)d * 128 + lane * 4;
    atomicAdd(o + 0, hv.x * alpha);
    atomicAdd(o + 1, hv.y * alpha);
    atomicAdd(o + 2, hv.z * alpha);
    atomicAdd(o + 3, hv.w * alpha);
}

// ---------------- semantic softmax beta ----------------
__global__ void beta_kernel(const float* __restrict__ acc, const float* __restrict__ q,
                            float* __restrict__ beta)
{
    __shared__ float red[2][4];
    int t = threadIdx.x;  // 128 threads
    float s0 = q[t] * acc[t]       * (1.f / N_NEWS);
    float s1 = q[t] * acc[128 + t] * (1.f / N_NEWS);
#pragma unroll
    for (int off = 16; off; off >>= 1) {
        s0 += __shfl_down_sync(0xffffffffu, s0, off);
        s1 += __shfl_down_sync(0xffffffffu, s1, off);
    }
    if ((t & 31) == 0) { red[0][t >> 5] = s0; red[1][t >> 5] = s1; }
    __syncthreads();
    if (t == 0) {
        float sc0 = red[0][0] + red[0][1] + red[0][2] + red[0][3];
        float sc1 = red[1][0] + red[1][1] + red[1][2] + red[1][3];
        float mx = fmaxf(sc0, sc1);
        float e0 = __expf(sc0 - mx), e1 = __expf(sc1 - mx);
        float inv = 1.f / (e0 + e1);
        beta[0] = e0 * inv;
        beta[1] = e1 * inv;
    }
}

// ---------------- final: fuse + ELU + [128x4] head (warp per node) ----------------
__global__ void final_kernel(const float* __restrict__ onn, const float* __restrict__ oin,
                             const float* __restrict__ beta, const float* __restrict__ Wout,
                             const float* __restrict__ bout, float* __restrict__ y)
{
    __shared__ float sw[HID * 4];
    for (int i = threadIdx.x; i < HID * 4; i += blockDim.x) sw[i] = Wout[i];
    __syncthreads();

    int gtid = blockIdx.x * blockDim.x + threadIdx.x;
    int node = gtid >> 5;
    int lane = threadIdx.x & 31;
    if (node >= N_NEWS) return;

    float b0 = beta[0], b1 = beta[1];
    float4 a = reinterpret_cast<const float4*>(onn)[(size_t)node * 32 + lane];
    float4 b = reinterpret_cast<const float4*>(oin)[(size_t)node * 32 + lane];
    float f[4] = { b0 * fmaxf(a.x, 0.f) + b1 * fmaxf(b.x, 0.f),
                   b0 * fmaxf(a.y, 0.f) + b1 * fmaxf(b.y, 0.f),
                   b0 * fmaxf(a.z, 0.f) + b1 * fmaxf(b.z, 0.f),
                   b0 * fmaxf(a.w, 0.f) + b1 * fmaxf(b.w, 0.f) };
#pragma unroll
    for (int u = 0; u < 4; u++) f[u] = f[u] > 0.f ? f[u] : (__expf(f[u]) - 1.f);

    float p[4] = { 0.f, 0.f, 0.f, 0.f };
#pragma unroll
    for (int u = 0; u < 4; u++) {
        int r = lane * 4 + u;
#pragma unroll
        for (int c = 0; c < 4; c++) p[c] += f[u] * sw[r * 4 + c];
    }
#pragma unroll
    for (int off = 16; off; off >>= 1)
#pragma unroll
        for (int c = 0; c < 4; c++) p[c] += __shfl_down_sync(0xffffffffu, p[c], off);
    if (lane == 0) {
#pragma unroll
        for (int c = 0; c < 4; c++) y[(size_t)node * 4 + c] = p[c] + bout[c];
    }
}

// ---------------- host ----------------
static inline int cdiv(int a, int b) { return (a + b - 1) / b; }

extern "C" void kernel_launch(void* const* d_in, const int* in_sizes, int n_in,
                              void* d_out, int out_size)
{
    const float* x_news   = (const float*)d_in[0];
    const float* x_inter  = (const float*)d_in[1];
    const int*   edge_nn  = (const int*)  d_in[2];
    const int*   edge_in  = (const int*)  d_in[3];
    const float* W_news   = (const float*)d_in[4];
    const float* b_news   = (const float*)d_in[5];
    const float* W_inter  = (const float*)d_in[6];
    const float* b_inter  = (const float*)d_in[7];
    const float* a_src_nn = (const float*)d_in[8];
    const float* a_dst_nn = (const float*)d_in[9];
    const float* a_src_in = (const float*)d_in[10];
    const float* a_dst_in = (const float*)d_in[11];
    const float* Wk       = (const float*)d_in[12];
    const float* bk       = (const float*)d_in[13];
    const float* q        = (const float*)d_in[14];
    const float* W_out    = (const float*)d_in[15];
    const float* b_out    = (const float*)d_in[16];
    float* y = (float*)d_out;

    const int E_nn = in_sizes[2] / 2;
    const int E_in = in_sizes[3] / 2;

    float *h_news, *h_inter, *out_nn, *out_in, *Bt;
    float *asrc_nn, *adst_nn, *asrc_in, *adst_in;
    float *m_nn, *den_nn, *m_in, *den_in, *accsem, *beta;
    cudaGetSymbolAddress((void**)&h_news,  g_h_news);
    cudaGetSymbolAddress((void**)&h_inter, g_h_inter);
    cudaGetSymbolAddress((void**)&out_nn,  g_out_nn);
    cudaGetSymbolAddress((void**)&out_in,  g_out_in);
    cudaGetSymbolAddress((void**)&Bt,      g_Bt);
    cudaGetSymbolAddress((void**)&asrc_nn, g_asrc_nn);
    cudaGetSymbolAddress((void**)&adst_nn, g_adst_nn);
    cudaGetSymbolAddress((void**)&asrc_in, g_asrc_in);
    cudaGetSymbolAddress((void**)&adst_in, g_adst_in);
    cudaGetSymbolAddress((void**)&m_nn,    g_m_nn);
    cudaGetSymbolAddress((void**)&den_nn,  g_den_nn);
    cudaGetSymbolAddress((void**)&m_in,    g_m_in);
    cudaGetSymbolAddress((void**)&den_in,  g_den_in);
    cudaGetSymbolAddress((void**)&accsem,  g_accsem);
    cudaGetSymbolAddress((void**)&beta,    g_beta);

    const int T = 256;
    const int SMEM_GEMM = 2 * 2 * BUF_F * 4;   // 73728 bytes
    cudaFuncSetAttribute(mma_gemm, cudaFuncAttributeMaxDynamicSharedMemorySize, SMEM_GEMM);

    // init scratch (graph replays must be deterministic)
    fill_kernel<<<cdiv(N_NEWS * HID, T), T>>>(out_nn, N_NEWS * HID, 0.f);
    fill_kernel<<<cdiv(N_NEWS * HID, T), T>>>(out_in, N_NEWS * HID, 0.f);
    fill_kernel<<<1, T>>>(accsem, 2 * HID, 0.f);
    fill_kernel<<<cdiv(N_NEWS * NH, T), T>>>(m_nn, N_NEWS * NH, -INFINITY);
    fill_kernel<<<cdiv(N_NEWS * NH, T), T>>>(m_in, N_NEWS * NH, -INFINITY);
    fill_kernel<<<cdiv(N_NEWS * NH, T), T>>>(den_nn, N_NEWS * NH, 0.f);
    fill_kernel<<<cdiv(N_NEWS * NH, T), T>>>(den_in, N_NEWS * NH, 0.f);

    // projections (tf32 mma)
    transpose_w<<<cdiv(768 * 128, T), T>>>(W_news, Bt, 768);
    mma_gemm<<<cdiv(N_NEWS, 128), 256, SMEM_GEMM>>>(x_news, Bt, b_news, h_news, N_NEWS, 768, 0, 0);
    transpose_w<<<cdiv(768 * 128, T), T>>>(W_inter, Bt, 768);
    mma_gemm<<<cdiv(N_INTER, 128), 256, SMEM_GEMM>>>(x_inter, Bt, b_inter, h_inter, N_INTER, 768, 0, 0);

    // node-level attention coefficients
    att_dot<<<cdiv(N_NEWS  * NH, T), T>>>(h_news,  a_src_nn, asrc_nn, N_NEWS);
    att_dot<<<cdiv(N_NEWS  * NH, T), T>>>(h_news,  a_dst_nn, adst_nn, N_NEWS);
    att_dot<<<cdiv(N_INTER * NH, T), T>>>(h_inter, a_src_in, asrc_in, N_INTER);
    att_dot<<<cdiv(N_NEWS  * NH, T), T>>>(h_news,  a_dst_in, adst_in, N_NEWS);

    // softmax over incoming edges (3 passes per edge type)
    edge_max  <<<cdiv(E_nn, T), T>>>(edge_nn, E_nn, asrc_nn, adst_nn, m_nn);
    edge_max  <<<cdiv(E_in, T), T>>>(edge_in, E_in, asrc_in, adst_in, m_in);
    edge_denom<<<cdiv(E_nn, T), T>>>(edge_nn, E_nn, asrc_nn, adst_nn, m_nn, den_nn);
    edge_denom<<<cdiv(E_in, T), T>>>(edge_in, E_in, asrc_in, adst_in, m_in, den_in);
    edge_agg  <<<cdiv(E_nn * 32, T), T>>>(edge_nn, E_nn, asrc_nn, adst_nn, m_nn, den_nn, h_news,  out_nn);
    edge_agg  <<<cdiv(E_in * 32, T), T>>>(edge_in, E_in, asrc_in, adst_in, m_in, den_in, h_inter, out_in);

    // semantic attention: sum over nodes of tanh(relu(out) @ Wk + bk)
    transpose_w<<<cdiv(128 * 128, T), T>>>(Wk, Bt, 128);
    mma_gemm<<<cdiv(N_NEWS, 128), 256, SMEM_GEMM>>>(out_nn, Bt, bk, accsem,       N_NEWS, 128, 1, 1);
    mma_gemm<<<cdiv(N_NEWS, 128), 256, SMEM_GEMM>>>(out_in, Bt, bk, accsem + 128, N_NEWS, 128, 1, 1);
    beta_kernel<<<1, 128>>>(accsem, q, beta);

    // fuse + ELU + output head
    final_kernel<<<cdiv(N_NEWS * 32, T), T>>>(out_nn, out_in, beta, W_out, b_out, y);
}

// round 4
// speedup vs baseline: 2.3700x; 1.6946x over previous
#include <cuda_runtime.h>
#include <math.h>
#include <stdint.h>

#define N_NEWS  30000
#define N_INTER 60000
#define HID 128
#define NH  8
#define HD  16
#define E_NN_CAP 480000
#define E_IN_CAP 960000

// ---------------- scratch (static device globals; no allocation) ----------------
__device__ float g_h_news [N_NEWS  * HID];
__device__ float g_h_inter[N_INTER * HID];
__device__ float g_out_nn [N_NEWS  * HID];
__device__ float g_out_in [N_NEWS  * HID];
__device__ float g_Bt     [HID * 768];       // transposed weight staging [N=128, K<=768]
__device__ float g_asrc_nn[N_NEWS  * NH];
__device__ float g_adst_nn[N_NEWS  * NH];
__device__ float g_asrc_in[N_INTER * NH];
__device__ float g_adst_in[N_NEWS  * NH];
__device__ int   g_deg_nn [N_NEWS];
__device__ int   g_deg_in [N_NEWS];
__device__ int   g_rp_nn  [N_NEWS + 1];
__device__ int   g_rp_in  [N_NEWS + 1];
__device__ int   g_cur_nn [N_NEWS];
__device__ int   g_cur_in [N_NEWS];
__device__ int   g_csr_nn [E_NN_CAP];
__device__ int   g_csr_in [E_IN_CAP];
__device__ float g_accsem[2 * HID];
__device__ float g_beta  [2];

// ---------------- init ----------------
__global__ void fill_kernel(float* __restrict__ p, int n, float v) {
    int i = blockIdx.x * blockDim.x + threadIdx.x;
    if (i < n) p[i] = v;
}
__global__ void zero_int(int* __restrict__ p, int n) {
    int i = blockIdx.x * blockDim.x + threadIdx.x;
    if (i < n) p[i] = 0;
}

// ---------------- helpers ----------------
static __device__ __forceinline__ uint32_t smem_u32(const void* p) {
    uint32_t r;
    asm("{ .reg .u64 t; cvta.to.shared.u64 t, %1; cvt.u32.u64 %0, t; }" : "=r"(r) : "l"(p));
    return r;
}
static __device__ __forceinline__ uint32_t f2tf(float x) {
    uint32_t r;
    asm("cvt.rna.tf32.f32 %0, %1;" : "=r"(r) : "f"(x));
    return r;
}
static __device__ __forceinline__ void mma_tf32(float* c, const uint32_t* a, const uint32_t* b) {
    asm volatile(
        "mma.sync.aligned.m16n8k8.row.col.f32.tf32.tf32.f32 "
        "{%0,%1,%2,%3},{%4,%5,%6,%7},{%8,%9},{%0,%1,%2,%3};"
        : "+f"(c[0]), "+f"(c[1]), "+f"(c[2]), "+f"(c[3])
        : "r"(a[0]), "r"(a[1]), "r"(a[2]), "r"(a[3]), "r"(b[0]), "r"(b[1]));
}
static __device__ __forceinline__ void cp16(uint32_t dst, const void* src, int srcsz) {
    asm volatile("cp.async.cg.shared.global [%0], [%1], 16, %2;"
                 :: "r"(dst), "l"(src), "r"(srcsz));
}

// ---------------- transpose W[K,128] -> Wt[128,K] ----------------
__global__ void transpose_w(const float* __restrict__ W, float* __restrict__ Wt, int K) {
    int i = blockIdx.x * blockDim.x + threadIdx.x;
    if (i < K * 128) {
        int k = i >> 7, n = i & 127;
        Wt[(size_t)n * K + k] = W[i];
    }
}

// ---------------- tf32 tensor-core GEMM: C[M,128] = A[M,K] @ Bt^T ----------------
#define LDT 36              // padded row length (floats): conflict-free
#define BUF_F (128 * LDT)   // floats per (A or B) tile

__global__ __launch_bounds__(256)
void mma_gemm(const float* __restrict__ A, const float* __restrict__ Bt,
              const float* __restrict__ bias, float* __restrict__ C,
              int M, int K, int semantic)
{
    extern __shared__ float smem[];     // [2][A(4608) + B(4608)] floats
    __shared__ float s_bias[128];
    __shared__ float s_col[128];

    const int tid  = threadIdx.x;
    const int warp = tid >> 5;
    const int lane = tid & 31;
    const int group = lane >> 2, tig = lane & 3;
    const int warpM = warp & 3, warpN = warp >> 2;
    const int mbase = warpM * 32, nbase = warpN * 64;
    const int m0 = blockIdx.x * 128;

    if (tid < 128) { s_bias[tid] = bias[tid]; s_col[tid] = 0.f; }

    float acc[2][8][4];
#pragma unroll
    for (int i = 0; i < 2; i++)
#pragma unroll
        for (int j = 0; j < 8; j++)
#pragma unroll
            for (int l = 0; l < 4; l++) acc[i][j][l] = 0.f;

    const int nchunk = K >> 5;
    const uint32_t smem_b = smem_u32(smem);

    // issue chunk 0
    {
#pragma unroll
        for (int l = 0; l < 4; l++) {
            int f = tid + 256 * l;
            int row = f >> 3, q = f & 7;
            int m = m0 + row; int ok = m < M; int mc = ok ? m : 0;
            cp16(smem_b + (uint32_t)((row * LDT + q * 4) << 2),
                 A + (size_t)mc * K + q * 4, ok ? 16 : 0);
            cp16(smem_b + (uint32_t)((BUF_F + row * LDT + q * 4) << 2),
                 Bt + (size_t)row * K + q * 4, 16);
        }
        asm volatile("cp.async.commit_group;");
    }
    for (int c = 0; c < nchunk; c++) {
        if (c + 1 < nchunk) {
            const int kb = (c + 1) * 32;
            const uint32_t bufo = (uint32_t)(((c + 1) & 1) * 2 * BUF_F) << 2;
#pragma unroll
            for (int l = 0; l < 4; l++) {
                int f = tid + 256 * l;
                int row = f >> 3, q = f & 7;
                int m = m0 + row; int ok = m < M; int mc = ok ? m : 0;
                cp16(smem_b + bufo + (uint32_t)((row * LDT + q * 4) << 2),
                     A + (size_t)mc * K + kb + q * 4, ok ? 16 : 0);
                cp16(smem_b + bufo + (uint32_t)((BUF_F + row * LDT + q * 4) << 2),
                     Bt + (size_t)row * K + kb + q * 4, 16);
            }
            asm volatile("cp.async.commit_group;");
            asm volatile("cp.async.wait_group 1;");
        } else {
            asm volatile("cp.async.wait_group 0;");
        }
        __syncthreads();
        const float* As = smem + (c & 1) * 2 * BUF_F;
        const float* Bs = As + BUF_F;
#pragma unroll
        for (int ks = 0; ks < 4; ks++) {
            const int kk = ks * 8;
            uint32_t af[2][4], bf[8][2];
#pragma unroll
            for (int ma = 0; ma < 2; ma++) {
                int r0 = mbase + ma * 16 + group;
                af[ma][0] = f2tf(As[r0 * LDT + kk + tig]);
                af[ma][1] = f2tf(As[(r0 + 8) * LDT + kk + tig]);
                af[ma][2] = f2tf(As[r0 * LDT + kk + tig + 4]);
                af[ma][3] = f2tf(As[(r0 + 8) * LDT + kk + tig + 4]);
            }
#pragma unroll
            for (int na = 0; na < 8; na++) {
                int col = nbase + na * 8 + group;
                bf[na][0] = f2tf(Bs[col * LDT + kk + tig]);
                bf[na][1] = f2tf(Bs[col * LDT + kk + tig + 4]);
            }
#pragma unroll
            for (int ma = 0; ma < 2; ma++)
#pragma unroll
                for (int na = 0; na < 8; na++)
                    mma_tf32(acc[ma][na], af[ma], bf[na]);
        }
        __syncthreads();
    }

    // -------- epilogue --------
    if (!semantic) {
#pragma unroll
        for (int ma = 0; ma < 2; ma++) {
            int row = m0 + mbase + ma * 16 + group;
#pragma unroll
            for (int na = 0; na < 8; na++) {
                int col = nbase + na * 8 + tig * 2;
                if (row < M) {
                    float2 v = { acc[ma][na][0] + s_bias[col],
                                 acc[ma][na][1] + s_bias[col + 1] };
                    *reinterpret_cast<float2*>(C + (size_t)row * 128 + col) = v;
                }
                if (row + 8 < M) {
                    float2 v = { acc[ma][na][2] + s_bias[col],
                                 acc[ma][na][3] + s_bias[col + 1] };
                    *reinterpret_cast<float2*>(C + (size_t)(row + 8) * 128 + col) = v;
                }
            }
        }
    } else {
#pragma unroll
        for (int na = 0; na < 8; na++) {
            int col = nbase + na * 8 + tig * 2;
            float p0 = 0.f, p1 = 0.f;
#pragma unroll
            for (int ma = 0; ma < 2; ma++) {
                int row = m0 + mbase + ma * 16 + group;
                if (row < M) {
                    p0 += tanhf(acc[ma][na][0] + s_bias[col]);
                    p1 += tanhf(acc[ma][na][1] + s_bias[col + 1]);
                }
                if (row + 8 < M) {
                    p0 += tanhf(acc[ma][na][2] + s_bias[col]);
                    p1 += tanhf(acc[ma][na][3] + s_bias[col + 1]);
                }
            }
            atomicAdd(&s_col[col], p0);
            atomicAdd(&s_col[col + 1], p1);
        }
        __syncthreads();
        if (tid < 128) atomicAdd(&C[tid], s_col[tid]);
    }
}

// ---------------- per-(node,head) attention dot ----------------
__global__ void att_dot(const float* __restrict__ h, const float* __restrict__ vec,
                        float* __restrict__ out, int N)
{
    __shared__ float sv[128];
    if (threadIdx.x < 128) sv[threadIdx.x] = vec[threadIdx.x];
    __syncthreads();
    int i = blockIdx.x * blockDim.x + threadIdx.x;
    if (i < N * NH) {
        int n = i >> 3, hh = i & 7;
        const float* hp = h + (size_t)n * HID + hh * HD;
        float s = 0.f;
#pragma unroll
        for (int d = 0; d < HD; d++) s += hp[d] * sv[hh * HD + d];
        out[i] = s;
    }
}

__device__ __forceinline__ float lrelu02(float x) { return x > 0.f ? x : 0.2f * x; }

// ---------------- CSR build ----------------
__global__ void hist_kernel(const int* __restrict__ edge, int E, int* __restrict__ deg) {
    int e = blockIdx.x * blockDim.x + threadIdx.x;
    if (e < E) atomicAdd(&deg[edge[E + e]], 1);
}

// single-block exclusive scan over n<=30720 elements (1024 threads, chunked)
__global__ void scan_kernel(const int* __restrict__ deg, int* __restrict__ rowptr,
                            int* __restrict__ cursor, int n)
{
    __shared__ int part[1024];
    const int t = threadIdx.x;
    const int chunk = (n + 1023) >> 10;
    const int b = t * chunk;
    int sum = 0;
    for (int i = 0; i < chunk; i++) { int idx = b + i; if (idx < n) sum += deg[idx]; }
    part[t] = sum;
    __syncthreads();
    for (int off = 1; off < 1024; off <<= 1) {
        int v = (t >= off) ? part[t - off] : 0;
        __syncthreads();
        part[t] += v;
        __syncthreads();
    }
    int run = (t == 0) ? 0 : part[t - 1];
    for (int i = 0; i < chunk; i++) {
        int idx = b + i;
        if (idx < n) {
            rowptr[idx] = run;
            cursor[idx] = run;
            run += deg[idx];
        }
    }
    if (t == 1023) rowptr[n] = part[1023];
}

__global__ void scatter_kernel(const int* __restrict__ edge, int E,
                               int* __restrict__ cursor, int* __restrict__ csr)
{
    int e = blockIdx.x * blockDim.x + threadIdx.x;
    if (e < E) {
        int pos = atomicAdd(&cursor[edge[E + e]], 1);
        csr[pos] = edge[e];
    }
}

// ---------------- fused softmax + aggregation: warp per dst node ----------------
// out[d,:] = relu( sum_e alpha_e * h_src[e,:] ), alpha = softmax over incoming edges.
__global__ __launch_bounds__(256)
void han_agg(const int* __restrict__ rowptr, const int* __restrict__ csr_src,
             const float* __restrict__ asrc, const float* __restrict__ adst,
             const float* __restrict__ hsrc, float* __restrict__ out, int N)
{
    int gtid = blockIdx.x * blockDim.x + threadIdx.x;
    int d = gtid >> 5;
    int lane = threadIdx.x & 31;
    if (d >= N) return;

    const int beg = rowptr[d], end = rowptr[d + 1];
    const int deg = end - beg;
    float4* o = reinterpret_cast<float4*>(out) + (size_t)d * 32 + lane;
    if (deg == 0) { *o = make_float4(0.f, 0.f, 0.f, 0.f); return; }

    // passes 1+2 layout: lane = eo*8 + h8  (4 edge slots x 8 heads)
    const int h8 = lane & 7, eo0 = lane >> 3;
    const float ad8 = adst[(size_t)d * 8 + h8];

    float mx = -INFINITY;
    for (int i = eo0; i < deg; i += 4) {
        int s = csr_src[beg + i];
        mx = fmaxf(mx, lrelu02(asrc[(size_t)s * 8 + h8] + ad8));
    }
    mx = fmaxf(mx, __shfl_xor_sync(0xffffffffu, mx, 8));
    mx = fmaxf(mx, __shfl_xor_sync(0xffffffffu, mx, 16));

    float den = 0.f;
    for (int i = eo0; i < deg; i += 4) {
        int s = csr_src[beg + i];
        den += __expf(lrelu02(asrc[(size_t)s * 8 + h8] + ad8) - mx);
    }
    den += __shfl_xor_sync(0xffffffffu, den, 8);
    den += __shfl_xor_sync(0xffffffffu, den, 16);

    // pass 3 layout: lane owns output cols lane*4..+3 -> head hh = lane>>2
    const int hh = lane >> 2;
    const float mxh  = __shfl_sync(0xffffffffu, mx, hh);
    const float adh  = __shfl_sync(0xffffffffu, ad8, hh);
    const float invd = 1.f / (__shfl_sync(0xffffffffu, den, hh) + 1e-16f);

    float a0 = 0.f, a1 = 0.f, a2 = 0.f, a3 = 0.f;
    for (int i = 0; i < deg; i++) {
        int s = csr_src[beg + i];
        float e = lrelu02(asrc[(size_t)s * 8 + hh] + adh);
        float alpha = __expf(e - mxh) * invd;
        float4 hv = reinterpret_cast<const float4*>(hsrc)[(size_t)s * 32 + lane];
        a0 += hv.x * alpha; a1 += hv.y * alpha;
        a2 += hv.z * alpha; a3 += hv.w * alpha;
    }
    *o = make_float4(fmaxf(a0, 0.f), fmaxf(a1, 0.f), fmaxf(a2, 0.f), fmaxf(a3, 0.f));
}

// ---------------- semantic softmax beta ----------------
__global__ void beta_kernel(const float* __restrict__ acc, const float* __restrict__ q,
                            float* __restrict__ beta)
{
    __shared__ float red[2][4];
    int t = threadIdx.x;  // 128 threads
    float s0 = q[t] * acc[t]       * (1.f / N_NEWS);
    float s1 = q[t] * acc[128 + t] * (1.f / N_NEWS);
#pragma unroll
    for (int off = 16; off; off >>= 1) {
        s0 += __shfl_down_sync(0xffffffffu, s0, off);
        s1 += __shfl_down_sync(0xffffffffu, s1, off);
    }
    if ((t & 31) == 0) { red[0][t >> 5] = s0; red[1][t >> 5] = s1; }
    __syncthreads();
    if (t == 0) {
        float sc0 = red[0][0] + red[0][1] + red[0][2] + red[0][3];
        float sc1 = red[1][0] + red[1][1] + red[1][2] + red[1][3];
        float mx = fmaxf(sc0, sc1);
        float e0 = __expf(sc0 - mx), e1 = __expf(sc1 - mx);
        float inv = 1.f / (e0 + e1);
        beta[0] = e0 * inv;
        beta[1] = e1 * inv;
    }
}

// ---------------- final: fuse + ELU + [128x4] head (warp per node) ----------------
__global__ void final_kernel(const float* __restrict__ onn, const float* __restrict__ oin,
                             const float* __restrict__ beta, const float* __restrict__ Wout,
                             const float* __restrict__ bout, float* __restrict__ y)
{
    __shared__ float sw[HID * 4];
    for (int i = threadIdx.x; i < HID * 4; i += blockDim.x) sw[i] = Wout[i];
    __syncthreads();

    int gtid = blockIdx.x * blockDim.x + threadIdx.x;
    int node = gtid >> 5;
    int lane = threadIdx.x & 31;
    if (node >= N_NEWS) return;

    float b0 = beta[0], b1 = beta[1];
    float4 a = reinterpret_cast<const float4*>(onn)[(size_t)node * 32 + lane];
    float4 b = reinterpret_cast<const float4*>(oin)[(size_t)node * 32 + lane];
    float f[4] = { b0 * a.x + b1 * b.x, b0 * a.y + b1 * b.y,
                   b0 * a.z + b1 * b.z, b0 * a.w + b1 * b.w };   // inputs already relu'd
#pragma unroll
    for (int u = 0; u < 4; u++) f[u] = f[u] > 0.f ? f[u] : (__expf(f[u]) - 1.f);

    float p[4] = { 0.f, 0.f, 0.f, 0.f };
#pragma unroll
    for (int u = 0; u < 4; u++) {
        int r = lane * 4 + u;
#pragma unroll
        for (int c = 0; c < 4; c++) p[c] += f[u] * sw[r * 4 + c];
    }
#pragma unroll
    for (int off = 16; off; off >>= 1)
#pragma unroll
        for (int c = 0; c < 4; c++) p[c] += __shfl_down_sync(0xffffffffu, p[c], off);
    if (lane == 0) {
#pragma unroll
        for (int c = 0; c < 4; c++) y[(size_t)node * 4 + c] = p[c] + bout[c];
    }
}

// ---------------- host ----------------
static inline int cdiv(int a, int b) { return (a + b - 1) / b; }

extern "C" void kernel_launch(void* const* d_in, const int* in_sizes, int n_in,
                              void* d_out, int out_size)
{
    const float* x_news   = (const float*)d_in[0];
    const float* x_inter  = (const float*)d_in[1];
    const int*   edge_nn  = (const int*)  d_in[2];
    const int*   edge_in  = (const int*)  d_in[3];
    const float* W_news   = (const float*)d_in[4];
    const float* b_news   = (const float*)d_in[5];
    const float* W_inter  = (const float*)d_in[6];
    const float* b_inter  = (const float*)d_in[7];
    const float* a_src_nn = (const float*)d_in[8];
    const float* a_dst_nn = (const float*)d_in[9];
    const float* a_src_in = (const float*)d_in[10];
    const float* a_dst_in = (const float*)d_in[11];
    const float* Wk       = (const float*)d_in[12];
    const float* bk       = (const float*)d_in[13];
    const float* q        = (const float*)d_in[14];
    const float* W_out    = (const float*)d_in[15];
    const float* b_out    = (const float*)d_in[16];
    float* y = (float*)d_out;

    const int E_nn = in_sizes[2] / 2;
    const int E_in = in_sizes[3] / 2;

    float *h_news, *h_inter, *out_nn, *out_in, *Bt;
    float *asrc_nn, *adst_nn, *asrc_in, *adst_in, *accsem, *beta;
    int *deg_nn, *deg_in, *rp_nn, *rp_in, *cur_nn, *cur_in, *csr_nn, *csr_in;
    cudaGetSymbolAddress((void**)&h_news,  g_h_news);
    cudaGetSymbolAddress((void**)&h_inter, g_h_inter);
    cudaGetSymbolAddress((void**)&out_nn,  g_out_nn);
    cudaGetSymbolAddress((void**)&out_in,  g_out_in);
    cudaGetSymbolAddress((void**)&Bt,      g_Bt);
    cudaGetSymbolAddress((void**)&asrc_nn, g_asrc_nn);
    cudaGetSymbolAddress((void**)&adst_nn, g_adst_nn);
    cudaGetSymbolAddress((void**)&asrc_in, g_asrc_in);
    cudaGetSymbolAddress((void**)&adst_in, g_adst_in);
    cudaGetSymbolAddress((void**)&deg_nn,  g_deg_nn);
    cudaGetSymbolAddress((void**)&deg_in,  g_deg_in);
    cudaGetSymbolAddress((void**)&rp_nn,   g_rp_nn);
    cudaGetSymbolAddress((void**)&rp_in,   g_rp_in);
    cudaGetSymbolAddress((void**)&cur_nn,  g_cur_nn);
    cudaGetSymbolAddress((void**)&cur_in,  g_cur_in);
    cudaGetSymbolAddress((void**)&csr_nn,  g_csr_nn);
    cudaGetSymbolAddress((void**)&csr_in,  g_csr_in);
    cudaGetSymbolAddress((void**)&accsem,  g_accsem);
    cudaGetSymbolAddress((void**)&beta,    g_beta);

    const int T = 256;
    const int SMEM_GEMM = 2 * 2 * BUF_F * 4;   // 73728 bytes
    cudaFuncSetAttribute(mma_gemm, cudaFuncAttributeMaxDynamicSharedMemorySize, SMEM_GEMM);

    // ---- CSR build (independent of GEMMs) ----
    zero_int<<<cdiv(N_NEWS, T), T>>>(deg_nn, N_NEWS);
    zero_int<<<cdiv(N_NEWS, T), T>>>(deg_in, N_NEWS);
    fill_kernel<<<1, T>>>(accsem, 2 * HID, 0.f);
    hist_kernel<<<cdiv(E_nn, T), T>>>(edge_nn, E_nn, deg_nn);
    hist_kernel<<<cdiv(E_in, T), T>>>(edge_in, E_in, deg_in);
    scan_kernel<<<1, 1024>>>(deg_nn, rp_nn, cur_nn, N_NEWS);
    scan_kernel<<<1, 1024>>>(deg_in, rp_in, cur_in, N_NEWS);
    scatter_kernel<<<cdiv(E_nn, T), T>>>(edge_nn, E_nn, cur_nn, csr_nn);
    scatter_kernel<<<cdiv(E_in, T), T>>>(edge_in, E_in, cur_in, csr_in);

    // ---- projections (tf32 mma) ----
    transpose_w<<<cdiv(768 * 128, T), T>>>(W_news, Bt, 768);
    mma_gemm<<<cdiv(N_NEWS, 128), 256, SMEM_GEMM>>>(x_news, Bt, b_news, h_news, N_NEWS, 768, 0);
    transpose_w<<<cdiv(768 * 128, T), T>>>(W_inter, Bt, 768);
    mma_gemm<<<cdiv(N_INTER, 128), 256, SMEM_GEMM>>>(x_inter, Bt, b_inter, h_inter, N_INTER, 768, 0);

    // ---- node-level attention coefficients ----
    att_dot<<<cdiv(N_NEWS  * NH, T), T>>>(h_news,  a_src_nn, asrc_nn, N_NEWS);
    att_dot<<<cdiv(N_NEWS  * NH, T), T>>>(h_news,  a_dst_nn, adst_nn, N_NEWS);
    att_dot<<<cdiv(N_INTER * NH, T), T>>>(h_inter, a_src_in, asrc_in, N_INTER);
    att_dot<<<cdiv(N_NEWS  * NH, T), T>>>(h_news,  a_dst_in, adst_in, N_NEWS);

    // ---- fused softmax + aggregation (warp per dst node, no atomics) ----
    han_agg<<<cdiv(N_NEWS * 32, T), T>>>(rp_nn, csr_nn, asrc_nn, adst_nn, h_news,  out_nn, N_NEWS);
    han_agg<<<cdiv(N_NEWS * 32, T), T>>>(rp_in, csr_in, asrc_in, adst_in, h_inter, out_in, N_NEWS);

    // ---- semantic attention (out_* already relu'd -> fast path) ----
    transpose_w<<<cdiv(128 * 128, T), T>>>(Wk, Bt, 128);
    mma_gemm<<<cdiv(N_NEWS, 128), 256, SMEM_GEMM>>>(out_nn, Bt, bk, accsem,       N_NEWS, 128, 1);
    mma_gemm<<<cdiv(N_NEWS, 128), 256, SMEM_GEMM>>>(out_in, Bt, bk, accsem + 128, N_NEWS, 128, 1);
    beta_kernel<<<1, 128>>>(accsem, q, beta);

    // ---- fuse + ELU + output head ----
    final_kernel<<<cdiv(N_NEWS * 32, T), T>>>(out_nn, out_in, beta, W_out, b_out, y);
}

// round 5
// speedup vs baseline: 2.9662x; 1.2516x over previous
#include <cuda_runtime.h>
#include <math.h>
#include <stdint.h>

#define N_NEWS  30000
#define N_INTER 60000
#define HID 128
#define NH  8
#define HD  16
#define E_NN_CAP 480000
#define E_IN_CAP 960000

// ---------------- scratch (static device globals; no allocation) ----------------
__device__ float g_h_news [N_NEWS  * HID];
__device__ float g_h_inter[N_INTER * HID];
__device__ float g_out_nn [N_NEWS  * HID];
__device__ float g_out_in [N_NEWS  * HID];
__device__ float g_BtN    [HID * 768];       // W_news^T, tf32-rounded bits
__device__ float g_BtI    [HID * 768];       // W_inter^T, tf32-rounded bits
__device__ float g_BtK    [HID * HID];       // Wk^T, tf32-rounded bits
__device__ float g_asrc_nn[N_NEWS  * NH];
__device__ float g_adst_nn[N_NEWS  * NH];
__device__ float g_asrc_in[N_INTER * NH];
__device__ float g_adst_in[N_NEWS  * NH];
__device__ int   g_deg_nn [N_NEWS];
__device__ int   g_deg_in [N_NEWS];
__device__ int   g_rp_nn  [N_NEWS + 1];
__device__ int   g_rp_in  [N_NEWS + 1];
__device__ int   g_cur_nn [N_NEWS];
__device__ int   g_cur_in [N_NEWS];
__device__ int   g_csr_nn [E_NN_CAP];
__device__ int   g_csr_in [E_IN_CAP];
__device__ float g_accsem[2 * HID];
__device__ float g_beta  [2];

// ---------------- init ----------------
__global__ void fill_kernel(float* __restrict__ p, int n, float v) {
    int i = blockIdx.x * blockDim.x + threadIdx.x;
    if (i < n) p[i] = v;
}
__global__ void zero_int(int* __restrict__ p, int n) {
    int i = blockIdx.x * blockDim.x + threadIdx.x;
    if (i < n) p[i] = 0;
}

// ---------------- helpers ----------------
static __device__ __forceinline__ uint32_t smem_u32(const void* p) {
    uint32_t r;
    asm("{ .reg .u64 t; cvta.to.shared.u64 t, %1; cvt.u32.u64 %0, t; }" : "=r"(r) : "l"(p));
    return r;
}
static __device__ __forceinline__ uint32_t f2tf(float x) {
    uint32_t r;
    asm("cvt.rna.tf32.f32 %0, %1;" : "=r"(r) : "f"(x));
    return r;
}
static __device__ __forceinline__ void mma_tf32(float* c, const uint32_t* a, const uint32_t* b) {
    asm volatile(
        "mma.sync.aligned.m16n8k8.row.col.f32.tf32.tf32.f32 "
        "{%0,%1,%2,%3},{%4,%5,%6,%7},{%8,%9},{%0,%1,%2,%3};"
        : "+f"(c[0]), "+f"(c[1]), "+f"(c[2]), "+f"(c[3])
        : "r"(a[0]), "r"(a[1]), "r"(a[2]), "r"(a[3]), "r"(b[0]), "r"(b[1]));
}
static __device__ __forceinline__ void cp16(uint32_t dst, const void* src) {
    asm volatile("cp.async.cg.shared.global [%0], [%1], 16;" :: "r"(dst), "l"(src));
}
static __device__ __forceinline__ void ldsm4(uint32_t* r, uint32_t addr) {
    asm volatile("ldmatrix.sync.aligned.m8n8.x4.shared.b16 {%0,%1,%2,%3}, [%4];"
                 : "=r"(r[0]), "=r"(r[1]), "=r"(r[2]), "=r"(r[3]) : "r"(addr));
}

// ---------------- transpose + tf32-round all weights in one pass ----------------
__global__ void transpose_all(const float* __restrict__ Wn, const float* __restrict__ Wi,
                              const float* __restrict__ Wk,
                              float* __restrict__ BtN, float* __restrict__ BtI,
                              float* __restrict__ BtK)
{
    int i = blockIdx.x * blockDim.x + threadIdx.x;   // over 768*128 (write-coalesced)
    if (i < 768 * 128) {
        int n = i / 768, k = i % 768;
        BtN[i] = __uint_as_float(f2tf(Wn[k * 128 + n]));
        BtI[i] = __uint_as_float(f2tf(Wi[k * 128 + n]));
    }
    if (i < 128 * 128) {
        int n = i >> 7, k = i & 127;
        BtK[i] = __uint_as_float(f2tf(Wk[k * 128 + n]));
    }
}

// ---------------- tf32 tensor-core GEMM (dual-part merged launch) ----------------
// Part p covers blocks [0,nb1) / [nb1,grid): C[M,128] = A[M,K] @ Bt^T (+bias).
// Bt holds tf32-rounded bits. A converted in-kernel (LDG->cvt->STS), B via cp.async.
// semantic=0: C[m,n] = acc + bias[n]
// semantic=1: atomicAdd(C[n], sum_{m<M} tanh(acc + bias[n]))
#define LDT 36              // padded row length (floats)
#define BUF_F (128 * LDT)   // floats per (A or B) tile

__global__ __launch_bounds__(256, 2)
void mma_gemm(const float* __restrict__ A1, const float* __restrict__ A2,
              const float* __restrict__ Bt1, const float* __restrict__ Bt2,
              const float* __restrict__ bias1, const float* __restrict__ bias2,
              float* __restrict__ C1, float* __restrict__ C2,
              int M1, int M2, int nb1, int K, int semantic)
{
    extern __shared__ float smem[];     // [2][A + B] tiles
    __shared__ float s_bias[128];
    __shared__ float s_col[128];

    const int tid  = threadIdx.x;
    const int warp = tid >> 5;
    const int lane = tid & 31;
    const int group = lane >> 2, tig = lane & 3;
    const int warpM = warp & 3, warpN = warp >> 2;
    const int mbase = warpM * 32, nbase = warpN * 64;

    const float* A; const float* Bt; const float* bias; float* C; int M, m0;
    if ((int)blockIdx.x < nb1) {
        A = A1; Bt = Bt1; bias = bias1; C = C1; M = M1; m0 = blockIdx.x * 128;
    } else {
        A = A2; Bt = Bt2; bias = bias2; C = C2; M = M2; m0 = (blockIdx.x - nb1) * 128;
    }

    if (tid < 128) { s_bias[tid] = bias[tid]; s_col[tid] = 0.f; }

    float acc[2][8][4];
#pragma unroll
    for (int i = 0; i < 2; i++)
#pragma unroll
        for (int j = 0; j < 8; j++)
#pragma unroll
            for (int l = 0; l < 4; l++) acc[i][j][l] = 0.f;

    const int nchunk = K >> 5;
    const uint32_t smem_b = smem_u32(smem);

    // per-thread tile-load coords: 4 rows (rowL+32l), fixed q
    const int rowL = tid >> 3, qL = tid & 7;
    // per-lane ldmatrix offsets (bytes, within tile)
    const int blk = lane >> 3, rr = lane & 7;
    const uint32_t offA = (uint32_t)(((mbase + (blk & 1) * 8 + rr) * LDT + (blk >> 1) * 4) * 4);
    const uint32_t offB = (uint32_t)(((nbase + (blk >> 1) * 8 + rr) * LDT + (blk & 1) * 4) * 4);

    // prefetch A chunk 0 into regs
    float4 pA[4];
#pragma unroll
    for (int l = 0; l < 4; l++) {
        int m = m0 + rowL + 32 * l;
        pA[l] = (m < M) ? *reinterpret_cast<const float4*>(A + (size_t)m * K + qL * 4)
                        : make_float4(0.f, 0.f, 0.f, 0.f);
    }
    // cp.async B chunk 0 into buf 0
#pragma unroll
    for (int l = 0; l < 4; l++) {
        int row = rowL + 32 * l;
        cp16(smem_b + (uint32_t)((BUF_F + row * LDT + qL * 4) << 2),
             Bt + (size_t)row * K + qL * 4);
    }
    asm volatile("cp.async.commit_group;");

    for (int c = 0; c < nchunk; c++) {
        const uint32_t bufo = (uint32_t)((c & 1) * 2 * BUF_F) << 2;
        // store A(c): cvt to tf32 bits, STS.128
#pragma unroll
        for (int l = 0; l < 4; l++) {
            int row = rowL + 32 * l;
            float4 v = pA[l];
            float4 u = make_float4(__uint_as_float(f2tf(v.x)), __uint_as_float(f2tf(v.y)),
                                   __uint_as_float(f2tf(v.z)), __uint_as_float(f2tf(v.w)));
            *reinterpret_cast<float4*>(smem + (c & 1) * 2 * BUF_F + row * LDT + qL * 4) = u;
        }
        // issue B(c+1), ensure B(c) done
        if (c + 1 < nchunk) {
            const int kb = (c + 1) * 32;
            const uint32_t bufo2 = (uint32_t)(((c + 1) & 1) * 2 * BUF_F) << 2;
#pragma unroll
            for (int l = 0; l < 4; l++) {
                int row = rowL + 32 * l;
                cp16(smem_b + bufo2 + (uint32_t)((BUF_F + row * LDT + qL * 4) << 2),
                     Bt + (size_t)row * K + kb + qL * 4);
            }
            asm volatile("cp.async.commit_group;");
            asm volatile("cp.async.wait_group 1;");
        } else {
            asm volatile("cp.async.wait_group 0;");
        }
        __syncthreads();
        // prefetch A(c+1) into regs (latency hidden by compute)
        if (c + 1 < nchunk) {
            const int kb = (c + 1) * 32;
#pragma unroll
            for (int l = 0; l < 4; l++) {
                int m = m0 + rowL + 32 * l;
                pA[l] = (m < M) ? *reinterpret_cast<const float4*>(A + (size_t)m * K + kb + qL * 4)
                                : make_float4(0.f, 0.f, 0.f, 0.f);
            }
        }
        // compute from buf (c&1) via ldmatrix
        const uint32_t Asb = smem_b + bufo;
        const uint32_t Bsb = Asb + (uint32_t)(BUF_F << 2);
#pragma unroll
        for (int ks = 0; ks < 4; ks++) {
            uint32_t af[2][4], bf[8][2];
            ldsm4(af[0], Asb + offA + (uint32_t)((ks * 8) << 2));
            ldsm4(af[1], Asb + offA + (uint32_t)((16 * LDT + ks * 8) << 2));
#pragma unroll
            for (int na2 = 0; na2 < 8; na2 += 2) {
                uint32_t t[4];
                ldsm4(t, Bsb + offB + (uint32_t)((na2 * 8 * LDT + ks * 8) << 2));
                bf[na2][0] = t[0]; bf[na2][1] = t[1];
                bf[na2 + 1][0] = t[2]; bf[na2 + 1][1] = t[3];
            }
#pragma unroll
            for (int ma = 0; ma < 2; ma++)
#pragma unroll
                for (int na = 0; na < 8; na++)
                    mma_tf32(acc[ma][na], af[ma], bf[na]);
        }
        __syncthreads();
    }

    // -------- epilogue --------
    if (!semantic) {
#pragma unroll
        for (int ma = 0; ma < 2; ma++) {
            int row = m0 + mbase + ma * 16 + group;
#pragma unroll
            for (int na = 0; na < 8; na++) {
                int col = nbase + na * 8 + tig * 2;
                if (row < M) {
                    float2 v = { acc[ma][na][0] + s_bias[col],
                                 acc[ma][na][1] + s_bias[col + 1] };
                    *reinterpret_cast<float2*>(C + (size_t)row * 128 + col) = v;
                }
                if (row + 8 < M) {
                    float2 v = { acc[ma][na][2] + s_bias[col],
                                 acc[ma][na][3] + s_bias[col + 1] };
                    *reinterpret_cast<float2*>(C + (size_t)(row + 8) * 128 + col) = v;
                }
            }
        }
    } else {
#pragma unroll
        for (int na = 0; na < 8; na++) {
            int col = nbase + na * 8 + tig * 2;
            float p0 = 0.f, p1 = 0.f;
#pragma unroll
            for (int ma = 0; ma < 2; ma++) {
                int row = m0 + mbase + ma * 16 + group;
                if (row < M) {
                    p0 += tanhf(acc[ma][na][0] + s_bias[col]);
                    p1 += tanhf(acc[ma][na][1] + s_bias[col + 1]);
                }
                if (row + 8 < M) {
                    p0 += tanhf(acc[ma][na][2] + s_bias[col]);
                    p1 += tanhf(acc[ma][na][3] + s_bias[col + 1]);
                }
            }
            atomicAdd(&s_col[col], p0);
            atomicAdd(&s_col[col + 1], p1);
        }
        __syncthreads();
        if (tid < 128) atomicAdd(&C[tid], s_col[tid]);
    }
}

// ---------------- attention dots: 3 vectors in one pass (news side) ----------------
__global__ void att_dot3(const float* __restrict__ h,
                         const float* __restrict__ v0, const float* __restrict__ v1,
                         const float* __restrict__ v2,
                         float* __restrict__ o0, float* __restrict__ o1,
                         float* __restrict__ o2, int N)
{
    __shared__ float sv[3][128];
    if (threadIdx.x < 128) {
        sv[0][threadIdx.x] = v0[threadIdx.x];
        sv[1][threadIdx.x] = v1[threadIdx.x];
        sv[2][threadIdx.x] = v2[threadIdx.x];
    }
    __syncthreads();
    int i = blockIdx.x * blockDim.x + threadIdx.x;
    if (i < N * NH) {
        int n = i >> 3, hh = i & 7;
        const float* hp = h + (size_t)n * HID + hh * HD;
        float s0 = 0.f, s1 = 0.f, s2 = 0.f;
#pragma unroll
        for (int d = 0; d < HD; d++) {
            float x = hp[d];
            s0 += x * sv[0][hh * HD + d];
            s1 += x * sv[1][hh * HD + d];
            s2 += x * sv[2][hh * HD + d];
        }
        o0[i] = s0; o1[i] = s1; o2[i] = s2;
    }
}

__global__ void att_dot(const float* __restrict__ h, const float* __restrict__ vec,
                        float* __restrict__ out, int N)
{
    __shared__ float sv[128];
    if (threadIdx.x < 128) sv[threadIdx.x] = vec[threadIdx.x];
    __syncthreads();
    int i = blockIdx.x * blockDim.x + threadIdx.x;
    if (i < N * NH) {
        int n = i >> 3, hh = i & 7;
        const float* hp = h + (size_t)n * HID + hh * HD;
        float s = 0.f;
#pragma unroll
        for (int d = 0; d < HD; d++) s += hp[d] * sv[hh * HD + d];
        out[i] = s;
    }
}

__device__ __forceinline__ float lrelu02(float x) { return x > 0.f ? x : 0.2f * x; }

// ---------------- CSR build ----------------
__global__ void hist_kernel(const int* __restrict__ edge, int E, int* __restrict__ deg) {
    int e = blockIdx.x * blockDim.x + threadIdx.x;
    if (e < E) atomicAdd(&deg[edge[E + e]], 1);
}

__global__ void scan_kernel(const int* __restrict__ deg, int* __restrict__ rowptr,
                            int* __restrict__ cursor, int n)
{
    __shared__ int part[1024];
    const int t = threadIdx.x;
    const int chunk = (n + 1023) >> 10;
    const int b = t * chunk;
    int sum = 0;
    for (int i = 0; i < chunk; i++) { int idx = b + i; if (idx < n) sum += deg[idx]; }
    part[t] = sum;
    __syncthreads();
    for (int off = 1; off < 1024; off <<= 1) {
        int v = (t >= off) ? part[t - off] : 0;
        __syncthreads();
        part[t] += v;
        __syncthreads();
    }
    int run = (t == 0) ? 0 : part[t - 1];
    for (int i = 0; i < chunk; i++) {
        int idx = b + i;
        if (idx < n) {
            rowptr[idx] = run;
            cursor[idx] = run;
            run += deg[idx];
        }
    }
    if (t == 1023) rowptr[n] = part[1023];
}

__global__ void scatter_kernel(const int* __restrict__ edge, int E,
                               int* __restrict__ cursor, int* __restrict__ csr)
{
    int e = blockIdx.x * blockDim.x + threadIdx.x;
    if (e < E) {
        int pos = atomicAdd(&cursor[edge[E + e]], 1);
        csr[pos] = edge[e];
    }
}

// ---------------- fused softmax + aggregation: warp per dst node ----------------
__global__ __launch_bounds__(256)
void han_agg(const int* __restrict__ rowptr, const int* __restrict__ csr_src,
             const float* __restrict__ asrc, const float* __restrict__ adst,
             const float* __restrict__ hsrc, float* __restrict__ out, int N)
{
    int gtid = blockIdx.x * blockDim.x + threadIdx.x;
    int d = gtid >> 5;
    int lane = threadIdx.x & 31;
    if (d >= N) return;

    const int beg = rowptr[d], end = rowptr[d + 1];
    const int deg = end - beg;
    float4* o = reinterpret_cast<float4*>(out) + (size_t)d * 32 + lane;
    if (deg == 0) { *o = make_float4(0.f, 0.f, 0.f, 0.f); return; }

    const int h8 = lane & 7, eo0 = lane >> 3;
    const float ad8 = adst[(size_t)d * 8 + h8];

    float mx = -INFINITY;
    for (int i = eo0; i < deg; i += 4) {
        int s = csr_src[beg + i];
        mx = fmaxf(mx, lrelu02(asrc[(size_t)s * 8 + h8] + ad8));
    }
    mx = fmaxf(mx, __shfl_xor_sync(0xffffffffu, mx, 8));
    mx = fmaxf(mx, __shfl_xor_sync(0xffffffffu, mx, 16));

    float den = 0.f;
    for (int i = eo0; i < deg; i += 4) {
        int s = csr_src[beg + i];
        den += __expf(lrelu02(asrc[(size_t)s * 8 + h8] + ad8) - mx);
    }
    den += __shfl_xor_sync(0xffffffffu, den, 8);
    den += __shfl_xor_sync(0xffffffffu, den, 16);

    const int hh = lane >> 2;
    const float mxh  = __shfl_sync(0xffffffffu, mx, hh);
    const float adh  = __shfl_sync(0xffffffffu, ad8, hh);
    const float invd = 1.f / (__shfl_sync(0xffffffffu, den, hh) + 1e-16f);

    float a0 = 0.f, a1 = 0.f, a2 = 0.f, a3 = 0.f;
    for (int i = 0; i < deg; i++) {
        int s = csr_src[beg + i];
        float e = lrelu02(asrc[(size_t)s * 8 + hh] + adh);
        float alpha = __expf(e - mxh) * invd;
        float4 hv = reinterpret_cast<const float4*>(hsrc)[(size_t)s * 32 + lane];
        a0 += hv.x * alpha; a1 += hv.y * alpha;
        a2 += hv.z * alpha; a3 += hv.w * alpha;
    }
    *o = make_float4(fmaxf(a0, 0.f), fmaxf(a1, 0.f), fmaxf(a2, 0.f), fmaxf(a3, 0.f));
}

// ---------------- semantic softmax beta ----------------
__global__ void beta_kernel(const float* __restrict__ acc, const float* __restrict__ q,
                            float* __restrict__ beta)
{
    __shared__ float red[2][4];
    int t = threadIdx.x;  // 128 threads
    float s0 = q[t] * acc[t]       * (1.f / N_NEWS);
    float s1 = q[t] * acc[128 + t] * (1.f / N_NEWS);
#pragma unroll
    for (int off = 16; off; off >>= 1) {
        s0 += __shfl_down_sync(0xffffffffu, s0, off);
        s1 += __shfl_down_sync(0xffffffffu, s1, off);
    }
    if ((t & 31) == 0) { red[0][t >> 5] = s0; red[1][t >> 5] = s1; }
    __syncthreads();
    if (t == 0) {
        float sc0 = red[0][0] + red[0][1] + red[0][2] + red[0][3];
        float sc1 = red[1][0] + red[1][1] + red[1][2] + red[1][3];
        float mx = fmaxf(sc0, sc1);
        float e0 = __expf(sc0 - mx), e1 = __expf(sc1 - mx);
        float inv = 1.f / (e0 + e1);
        beta[0] = e0 * inv;
        beta[1] = e1 * inv;
    }
}

// ---------------- final: fuse + ELU + [128x4] head (warp per node) ----------------
__global__ void final_kernel(const float* __restrict__ onn, const float* __restrict__ oin,
                             const float* __restrict__ beta, const float* __restrict__ Wout,
                             const float* __restrict__ bout, float* __restrict__ y)
{
    __shared__ float sw[HID * 4];
    for (int i = threadIdx.x; i < HID * 4; i += blockDim.x) sw[i] = Wout[i];
    __syncthreads();

    int gtid = blockIdx.x * blockDim.x + threadIdx.x;
    int node = gtid >> 5;
    int lane = threadIdx.x & 31;
    if (node >= N_NEWS) return;

    float b0 = beta[0], b1 = beta[1];
    float4 a = reinterpret_cast<const float4*>(onn)[(size_t)node * 32 + lane];
    float4 b = reinterpret_cast<const float4*>(oin)[(size_t)node * 32 + lane];
    float f[4] = { b0 * a.x + b1 * b.x, b0 * a.y + b1 * b.y,
                   b0 * a.z + b1 * b.z, b0 * a.w + b1 * b.w };   // inputs already relu'd
#pragma unroll
    for (int u = 0; u < 4; u++) f[u] = f[u] > 0.f ? f[u] : (__expf(f[u]) - 1.f);

    float p[4] = { 0.f, 0.f, 0.f, 0.f };
#pragma unroll
    for (int u = 0; u < 4; u++) {
        int r = lane * 4 + u;
#pragma unroll
        for (int c = 0; c < 4; c++) p[c] += f[u] * sw[r * 4 + c];
    }
#pragma unroll
    for (int off = 16; off; off >>= 1)
#pragma unroll
        for (int c = 0; c < 4; c++) p[c] += __shfl_down_sync(0xffffffffu, p[c], off);
    if (lane == 0) {
#pragma unroll
        for (int c = 0; c < 4; c++) y[(size_t)node * 4 + c] = p[c] + bout[c];
    }
}

// ---------------- host ----------------
static inline int cdiv(int a, int b) { return (a + b - 1) / b; }

extern "C" void kernel_launch(void* const* d_in, const int* in_sizes, int n_in,
                              void* d_out, int out_size)
{
    const float* x_news   = (const float*)d_in[0];
    const float* x_inter  = (const float*)d_in[1];
    const int*   edge_nn  = (const int*)  d_in[2];
    const int*   edge_in  = (const int*)  d_in[3];
    const float* W_news   = (const float*)d_in[4];
    const float* b_news   = (const float*)d_in[5];
    const float* W_inter  = (const float*)d_in[6];
    const float* b_inter  = (const float*)d_in[7];
    const float* a_src_nn = (const float*)d_in[8];
    const float* a_dst_nn = (const float*)d_in[9];
    const float* a_src_in = (const float*)d_in[10];
    const float* a_dst_in = (const float*)d_in[11];
    const float* Wk       = (const float*)d_in[12];
    const float* bk       = (const float*)d_in[13];
    const float* q        = (const float*)d_in[14];
    const float* W_out    = (const float*)d_in[15];
    const float* b_out    = (const float*)d_in[16];
    float* y = (float*)d_out;

    const int E_nn = in_sizes[2] / 2;
    const int E_in = in_sizes[3] / 2;

    float *h_news, *h_inter, *out_nn, *out_in, *BtN, *BtI, *BtK;
    float *asrc_nn, *adst_nn, *asrc_in, *adst_in, *accsem, *beta;
    int *deg_nn, *deg_in, *rp_nn, *rp_in, *cur_nn, *cur_in, *csr_nn, *csr_in;
    cudaGetSymbolAddress((void**)&h_news,  g_h_news);
    cudaGetSymbolAddress((void**)&h_inter, g_h_inter);
    cudaGetSymbolAddress((void**)&out_nn,  g_out_nn);
    cudaGetSymbolAddress((void**)&out_in,  g_out_in);
    cudaGetSymbolAddress((void**)&BtN,     g_BtN);
    cudaGetSymbolAddress((void**)&BtI,     g_BtI);
    cudaGetSymbolAddress((void**)&BtK,     g_BtK);
    cudaGetSymbolAddress((void**)&asrc_nn, g_asrc_nn);
    cudaGetSymbolAddress((void**)&adst_nn, g_adst_nn);
    cudaGetSymbolAddress((void**)&asrc_in, g_asrc_in);
    cudaGetSymbolAddress((void**)&adst_in, g_adst_in);
    cudaGetSymbolAddress((void**)&deg_nn,  g_deg_nn);
    cudaGetSymbolAddress((void**)&deg_in,  g_deg_in);
    cudaGetSymbolAddress((void**)&rp_nn,   g_rp_nn);
    cudaGetSymbolAddress((void**)&rp_in,   g_rp_in);
    cudaGetSymbolAddress((void**)&cur_nn,  g_cur_nn);
    cudaGetSymbolAddress((void**)&cur_in,  g_cur_in);
    cudaGetSymbolAddress((void**)&csr_nn,  g_csr_nn);
    cudaGetSymbolAddress((void**)&csr_in,  g_csr_in);
    cudaGetSymbolAddress((void**)&accsem,  g_accsem);
    cudaGetSymbolAddress((void**)&beta,    g_beta);

    const int T = 256;
    const int SMEM_GEMM = 2 * 2 * BUF_F * 4;   // 73728 bytes
    cudaFuncSetAttribute(mma_gemm, cudaFuncAttributeMaxDynamicSharedMemorySize, SMEM_GEMM);

    // ---- CSR build + weight prep (independent of GEMMs) ----
    zero_int<<<cdiv(N_NEWS, T), T>>>(deg_nn, N_NEWS);
    zero_int<<<cdiv(N_NEWS, T), T>>>(deg_in, N_NEWS);
    fill_kernel<<<1, T>>>(accsem, 2 * HID, 0.f);
    transpose_all<<<cdiv(768 * 128, T), T>>>(W_news, W_inter, Wk, BtN, BtI, BtK);
    hist_kernel<<<cdiv(E_nn, T), T>>>(edge_nn, E_nn, deg_nn);
    hist_kernel<<<cdiv(E_in, T), T>>>(edge_in, E_in, deg_in);
    scan_kernel<<<1, 1024>>>(deg_nn, rp_nn, cur_nn, N_NEWS);
    scan_kernel<<<1, 1024>>>(deg_in, rp_in, cur_in, N_NEWS);
    scatter_kernel<<<cdiv(E_nn, T), T>>>(edge_nn, E_nn, cur_nn, csr_nn);
    scatter_kernel<<<cdiv(E_in, T), T>>>(edge_in, E_in, cur_in, csr_in);

    // ---- projections (merged dual-part tf32 mma) ----
    const int nb1 = cdiv(N_NEWS, 128), nb2 = cdiv(N_INTER, 128);
    mma_gemm<<<nb1 + nb2, 256, SMEM_GEMM>>>(x_news, x_inter, BtN, BtI, b_news, b_inter,
                                            h_news, h_inter, N_NEWS, N_INTER, nb1, 768, 0);

    // ---- node-level attention coefficients ----
    att_dot3<<<cdiv(N_NEWS * NH, T), T>>>(h_news, a_src_nn, a_dst_nn, a_dst_in,
                                          asrc_nn, adst_nn, adst_in, N_NEWS);
    att_dot<<<cdiv(N_INTER * NH, T), T>>>(h_inter, a_src_in, asrc_in, N_INTER);

    // ---- fused softmax + aggregation (warp per dst node, no atomics) ----
    han_agg<<<cdiv(N_NEWS * 32, T), T>>>(rp_nn, csr_nn, asrc_nn, adst_nn, h_news,  out_nn, N_NEWS);
    han_agg<<<cdiv(N_NEWS * 32, T), T>>>(rp_in, csr_in, asrc_in, adst_in, h_inter, out_in, N_NEWS);

    // ---- semantic attention (merged dual-part) ----
    mma_gemm<<<2 * nb1, 256, SMEM_GEMM>>>(out_nn, out_in, BtK, BtK, bk, bk,
                                          accsem, accsem + 128, N_NEWS, N_NEWS, nb1, 128, 1);
    beta_kernel<<<1, 128>>>(accsem, q, beta);

    // ---- fuse + ELU + output head ----
    final_kernel<<<cdiv(N_NEWS * 32, T), T>>>(out_nn, out_in, beta, W_out, b_out, y);
}

// round 6
// speedup vs baseline: 3.6408x; 1.2274x over previous
#include <cuda_runtime.h>
#include <math.h>
#include <stdint.h>

#define N_NEWS  30000
#define N_INTER 60000
#define HID 128
#define NH  8
#define HD  16
#define E_NN_CAP 480000
#define E_IN_CAP 960000

// ---------------- scratch (static device globals; no allocation) ----------------
__device__ float g_h_news [N_NEWS  * HID];
__device__ float g_h_inter[N_INTER * HID];
__device__ float g_out_nn [N_NEWS  * HID];
__device__ float g_out_in [N_NEWS  * HID];
__device__ float g_BtN    [HID * 768];       // W_news^T, tf32-rounded bits
__device__ float g_BtI    [HID * 768];       // W_inter^T, tf32-rounded bits
__device__ float g_BtK    [HID * HID];       // Wk^T, tf32-rounded bits
__device__ float g_asrc_nn[N_NEWS  * NH];
__device__ float g_adst_nn[N_NEWS  * NH];
__device__ float g_asrc_in[N_INTER * NH];
__device__ float g_adst_in[N_NEWS  * NH];
__device__ int   g_deg_nn [N_NEWS];
__device__ int   g_deg_in [N_NEWS];
__device__ int   g_rp_nn  [N_NEWS + 1];
__device__ int   g_rp_in  [N_NEWS + 1];
__device__ int   g_cur_nn [N_NEWS];
__device__ int   g_cur_in [N_NEWS];
__device__ int   g_csr_nn [E_NN_CAP];
__device__ int   g_csr_in [E_IN_CAP];
__device__ float g_accsem[2 * HID];
__device__ float g_beta  [2];

// ---------------- helpers ----------------
static __device__ __forceinline__ uint32_t smem_u32(const void* p) {
    uint32_t r;
    asm("{ .reg .u64 t; cvta.to.shared.u64 t, %1; cvt.u32.u64 %0, t; }" : "=r"(r) : "l"(p));
    return r;
}
static __device__ __forceinline__ uint32_t f2tf(float x) {
    uint32_t r;
    asm("cvt.rna.tf32.f32 %0, %1;" : "=r"(r) : "f"(x));
    return r;
}
static __device__ __forceinline__ void mma_tf32(float* c, const uint32_t* a, const uint32_t* b) {
    asm volatile(
        "mma.sync.aligned.m16n8k8.row.col.f32.tf32.tf32.f32 "
        "{%0,%1,%2,%3},{%4,%5,%6,%7},{%8,%9},{%0,%1,%2,%3};"
        : "+f"(c[0]), "+f"(c[1]), "+f"(c[2]), "+f"(c[3])
        : "r"(a[0]), "r"(a[1]), "r"(a[2]), "r"(a[3]), "r"(b[0]), "r"(b[1]));
}
static __device__ __forceinline__ void cp16(uint32_t dst, const void* src) {
    asm volatile("cp.async.cg.shared.global [%0], [%1], 16;" :: "r"(dst), "l"(src));
}
static __device__ __forceinline__ void ldsm4(uint32_t* r, uint32_t addr) {
    asm volatile("ldmatrix.sync.aligned.m8n8.x4.shared.b16 {%0,%1,%2,%3}, [%4];"
                 : "=r"(r[0]), "=r"(r[1]), "=r"(r[2]), "=r"(r[3]) : "r"(addr));
}
__device__ __forceinline__ float lrelu02(float x) { return x > 0.f ? x : 0.2f * x; }

// ---------------- setup: zero degree counters ----------------
__global__ void zero_deg2(int* __restrict__ d1, int* __restrict__ d2, int n) {
    int i = blockIdx.x * blockDim.x + threadIdx.x;
    if (i < n) { d1[i] = 0; d2[i] = 0; }
}

// ---------------- transpose + tf32-round all weights + zero accsem ----------------
__global__ void transpose_all(const float* __restrict__ Wn, const float* __restrict__ Wi,
                              const float* __restrict__ Wk,
                              float* __restrict__ BtN, float* __restrict__ BtI,
                              float* __restrict__ BtK, float* __restrict__ accsem)
{
    int i = blockIdx.x * blockDim.x + threadIdx.x;   // over 768*128 (write-coalesced)
    if (i < 768 * 128) {
        int n = i / 768, k = i % 768;
        BtN[i] = __uint_as_float(f2tf(Wn[k * 128 + n]));
        BtI[i] = __uint_as_float(f2tf(Wi[k * 128 + n]));
    }
    if (i < 128 * 128) {
        int n = i >> 7, k = i & 127;
        BtK[i] = __uint_as_float(f2tf(Wk[k * 128 + n]));
    }
    if (i < 2 * HID) accsem[i] = 0.f;
}

// ---------------- tf32 tensor-core GEMM (dual-part merged launch) ----------------
#define LDT 36              // padded row length (floats)
#define BUF_F (128 * LDT)   // floats per (A or B) tile

__global__ __launch_bounds__(256, 2)
void mma_gemm(const float* __restrict__ A1, const float* __restrict__ A2,
              const float* __restrict__ Bt1, const float* __restrict__ Bt2,
              const float* __restrict__ bias1, const float* __restrict__ bias2,
              float* __restrict__ C1, float* __restrict__ C2,
              int M1, int M2, int nb1, int K, int semantic)
{
    extern __shared__ float smem[];     // [2][A + B] tiles
    __shared__ float s_bias[128];
    __shared__ float s_col[128];

    const int tid  = threadIdx.x;
    const int warp = tid >> 5;
    const int lane = tid & 31;
    const int group = lane >> 2, tig = lane & 3;
    const int warpM = warp & 3, warpN = warp >> 2;
    const int mbase = warpM * 32, nbase = warpN * 64;

    const float* A; const float* Bt; const float* bias; float* C; int M, m0;
    if ((int)blockIdx.x < nb1) {
        A = A1; Bt = Bt1; bias = bias1; C = C1; M = M1; m0 = blockIdx.x * 128;
    } else {
        A = A2; Bt = Bt2; bias = bias2; C = C2; M = M2; m0 = (blockIdx.x - nb1) * 128;
    }

    if (tid < 128) { s_bias[tid] = bias[tid]; s_col[tid] = 0.f; }

    float acc[2][8][4];
#pragma unroll
    for (int i = 0; i < 2; i++)
#pragma unroll
        for (int j = 0; j < 8; j++)
#pragma unroll
            for (int l = 0; l < 4; l++) acc[i][j][l] = 0.f;

    const int nchunk = K >> 5;
    const uint32_t smem_b = smem_u32(smem);

    const int rowL = tid >> 3, qL = tid & 7;
    const int blk = lane >> 3, rr = lane & 7;
    const uint32_t offA = (uint32_t)(((mbase + (blk & 1) * 8 + rr) * LDT + (blk >> 1) * 4) * 4);
    const uint32_t offB = (uint32_t)(((nbase + (blk >> 1) * 8 + rr) * LDT + (blk & 1) * 4) * 4);

    // prefetch A chunk 0 into regs
    float4 pA[4];
#pragma unroll
    for (int l = 0; l < 4; l++) {
        int m = m0 + rowL + 32 * l;
        pA[l] = (m < M) ? *reinterpret_cast<const float4*>(A + (size_t)m * K + qL * 4)
                        : make_float4(0.f, 0.f, 0.f, 0.f);
    }
    // cp.async B chunk 0 into buf 0
#pragma unroll
    for (int l = 0; l < 4; l++) {
        int row = rowL + 32 * l;
        cp16(smem_b + (uint32_t)((BUF_F + row * LDT + qL * 4) << 2),
             Bt + (size_t)row * K + qL * 4);
    }
    asm volatile("cp.async.commit_group;");

    for (int c = 0; c < nchunk; c++) {
        const uint32_t bufo = (uint32_t)((c & 1) * 2 * BUF_F) << 2;
        // store A(c): cvt to tf32 bits, STS.128
#pragma unroll
        for (int l = 0; l < 4; l++) {
            int row = rowL + 32 * l;
            float4 v = pA[l];
            float4 u = make_float4(__uint_as_float(f2tf(v.x)), __uint_as_float(f2tf(v.y)),
                                   __uint_as_float(f2tf(v.z)), __uint_as_float(f2tf(v.w)));
            *reinterpret_cast<float4*>(smem + (c & 1) * 2 * BUF_F + row * LDT + qL * 4) = u;
        }
        // issue B(c+1), ensure B(c) done
        if (c + 1 < nchunk) {
            const int kb = (c + 1) * 32;
            const uint32_t bufo2 = (uint32_t)(((c + 1) & 1) * 2 * BUF_F) << 2;
#pragma unroll
            for (int l = 0; l < 4; l++) {
                int row = rowL + 32 * l;
                cp16(smem_b + bufo2 + (uint32_t)((BUF_F + row * LDT + qL * 4) << 2),
                     Bt + (size_t)row * K + kb + qL * 4);
            }
            asm volatile("cp.async.commit_group;");
            asm volatile("cp.async.wait_group 1;");
        } else {
            asm volatile("cp.async.wait_group 0;");
        }
        __syncthreads();
        // prefetch A(c+1) into regs (latency hidden by compute)
        if (c + 1 < nchunk) {
            const int kb = (c + 1) * 32;
#pragma unroll
            for (int l = 0; l < 4; l++) {
                int m = m0 + rowL + 32 * l;
                pA[l] = (m < M) ? *reinterpret_cast<const float4*>(A + (size_t)m * K + kb + qL * 4)
                                : make_float4(0.f, 0.f, 0.f, 0.f);
            }
        }
        // compute from buf (c&1) via ldmatrix
        const uint32_t Asb = smem_b + bufo;
        const uint32_t Bsb = Asb + (uint32_t)(BUF_F << 2);
#pragma unroll
        for (int ks = 0; ks < 4; ks++) {
            uint32_t af[2][4], bf[8][2];
            ldsm4(af[0], Asb + offA + (uint32_t)((ks * 8) << 2));
            ldsm4(af[1], Asb + offA + (uint32_t)((16 * LDT + ks * 8) << 2));
#pragma unroll
            for (int na2 = 0; na2 < 8; na2 += 2) {
                uint32_t t[4];
                ldsm4(t, Bsb + offB + (uint32_t)((na2 * 8 * LDT + ks * 8) << 2));
                bf[na2][0] = t[0]; bf[na2][1] = t[1];
                bf[na2 + 1][0] = t[2]; bf[na2 + 1][1] = t[3];
            }
#pragma unroll
            for (int ma = 0; ma < 2; ma++)
#pragma unroll
                for (int na = 0; na < 8; na++)
                    mma_tf32(acc[ma][na], af[ma], bf[na]);
        }
        __syncthreads();
    }

    // -------- epilogue --------
    if (!semantic) {
#pragma unroll
        for (int ma = 0; ma < 2; ma++) {
            int row = m0 + mbase + ma * 16 + group;
#pragma unroll
            for (int na = 0; na < 8; na++) {
                int col = nbase + na * 8 + tig * 2;
                if (row < M) {
                    float2 v = { acc[ma][na][0] + s_bias[col],
                                 acc[ma][na][1] + s_bias[col + 1] };
                    *reinterpret_cast<float2*>(C + (size_t)row * 128 + col) = v;
                }
                if (row + 8 < M) {
                    float2 v = { acc[ma][na][2] + s_bias[col],
                                 acc[ma][na][3] + s_bias[col + 1] };
                    *reinterpret_cast<float2*>(C + (size_t)(row + 8) * 128 + col) = v;
                }
            }
        }
    } else {
#pragma unroll
        for (int na = 0; na < 8; na++) {
            int col = nbase + na * 8 + tig * 2;
            float p0 = 0.f, p1 = 0.f;
#pragma unroll
            for (int ma = 0; ma < 2; ma++) {
                int row = m0 + mbase + ma * 16 + group;
                if (row < M) {
                    p0 += tanhf(acc[ma][na][0] + s_bias[col]);
                    p1 += tanhf(acc[ma][na][1] + s_bias[col + 1]);
                }
                if (row + 8 < M) {
                    p0 += tanhf(acc[ma][na][2] + s_bias[col]);
                    p1 += tanhf(acc[ma][na][3] + s_bias[col + 1]);
                }
            }
            atomicAdd(&s_col[col], p0);
            atomicAdd(&s_col[col + 1], p1);
        }
        __syncthreads();
        if (tid < 128) atomicAdd(&C[tid], s_col[tid]);
    }
}

// ---------------- attention dots, both node types in one launch ----------------
// part 1 (news): 3 dots per (node,head); part 2 (inter): 1 dot.
__global__ void att_all(const float* __restrict__ hN, const float* __restrict__ hI,
                        const float* __restrict__ v0, const float* __restrict__ v1,
                        const float* __restrict__ v2, const float* __restrict__ v3,
                        float* __restrict__ o0, float* __restrict__ o1,
                        float* __restrict__ o2, float* __restrict__ o3, int nbA)
{
    __shared__ float sv[4][128];
    if (threadIdx.x < 128) {
        sv[0][threadIdx.x] = v0[threadIdx.x];
        sv[1][threadIdx.x] = v1[threadIdx.x];
        sv[2][threadIdx.x] = v2[threadIdx.x];
        sv[3][threadIdx.x] = v3[threadIdx.x];
    }
    __syncthreads();
    if ((int)blockIdx.x < nbA) {
        int i = blockIdx.x * blockDim.x + threadIdx.x;
        if (i < N_NEWS * NH) {
            int n = i >> 3, hh = i & 7;
            const float* hp = hN + (size_t)n * HID + hh * HD;
            float s0 = 0.f, s1 = 0.f, s2 = 0.f;
#pragma unroll
            for (int d = 0; d < HD; d++) {
                float x = hp[d];
                s0 += x * sv[0][hh * HD + d];
                s1 += x * sv[1][hh * HD + d];
                s2 += x * sv[2][hh * HD + d];
            }
            o0[i] = s0; o1[i] = s1; o2[i] = s2;
        }
    } else {
        int i = (blockIdx.x - nbA) * blockDim.x + threadIdx.x;
        if (i < N_INTER * NH) {
            int n = i >> 3, hh = i & 7;
            const float* hp = hI + (size_t)n * HID + hh * HD;
            float s = 0.f;
#pragma unroll
            for (int d = 0; d < HD; d++) s += hp[d] * sv[3][hh * HD + d];
            o3[i] = s;
        }
    }
}

// ---------------- CSR build (merged dual-edge-type kernels) ----------------
__global__ void hist2(const int* __restrict__ e1, int E1, int* __restrict__ d1,
                      const int* __restrict__ e2, int E2, int* __restrict__ d2, int nb1)
{
    if ((int)blockIdx.x < nb1) {
        int e = blockIdx.x * blockDim.x + threadIdx.x;
        if (e < E1) atomicAdd(&d1[e1[E1 + e]], 1);
    } else {
        int e = (blockIdx.x - nb1) * blockDim.x + threadIdx.x;
        if (e < E2) atomicAdd(&d2[e2[E2 + e]], 1);
    }
}

// 2 blocks; block b scans its own deg array (n<=30720, 1024 threads)
__global__ void scan2(const int* __restrict__ degA, int* __restrict__ rpA, int* __restrict__ curA,
                      const int* __restrict__ degB, int* __restrict__ rpB, int* __restrict__ curB,
                      int n)
{
    const int* deg = blockIdx.x ? degB : degA;
    int* rowptr    = blockIdx.x ? rpB  : rpA;
    int* cursor    = blockIdx.x ? curB : curA;
    __shared__ int part[1024];
    const int t = threadIdx.x;
    const int chunk = (n + 1023) >> 10;
    const int b = t * chunk;
    int sum = 0;
    for (int i = 0; i < chunk; i++) { int idx = b + i; if (idx < n) sum += deg[idx]; }
    part[t] = sum;
    __syncthreads();
    for (int off = 1; off < 1024; off <<= 1) {
        int v = (t >= off) ? part[t - off] : 0;
        __syncthreads();
        part[t] += v;
        __syncthreads();
    }
    int run = (t == 0) ? 0 : part[t - 1];
    for (int i = 0; i < chunk; i++) {
        int idx = b + i;
        if (idx < n) {
            rowptr[idx] = run;
            cursor[idx] = run;
            run += deg[idx];
        }
    }
    if (t == 1023) rowptr[n] = part[1023];
}

__global__ void scatter2(const int* __restrict__ e1, int E1, int* __restrict__ c1, int* __restrict__ s1,
                         const int* __restrict__ e2, int E2, int* __restrict__ c2, int* __restrict__ s2,
                         int nb1)
{
    if ((int)blockIdx.x < nb1) {
        int e = blockIdx.x * blockDim.x + threadIdx.x;
        if (e < E1) { int pos = atomicAdd(&c1[e1[E1 + e]], 1); s1[pos] = e1[e]; }
    } else {
        int e = (blockIdx.x - nb1) * blockDim.x + threadIdx.x;
        if (e < E2) { int pos = atomicAdd(&c2[e2[E2 + e]], 1); s2[pos] = e2[e]; }
    }
}

// ---------------- fused single-pass softmax-aggregation: warp per dst node ----------------
// out[d,:] = relu( (sum_e exp(e)*h_src[e,:]) / (sum_e exp(e) + eps) )
// Identical to max-subtracted softmax (values bounded, no overflow). Both edge
// types handled in one launch.
__global__ __launch_bounds__(256)
void han_agg2(const int* __restrict__ rp1, const int* __restrict__ csr1,
              const float* __restrict__ as1, const float* __restrict__ ad1,
              const float* __restrict__ h1, float* __restrict__ o1,
              const int* __restrict__ rp2, const int* __restrict__ csr2,
              const float* __restrict__ as2, const float* __restrict__ ad2,
              const float* __restrict__ h2, float* __restrict__ o2)
{
    int gtid = blockIdx.x * blockDim.x + threadIdx.x;
    int w = gtid >> 5;
    int lane = threadIdx.x & 31;

    const int* rowptr; const int* csr; const float* asrc; const float* adst;
    const float* hsrc; float* out; int d;
    if (w < N_NEWS) {
        d = w; rowptr = rp1; csr = csr1; asrc = as1; adst = ad1; hsrc = h1; out = o1;
    } else if (w < 2 * N_NEWS) {
        d = w - N_NEWS; rowptr = rp2; csr = csr2; asrc = as2; adst = ad2; hsrc = h2; out = o2;
    } else return;

    const int beg = rowptr[d], end = rowptr[d + 1];
    const int deg = end - beg;
    float4* o = reinterpret_cast<float4*>(out) + (size_t)d * 32 + lane;
    if (deg == 0) { *o = make_float4(0.f, 0.f, 0.f, 0.f); return; }

    const int hh = lane >> 2;
    const float adh = adst[(size_t)d * 8 + hh];

    float den = 0.f, a0 = 0.f, a1 = 0.f, a2 = 0.f, a3 = 0.f;
    int s = csr[beg];
    for (int i = 0; i < deg; i++) {
        int s_next = (i + 1 < deg) ? csr[beg + i + 1] : 0;   // prefetch: breaks load chain
        float av = asrc[(size_t)s * 8 + hh];
        float4 hv = reinterpret_cast<const float4*>(hsrc)[(size_t)s * 32 + lane];
        float wgt = __expf(lrelu02(av + adh));
        den += wgt;
        a0 += hv.x * wgt; a1 += hv.y * wgt;
        a2 += hv.z * wgt; a3 += hv.w * wgt;
        s = s_next;
    }
    float invd = 1.f / (den + 1e-16f);
    *o = make_float4(fmaxf(a0 * invd, 0.f), fmaxf(a1 * invd, 0.f),
                     fmaxf(a2 * invd, 0.f), fmaxf(a3 * invd, 0.f));
}

// ---------------- semantic softmax beta ----------------
__global__ void beta_kernel(const float* __restrict__ acc, const float* __restrict__ q,
                            float* __restrict__ beta)
{
    __shared__ float red[2][4];
    int t = threadIdx.x;  // 128 threads
    float s0 = q[t] * acc[t]       * (1.f / N_NEWS);
    float s1 = q[t] * acc[128 + t] * (1.f / N_NEWS);
#pragma unroll
    for (int off = 16; off; off >>= 1) {
        s0 += __shfl_down_sync(0xffffffffu, s0, off);
        s1 += __shfl_down_sync(0xffffffffu, s1, off);
    }
    if ((t & 31) == 0) { red[0][t >> 5] = s0; red[1][t >> 5] = s1; }
    __syncthreads();
    if (t == 0) {
        float sc0 = red[0][0] + red[0][1] + red[0][2] + red[0][3];
        float sc1 = red[1][0] + red[1][1] + red[1][2] + red[1][3];
        float mx = fmaxf(sc0, sc1);
        float e0 = __expf(sc0 - mx), e1 = __expf(sc1 - mx);
        float inv = 1.f / (e0 + e1);
        beta[0] = e0 * inv;
        beta[1] = e1 * inv;
    }
}

// ---------------- final: fuse + ELU + [128x4] head (warp per node) ----------------
__global__ void final_kernel(const float* __restrict__ onn, const float* __restrict__ oin,
                             const float* __restrict__ beta, const float* __restrict__ Wout,
                             const float* __restrict__ bout, float* __restrict__ y)
{
    __shared__ float sw[HID * 4];
    for (int i = threadIdx.x; i < HID * 4; i += blockDim.x) sw[i] = Wout[i];
    __syncthreads();

    int gtid = blockIdx.x * blockDim.x + threadIdx.x;
    int node = gtid >> 5;
    int lane = threadIdx.x & 31;
    if (node >= N_NEWS) return;

    float b0 = beta[0], b1 = beta[1];
    float4 a = reinterpret_cast<const float4*>(onn)[(size_t)node * 32 + lane];
    float4 b = reinterpret_cast<const float4*>(oin)[(size_t)node * 32 + lane];
    float f[4] = { b0 * a.x + b1 * b.x, b0 * a.y + b1 * b.y,
                   b0 * a.z + b1 * b.z, b0 * a.w + b1 * b.w };   // inputs already relu'd
#pragma unroll
    for (int u = 0; u < 4; u++) f[u] = f[u] > 0.f ? f[u] : (__expf(f[u]) - 1.f);

    float p[4] = { 0.f, 0.f, 0.f, 0.f };
#pragma unroll
    for (int u = 0; u < 4; u++) {
        int r = lane * 4 + u;
#pragma unroll
        for (int c = 0; c < 4; c++) p[c] += f[u] * sw[r * 4 + c];
    }
#pragma unroll
    for (int off = 16; off; off >>= 1)
#pragma unroll
        for (int c = 0; c < 4; c++) p[c] += __shfl_down_sync(0xffffffffu, p[c], off);
    if (lane == 0) {
#pragma unroll
        for (int c = 0; c < 4; c++) y[(size_t)node * 4 + c] = p[c] + bout[c];
    }
}

// ---------------- host ----------------
static inline int cdiv(int a, int b) { return (a + b - 1) / b; }

extern "C" void kernel_launch(void* const* d_in, const int* in_sizes, int n_in,
                              void* d_out, int out_size)
{
    const float* x_news   = (const float*)d_in[0];
    const float* x_inter  = (const float*)d_in[1];
    const int*   edge_nn  = (const int*)  d_in[2];
    const int*   edge_in  = (const int*)  d_in[3];
    const float* W_news   = (const float*)d_in[4];
    const float* b_news   = (const float*)d_in[5];
    const float* W_inter  = (const float*)d_in[6];
    const float* b_inter  = (const float*)d_in[7];
    const float* a_src_nn = (const float*)d_in[8];
    const float* a_dst_nn = (const float*)d_in[9];
    const float* a_src_in = (const float*)d_in[10];
    const float* a_dst_in = (const float*)d_in[11];
    const float* Wk       = (const float*)d_in[12];
    const float* bk       = (const float*)d_in[13];
    const float* q        = (const float*)d_in[14];
    const float* W_out    = (const float*)d_in[15];
    const float* b_out    = (const float*)d_in[16];
    float* y = (float*)d_out;

    const int E_nn = in_sizes[2] / 2;
    const int E_in = in_sizes[3] / 2;

    float *h_news, *h_inter, *out_nn, *out_in, *BtN, *BtI, *BtK;
    float *asrc_nn, *adst_nn, *asrc_in, *adst_in, *accsem, *beta;
    int *deg_nn, *deg_in, *rp_nn, *rp_in, *cur_nn, *cur_in, *csr_nn, *csr_in;
    cudaGetSymbolAddress((void**)&h_news,  g_h_news);
    cudaGetSymbolAddress((void**)&h_inter, g_h_inter);
    cudaGetSymbolAddress((void**)&out_nn,  g_out_nn);
    cudaGetSymbolAddress((void**)&out_in,  g_out_in);
    cudaGetSymbolAddress((void**)&BtN,     g_BtN);
    cudaGetSymbolAddress((void**)&BtI,     g_BtI);
    cudaGetSymbolAddress((void**)&BtK,     g_BtK);
    cudaGetSymbolAddress((void**)&asrc_nn, g_asrc_nn);
    cudaGetSymbolAddress((void**)&adst_nn, g_adst_nn);
    cudaGetSymbolAddress((void**)&asrc_in, g_asrc_in);
    cudaGetSymbolAddress((void**)&adst_in, g_adst_in);
    cudaGetSymbolAddress((void**)&deg_nn,  g_deg_nn);
    cudaGetSymbolAddress((void**)&deg_in,  g_deg_in);
    cudaGetSymbolAddress((void**)&rp_nn,   g_rp_nn);
    cudaGetSymbolAddress((void**)&rp_in,   g_rp_in);
    cudaGetSymbolAddress((void**)&cur_nn,  g_cur_nn);
    cudaGetSymbolAddress((void**)&cur_in,  g_cur_in);
    cudaGetSymbolAddress((void**)&csr_nn,  g_csr_nn);
    cudaGetSymbolAddress((void**)&csr_in,  g_csr_in);
    cudaGetSymbolAddress((void**)&accsem,  g_accsem);
    cudaGetSymbolAddress((void**)&beta,    g_beta);

    const int T = 256;
    const int SMEM_GEMM = 2 * 2 * BUF_F * 4;   // 73728 bytes
    cudaFuncSetAttribute(mma_gemm, cudaFuncAttributeMaxDynamicSharedMemorySize, SMEM_GEMM);

    // ---- CSR build + weight prep ----
    zero_deg2<<<cdiv(N_NEWS, T), T>>>(deg_nn, deg_in, N_NEWS);
    transpose_all<<<cdiv(768 * 128, T), T>>>(W_news, W_inter, Wk, BtN, BtI, BtK, accsem);
    {
        int nb1 = cdiv(E_nn, T), nb2 = cdiv(E_in, T);
        hist2<<<nb1 + nb2, T>>>(edge_nn, E_nn, deg_nn, edge_in, E_in, deg_in, nb1);
        scan2<<<2, 1024>>>(deg_nn, rp_nn, cur_nn, deg_in, rp_in, cur_in, N_NEWS);
        scatter2<<<nb1 + nb2, T>>>(edge_nn, E_nn, cur_nn, csr_nn, edge_in, E_in, cur_in, csr_in, nb1);
    }

    // ---- projections (merged dual-part tf32 mma) ----
    const int nb1 = cdiv(N_NEWS, 128), nb2 = cdiv(N_INTER, 128);
    mma_gemm<<<nb1 + nb2, 256, SMEM_GEMM>>>(x_news, x_inter, BtN, BtI, b_news, b_inter,
                                            h_news, h_inter, N_NEWS, N_INTER, nb1, 768, 0);

    // ---- node-level attention coefficients (one launch) ----
    {
        int nbA = cdiv(N_NEWS * NH, T), nbB = cdiv(N_INTER * NH, T);
        att_all<<<nbA + nbB, T>>>(h_news, h_inter, a_src_nn, a_dst_nn, a_dst_in, a_src_in,
                                  asrc_nn, adst_nn, adst_in, asrc_in, nbA);
    }

    // ---- fused single-pass softmax + aggregation (both edge types, no atomics) ----
    han_agg2<<<cdiv(2 * N_NEWS * 32, T), T>>>(rp_nn, csr_nn, asrc_nn, adst_nn, h_news, out_nn,
                                              rp_in, csr_in, asrc_in, adst_in, h_inter, out_in);

    // ---- semantic attention (merged dual-part) ----
    mma_gemm<<<2 * nb1, 256, SMEM_GEMM>>>(out_nn, out_in, BtK, BtK, bk, bk,
                                          accsem, accsem + 128, N_NEWS, N_NEWS, nb1, 128, 1);
    beta_kernel<<<1, 128>>>(accsem, q, beta);

    // ---- fuse + ELU + output head ----
    final_kernel<<<cdiv(N_NEWS * 32, T), T>>>(out_nn, out_in, beta, W_out, b_out, y);
}

// round 7
// speedup vs baseline: 3.7438x; 1.0283x over previous
#include <cuda_runtime.h>
#include <math.h>
#include <stdint.h>

#define N_NEWS  30000
#define N_INTER 60000
#define HID 128
#define NH  8
#define HD  16
#define E_NN_CAP 480000
#define E_IN_CAP 960000

// ---------------- scratch (static device globals; no allocation) ----------------
__device__ float g_h_news [N_NEWS  * HID];
__device__ float g_h_inter[N_INTER * HID];
__device__ float g_out_nn [N_NEWS  * HID];
__device__ float g_out_in [N_NEWS  * HID];
__device__ float g_BtN    [HID * 768];       // W_news^T, tf32-rounded bits
__device__ float g_BtI    [HID * 768];       // W_inter^T, tf32-rounded bits
__device__ float g_BtK    [HID * HID];       // Wk^T, tf32-rounded bits
__device__ float g_asrc_nn[N_NEWS  * NH];
__device__ float g_adst_nn[N_NEWS  * NH];
__device__ float g_asrc_in[N_INTER * NH];
__device__ float g_adst_in[N_NEWS  * NH];
__device__ int   g_deg_nn [N_NEWS];
__device__ int   g_deg_in [N_NEWS];
__device__ int   g_rp_nn  [N_NEWS + 1];
__device__ int   g_rp_in  [N_NEWS + 1];
__device__ int   g_cur_nn [N_NEWS];
__device__ int   g_cur_in [N_NEWS];
__device__ int   g_csr_nn [E_NN_CAP];
__device__ int   g_csr_in [E_IN_CAP];
__device__ float g_accsem[2 * HID];
__device__ float g_beta  [2];

// ---------------- helpers ----------------
static __device__ __forceinline__ uint32_t smem_u32(const void* p) {
    uint32_t r;
    asm("{ .reg .u64 t; cvta.to.shared.u64 t, %1; cvt.u32.u64 %0, t; }" : "=r"(r) : "l"(p));
    return r;
}
static __device__ __forceinline__ uint32_t f2tf(float x) {
    uint32_t r;
    asm("cvt.rna.tf32.f32 %0, %1;" : "=r"(r) : "f"(x));
    return r;
}
static __device__ __forceinline__ void mma_tf32(float* c, const uint32_t* a, const uint32_t* b) {
    asm volatile(
        "mma.sync.aligned.m16n8k8.row.col.f32.tf32.tf32.f32 "
        "{%0,%1,%2,%3},{%4,%5,%6,%7},{%8,%9},{%0,%1,%2,%3};"
        : "+f"(c[0]), "+f"(c[1]), "+f"(c[2]), "+f"(c[3])
        : "r"(a[0]), "r"(a[1]), "r"(a[2]), "r"(a[3]), "r"(b[0]), "r"(b[1]));
}
static __device__ __forceinline__ void cp16(uint32_t dst, const void* src) {
    asm volatile("cp.async.cg.shared.global [%0], [%1], 16;" :: "r"(dst), "l"(src));
}
static __device__ __forceinline__ void ldsm4(uint32_t* r, uint32_t addr) {
    asm volatile("ldmatrix.sync.aligned.m8n8.x4.shared.b16 {%0,%1,%2,%3}, [%4];"
                 : "=r"(r[0]), "=r"(r[1]), "=r"(r[2]), "=r"(r[3]) : "r"(addr));
}
__device__ __forceinline__ float lrelu02(float x) { return x > 0.f ? x : 0.2f * x; }

// ---------------- setup: zero degree counters ----------------
__global__ void zero_deg2(int* __restrict__ d1, int* __restrict__ d2, int n) {
    int i = blockIdx.x * blockDim.x + threadIdx.x;
    if (i < n) { d1[i] = 0; d2[i] = 0; }
}

// ---------------- transpose + tf32-round all weights + zero accsem ----------------
__global__ void transpose_all(const float* __restrict__ Wn, const float* __restrict__ Wi,
                              const float* __restrict__ Wk,
                              float* __restrict__ BtN, float* __restrict__ BtI,
                              float* __restrict__ BtK, float* __restrict__ accsem)
{
    int i = blockIdx.x * blockDim.x + threadIdx.x;   // over 768*128 (write-coalesced)
    if (i < 768 * 128) {
        int n = i / 768, k = i % 768;
        BtN[i] = __uint_as_float(f2tf(Wn[k * 128 + n]));
        BtI[i] = __uint_as_float(f2tf(Wi[k * 128 + n]));
    }
    if (i < 128 * 128) {
        int n = i >> 7, k = i & 127;
        BtK[i] = __uint_as_float(f2tf(Wk[k * 128 + n]));
    }
    if (i < 2 * HID) accsem[i] = 0.f;
}

// ---------------- tf32 tensor-core GEMM (dual-part merged launch) ----------------
#define LDT 36              // padded row length (floats)
#define BUF_F (128 * LDT)   // floats per (A or B) tile

__global__ __launch_bounds__(256, 2)
void mma_gemm(const float* __restrict__ A1, const float* __restrict__ A2,
              const float* __restrict__ Bt1, const float* __restrict__ Bt2,
              const float* __restrict__ bias1, const float* __restrict__ bias2,
              float* __restrict__ C1, float* __restrict__ C2,
              int M1, int M2, int nb1, int K, int semantic)
{
    extern __shared__ float smem[];     // [2][A + B] tiles
    __shared__ float s_bias[128];
    __shared__ float s_col[128];

    const int tid  = threadIdx.x;
    const int warp = tid >> 5;
    const int lane = tid & 31;
    const int group = lane >> 2, tig = lane & 3;
    const int warpM = warp & 3, warpN = warp >> 2;
    const int mbase = warpM * 32, nbase = warpN * 64;

    const float* A; const float* Bt; const float* bias; float* C; int M, m0;
    if ((int)blockIdx.x < nb1) {
        A = A1; Bt = Bt1; bias = bias1; C = C1; M = M1; m0 = blockIdx.x * 128;
    } else {
        A = A2; Bt = Bt2; bias = bias2; C = C2; M = M2; m0 = (blockIdx.x - nb1) * 128;
    }

    if (tid < 128) { s_bias[tid] = bias[tid]; s_col[tid] = 0.f; }

    float acc[2][8][4];
#pragma unroll
    for (int i = 0; i < 2; i++)
#pragma unroll
        for (int j = 0; j < 8; j++)
#pragma unroll
            for (int l = 0; l < 4; l++) acc[i][j][l] = 0.f;

    const int nchunk = K >> 5;
    const uint32_t smem_b = smem_u32(smem);

    const int rowL = tid >> 3, qL = tid & 7;
    const int blk = lane >> 3, rr = lane & 7;
    const uint32_t offA = (uint32_t)(((mbase + (blk & 1) * 8 + rr) * LDT + (blk >> 1) * 4) * 4);
    const uint32_t offB = (uint32_t)(((nbase + (blk >> 1) * 8 + rr) * LDT + (blk & 1) * 4) * 4);

    // prefetch A chunk 0 into regs
    float4 pA[4];
#pragma unroll
    for (int l = 0; l < 4; l++) {
        int m = m0 + rowL + 32 * l;
        pA[l] = (m < M) ? *reinterpret_cast<const float4*>(A + (size_t)m * K + qL * 4)
                        : make_float4(0.f, 0.f, 0.f, 0.f);
    }
    // cp.async B chunk 0 into buf 0
#pragma unroll
    for (int l = 0; l < 4; l++) {
        int row = rowL + 32 * l;
        cp16(smem_b + (uint32_t)((BUF_F + row * LDT + qL * 4) << 2),
             Bt + (size_t)row * K + qL * 4);
    }
    asm volatile("cp.async.commit_group;");

    for (int c = 0; c < nchunk; c++) {
        const uint32_t bufo = (uint32_t)((c & 1) * 2 * BUF_F) << 2;
        // store A(c): cvt to tf32 bits, STS.128
#pragma unroll
        for (int l = 0; l < 4; l++) {
            int row = rowL + 32 * l;
            float4 v = pA[l];
            float4 u = make_float4(__uint_as_float(f2tf(v.x)), __uint_as_float(f2tf(v.y)),
                                   __uint_as_float(f2tf(v.z)), __uint_as_float(f2tf(v.w)));
            *reinterpret_cast<float4*>(smem + (c & 1) * 2 * BUF_F + row * LDT + qL * 4) = u;
        }
        // issue B(c+1), ensure B(c) done
        if (c + 1 < nchunk) {
            const int kb = (c + 1) * 32;
            const uint32_t bufo2 = (uint32_t)(((c + 1) & 1) * 2 * BUF_F) << 2;
#pragma unroll
            for (int l = 0; l < 4; l++) {
                int row = rowL + 32 * l;
                cp16(smem_b + bufo2 + (uint32_t)((BUF_F + row * LDT + qL * 4) << 2),
                     Bt + (size_t)row * K + kb + qL * 4);
            }
            asm volatile("cp.async.commit_group;");
            asm volatile("cp.async.wait_group 1;");
        } else {
            asm volatile("cp.async.wait_group 0;");
        }
        __syncthreads();
        // prefetch A(c+1) into regs (latency hidden by compute)
        if (c + 1 < nchunk) {
            const int kb = (c + 1) * 32;
#pragma unroll
            for (int l = 0; l < 4; l++) {
                int m = m0 + rowL + 32 * l;
                pA[l] = (m < M) ? *reinterpret_cast<const float4*>(A + (size_t)m * K + kb + qL * 4)
                                : make_float4(0.f, 0.f, 0.f, 0.f);
            }
        }
        // compute from buf (c&1) via ldmatrix
        const uint32_t Asb = smem_b + bufo;
        const uint32_t Bsb = Asb + (uint32_t)(BUF_F << 2);
#pragma unroll
        for (int ks = 0; ks < 4; ks++) {
            uint32_t af[2][4], bf[8][2];
            ldsm4(af[0], Asb + offA + (uint32_t)((ks * 8) << 2));
            ldsm4(af[1], Asb + offA + (uint32_t)((16 * LDT + ks * 8) << 2));
#pragma unroll
            for (int na2 = 0; na2 < 8; na2 += 2) {
                uint32_t t[4];
                ldsm4(t, Bsb + offB + (uint32_t)((na2 * 8 * LDT + ks * 8) << 2));
                bf[na2][0] = t[0]; bf[na2][1] = t[1];
                bf[na2 + 1][0] = t[2]; bf[na2 + 1][1] = t[3];
            }
#pragma unroll
            for (int ma = 0; ma < 2; ma++)
#pragma unroll
                for (int na = 0; na < 8; na++)
                    mma_tf32(acc[ma][na], af[ma], bf[na]);
        }
        __syncthreads();
    }

    // -------- epilogue --------
    if (!semantic) {
#pragma unroll
        for (int ma = 0; ma < 2; ma++) {
            int row = m0 + mbase + ma * 16 + group;
#pragma unroll
            for (int na = 0; na < 8; na++) {
                int col = nbase + na * 8 + tig * 2;
                if (row < M) {
                    float2 v = { acc[ma][na][0] + s_bias[col],
                                 acc[ma][na][1] + s_bias[col + 1] };
                    *reinterpret_cast<float2*>(C + (size_t)row * 128 + col) = v;
                }
                if (row + 8 < M) {
                    float2 v = { acc[ma][na][2] + s_bias[col],
                                 acc[ma][na][3] + s_bias[col + 1] };
                    *reinterpret_cast<float2*>(C + (size_t)(row + 8) * 128 + col) = v;
                }
            }
        }
    } else {
#pragma unroll
        for (int na = 0; na < 8; na++) {
            int col = nbase + na * 8 + tig * 2;
            float p0 = 0.f, p1 = 0.f;
#pragma unroll
            for (int ma = 0; ma < 2; ma++) {
                int row = m0 + mbase + ma * 16 + group;
                if (row < M) {
                    p0 += tanhf(acc[ma][na][0] + s_bias[col]);
                    p1 += tanhf(acc[ma][na][1] + s_bias[col + 1]);
                }
                if (row + 8 < M) {
                    p0 += tanhf(acc[ma][na][2] + s_bias[col]);
                    p1 += tanhf(acc[ma][na][3] + s_bias[col + 1]);
                }
            }
            atomicAdd(&s_col[col], p0);
            atomicAdd(&s_col[col + 1], p1);
        }
        __syncthreads();
        if (tid < 128) atomicAdd(&C[tid], s_col[tid]);
    }
}

// ---------------- attention dots, both node types in one launch ----------------
__global__ void att_all(const float* __restrict__ hN, const float* __restrict__ hI,
                        const float* __restrict__ v0, const float* __restrict__ v1,
                        const float* __restrict__ v2, const float* __restrict__ v3,
                        float* __restrict__ o0, float* __restrict__ o1,
                        float* __restrict__ o2, float* __restrict__ o3, int nbA)
{
    __shared__ float sv[4][128];
    if (threadIdx.x < 128) {
        sv[0][threadIdx.x] = v0[threadIdx.x];
        sv[1][threadIdx.x] = v1[threadIdx.x];
        sv[2][threadIdx.x] = v2[threadIdx.x];
        sv[3][threadIdx.x] = v3[threadIdx.x];
    }
    __syncthreads();
    if ((int)blockIdx.x < nbA) {
        int i = blockIdx.x * blockDim.x + threadIdx.x;
        if (i < N_NEWS * NH) {
            int n = i >> 3, hh = i & 7;
            const float* hp = hN + (size_t)n * HID + hh * HD;
            float s0 = 0.f, s1 = 0.f, s2 = 0.f;
#pragma unroll
            for (int d = 0; d < HD; d++) {
                float x = hp[d];
                s0 += x * sv[0][hh * HD + d];
                s1 += x * sv[1][hh * HD + d];
                s2 += x * sv[2][hh * HD + d];
            }
            o0[i] = s0; o1[i] = s1; o2[i] = s2;
        }
    } else {
        int i = (blockIdx.x - nbA) * blockDim.x + threadIdx.x;
        if (i < N_INTER * NH) {
            int n = i >> 3, hh = i & 7;
            const float* hp = hI + (size_t)n * HID + hh * HD;
            float s = 0.f;
#pragma unroll
            for (int d = 0; d < HD; d++) s += hp[d] * sv[3][hh * HD + d];
            o3[i] = s;
        }
    }
}

// ---------------- CSR build (merged dual-edge-type kernels) ----------------
__global__ void hist2(const int* __restrict__ e1, int E1, int* __restrict__ d1,
                      const int* __restrict__ e2, int E2, int* __restrict__ d2, int nb1)
{
    if ((int)blockIdx.x < nb1) {
        int e = blockIdx.x * blockDim.x + threadIdx.x;
        if (e < E1) atomicAdd(&d1[e1[E1 + e]], 1);
    } else {
        int e = (blockIdx.x - nb1) * blockDim.x + threadIdx.x;
        if (e < E2) atomicAdd(&d2[e2[E2 + e]], 1);
    }
}

// 2 blocks; block b scans its own deg array (n<=32768). Register-resident:
// one deg read, shfl warp scan, one smem pass, writes straight from regs.
__global__ __launch_bounds__(1024)
void scan2(const int* __restrict__ degA, int* __restrict__ rpA, int* __restrict__ curA,
           const int* __restrict__ degB, int* __restrict__ rpB, int* __restrict__ curB,
           int n)
{
    const int* deg = blockIdx.x ? degB : degA;
    int* rowptr    = blockIdx.x ? rpB  : rpA;
    int* cursor    = blockIdx.x ? curB : curA;
    __shared__ int wsum[32];

    const int t = threadIdx.x, lane = t & 31, wid = t >> 5;
    const int chunk = (n + 1023) >> 10;           // <=32
    const int b = t * chunk;

    int v[32];                                     // local exclusive prefix
    int sum = 0;
#pragma unroll
    for (int i = 0; i < 32; i++) {
        if (i < chunk) {
            int idx = b + i;
            int x = (idx < n) ? deg[idx] : 0;
            v[i] = sum;
            sum += x;
        }
    }
    // warp-inclusive scan of per-thread sums
    int inc = sum;
#pragma unroll
    for (int off = 1; off < 32; off <<= 1) {
        int y = __shfl_up_sync(0xffffffffu, inc, off);
        if (lane >= off) inc += y;
    }
    if (lane == 31) wsum[wid] = inc;
    __syncthreads();
    if (wid == 0) {
        int ws = wsum[lane];
        int winc = ws;
#pragma unroll
        for (int off = 1; off < 32; off <<= 1) {
            int y = __shfl_up_sync(0xffffffffu, winc, off);
            if (lane >= off) winc += y;
        }
        wsum[lane] = winc - ws;                    // exclusive warp base
    }
    __syncthreads();
    const int base = wsum[wid] + (inc - sum);      // global exclusive base for this thread
#pragma unroll
    for (int i = 0; i < 32; i++) {
        if (i < chunk) {
            int idx = b + i;
            if (idx < n) {
                int val = base + v[i];
                rowptr[idx] = val;
                cursor[idx] = val;
            }
        }
    }
    if (t == 1023) rowptr[n] = base + sum;         // grand total
}

__global__ void scatter2(const int* __restrict__ e1, int E1, int* __restrict__ c1, int* __restrict__ s1,
                         const int* __restrict__ e2, int E2, int* __restrict__ c2, int* __restrict__ s2,
                         int nb1)
{
    if ((int)blockIdx.x < nb1) {
        int e = blockIdx.x * blockDim.x + threadIdx.x;
        if (e < E1) { int pos = atomicAdd(&c1[e1[E1 + e]], 1); s1[pos] = e1[e]; }
    } else {
        int e = (blockIdx.x - nb1) * blockDim.x + threadIdx.x;
        if (e < E2) { int pos = atomicAdd(&c2[e2[E2 + e]], 1); s2[pos] = e2[e]; }
    }
}

// ---------------- fused single-pass softmax-aggregation: warp per dst node ----------------
// out[d,:] = relu( (sum_e exp(e)*h_src[e,:]) / (sum_e exp(e) + eps) )
// 2-way unrolled to double gather MLP.
__global__ __launch_bounds__(256)
void han_agg2(const int* __restrict__ rp1, const int* __restrict__ csr1,
              const float* __restrict__ as1, const float* __restrict__ ad1,
              const float* __restrict__ h1, float* __restrict__ o1,
              const int* __restrict__ rp2, const int* __restrict__ csr2,
              const float* __restrict__ as2, const float* __restrict__ ad2,
              const float* __restrict__ h2, float* __restrict__ o2)
{
    int gtid = blockIdx.x * blockDim.x + threadIdx.x;
    int w = gtid >> 5;
    int lane = threadIdx.x & 31;

    const int* rowptr; const int* csr; const float* asrc; const float* adst;
    const float* hsrc; float* out; int d;
    if (w < N_NEWS) {
        d = w; rowptr = rp1; csr = csr1; asrc = as1; adst = ad1; hsrc = h1; out = o1;
    } else if (w < 2 * N_NEWS) {
        d = w - N_NEWS; rowptr = rp2; csr = csr2; asrc = as2; adst = ad2; hsrc = h2; out = o2;
    } else return;

    const int beg = rowptr[d], end = rowptr[d + 1];
    const int deg = end - beg;
    float4* o = reinterpret_cast<float4*>(out) + (size_t)d * 32 + lane;
    if (deg == 0) { *o = make_float4(0.f, 0.f, 0.f, 0.f); return; }

    const int hh = lane >> 2;
    const float adh = adst[(size_t)d * 8 + hh];
    const float4* h4 = reinterpret_cast<const float4*>(hsrc);

    float den = 0.f, a0 = 0.f, a1 = 0.f, a2 = 0.f, a3 = 0.f;
    int i = 0;
    for (; i + 2 <= deg; i += 2) {
        int sA = csr[beg + i], sB = csr[beg + i + 1];
        float avA = asrc[(size_t)sA * 8 + hh];
        float avB = asrc[(size_t)sB * 8 + hh];
        float4 hA = h4[(size_t)sA * 32 + lane];
        float4 hB = h4[(size_t)sB * 32 + lane];
        float wA = __expf(lrelu02(avA + adh));
        float wB = __expf(lrelu02(avB + adh));
        den += wA + wB;
        a0 += hA.x * wA + hB.x * wB;
        a1 += hA.y * wA + hB.y * wB;
        a2 += hA.z * wA + hB.z * wB;
        a3 += hA.w * wA + hB.w * wB;
    }
    if (i < deg) {
        int s = csr[beg + i];
        float av = asrc[(size_t)s * 8 + hh];
        float4 hv = h4[(size_t)s * 32 + lane];
        float wgt = __expf(lrelu02(av + adh));
        den += wgt;
        a0 += hv.x * wgt; a1 += hv.y * wgt;
        a2 += hv.z * wgt; a3 += hv.w * wgt;
    }
    float invd = 1.f / (den + 1e-16f);
    *o = make_float4(fmaxf(a0 * invd, 0.f), fmaxf(a1 * invd, 0.f),
                     fmaxf(a2 * invd, 0.f), fmaxf(a3 * invd, 0.f));
}

// ---------------- semantic softmax beta ----------------
__global__ void beta_kernel(const float* __restrict__ acc, const float* __restrict__ q,
                            float* __restrict__ beta)
{
    __shared__ float red[2][4];
    int t = threadIdx.x;  // 128 threads
    float s0 = q[t] * acc[t]       * (1.f / N_NEWS);
    float s1 = q[t] * acc[128 + t] * (1.f / N_NEWS);
#pragma unroll
    for (int off = 16; off; off >>= 1) {
        s0 += __shfl_down_sync(0xffffffffu, s0, off);
        s1 += __shfl_down_sync(0xffffffffu, s1, off);
    }
    if ((t & 31) == 0) { red[0][t >> 5] = s0; red[1][t >> 5] = s1; }
    __syncthreads();
    if (t == 0) {
        float sc0 = red[0][0] + red[0][1] + red[0][2] + red[0][3];
        float sc1 = red[1][0] + red[1][1] + red[1][2] + red[1][3];
        float mx = fmaxf(sc0, sc1);
        float e0 = __expf(sc0 - mx), e1 = __expf(sc1 - mx);
        float inv = 1.f / (e0 + e1);
        beta[0] = e0 * inv;
        beta[1] = e1 * inv;
    }
}

// ---------------- final: fuse + ELU + [128x4] head (warp per node) ----------------
__global__ void final_kernel(const float* __restrict__ onn, const float* __restrict__ oin,
                             const float* __restrict__ beta, const float* __restrict__ Wout,
                             const float* __restrict__ bout, float* __restrict__ y)
{
    __shared__ float sw[HID * 4];
    for (int i = threadIdx.x; i < HID * 4; i += blockDim.x) sw[i] = Wout[i];
    __syncthreads();

    int gtid = blockIdx.x * blockDim.x + threadIdx.x;
    int node = gtid >> 5;
    int lane = threadIdx.x & 31;
    if (node >= N_NEWS) return;

    float b0 = beta[0], b1 = beta[1];
    float4 a = reinterpret_cast<const float4*>(onn)[(size_t)node * 32 + lane];
    float4 b = reinterpret_cast<const float4*>(oin)[(size_t)node * 32 + lane];
    float f[4] = { b0 * a.x + b1 * b.x, b0 * a.y + b1 * b.y,
                   b0 * a.z + b1 * b.z, b0 * a.w + b1 * b.w };   // inputs already relu'd
#pragma unroll
    for (int u = 0; u < 4; u++) f[u] = f[u] > 0.f ? f[u] : (__expf(f[u]) - 1.f);

    float p[4] = { 0.f, 0.f, 0.f, 0.f };
#pragma unroll
    for (int u = 0; u < 4; u++) {
        int r = lane * 4 + u;
#pragma unroll
        for (int c = 0; c < 4; c++) p[c] += f[u] * sw[r * 4 + c];
    }
#pragma unroll
    for (int off = 16; off; off >>= 1)
#pragma unroll
        for (int c = 0; c < 4; c++) p[c] += __shfl_down_sync(0xffffffffu, p[c], off);
    if (lane == 0) {
#pragma unroll
        for (int c = 0; c < 4; c++) y[(size_t)node * 4 + c] = p[c] + bout[c];
    }
}

// ---------------- host ----------------
static inline int cdiv(int a, int b) { return (a + b - 1) / b; }

extern "C" void kernel_launch(void* const* d_in, const int* in_sizes, int n_in,
                              void* d_out, int out_size)
{
    const float* x_news   = (const float*)d_in[0];
    const float* x_inter  = (const float*)d_in[1];
    const int*   edge_nn  = (const int*)  d_in[2];
    const int*   edge_in  = (const int*)  d_in[3];
    const float* W_news   = (const float*)d_in[4];
    const float* b_news   = (const float*)d_in[5];
    const float* W_inter  = (const float*)d_in[6];
    const float* b_inter  = (const float*)d_in[7];
    const float* a_src_nn = (const float*)d_in[8];
    const float* a_dst_nn = (const float*)d_in[9];
    const float* a_src_in = (const float*)d_in[10];
    const float* a_dst_in = (const float*)d_in[11];
    const float* Wk       = (const float*)d_in[12];
    const float* bk       = (const float*)d_in[13];
    const float* q        = (const float*)d_in[14];
    const float* W_out    = (const float*)d_in[15];
    const float* b_out    = (const float*)d_in[16];
    float* y = (float*)d_out;

    const int E_nn = in_sizes[2] / 2;
    const int E_in = in_sizes[3] / 2;

    float *h_news, *h_inter, *out_nn, *out_in, *BtN, *BtI, *BtK;
    float *asrc_nn, *adst_nn, *asrc_in, *adst_in, *accsem, *beta;
    int *deg_nn, *deg_in, *rp_nn, *rp_in, *cur_nn, *cur_in, *csr_nn, *csr_in;
    cudaGetSymbolAddress((void**)&h_news,  g_h_news);
    cudaGetSymbolAddress((void**)&h_inter, g_h_inter);
    cudaGetSymbolAddress((void**)&out_nn,  g_out_nn);
    cudaGetSymbolAddress((void**)&out_in,  g_out_in);
    cudaGetSymbolAddress((void**)&BtN,     g_BtN);
    cudaGetSymbolAddress((void**)&BtI,     g_BtI);
    cudaGetSymbolAddress((void**)&BtK,     g_BtK);
    cudaGetSymbolAddress((void**)&asrc_nn, g_asrc_nn);
    cudaGetSymbolAddress((void**)&adst_nn, g_adst_nn);
    cudaGetSymbolAddress((void**)&asrc_in, g_asrc_in);
    cudaGetSymbolAddress((void**)&adst_in, g_adst_in);
    cudaGetSymbolAddress((void**)&deg_nn,  g_deg_nn);
    cudaGetSymbolAddress((void**)&deg_in,  g_deg_in);
    cudaGetSymbolAddress((void**)&rp_nn,   g_rp_nn);
    cudaGetSymbolAddress((void**)&rp_in,   g_rp_in);
    cudaGetSymbolAddress((void**)&cur_nn,  g_cur_nn);
    cudaGetSymbolAddress((void**)&cur_in,  g_cur_in);
    cudaGetSymbolAddress((void**)&csr_nn,  g_csr_nn);
    cudaGetSymbolAddress((void**)&csr_in,  g_csr_in);
    cudaGetSymbolAddress((void**)&accsem,  g_accsem);
    cudaGetSymbolAddress((void**)&beta,    g_beta);

    const int T = 256;
    const int SMEM_GEMM = 2 * 2 * BUF_F * 4;   // 73728 bytes
    cudaFuncSetAttribute(mma_gemm, cudaFuncAttributeMaxDynamicSharedMemorySize, SMEM_GEMM);

    // ---- CSR build + weight prep ----
    zero_deg2<<<cdiv(N_NEWS, T), T>>>(deg_nn, deg_in, N_NEWS);
    transpose_all<<<cdiv(768 * 128, T), T>>>(W_news, W_inter, Wk, BtN, BtI, BtK, accsem);
    {
        int nb1 = cdiv(E_nn, T), nb2 = cdiv(E_in, T);
        hist2<<<nb1 + nb2, T>>>(edge_nn, E_nn, deg_nn, edge_in, E_in, deg_in, nb1);
        scan2<<<2, 1024>>>(deg_nn, rp_nn, cur_nn, deg_in, rp_in, cur_in, N_NEWS);
        scatter2<<<nb1 + nb2, T>>>(edge_nn, E_nn, cur_nn, csr_nn, edge_in, E_in, cur_in, csr_in, nb1);
    }

    // ---- projections (merged dual-part tf32 mma) ----
    const int nb1 = cdiv(N_NEWS, 128), nb2 = cdiv(N_INTER, 128);
    mma_gemm<<<nb1 + nb2, 256, SMEM_GEMM>>>(x_news, x_inter, BtN, BtI, b_news, b_inter,
                                            h_news, h_inter, N_NEWS, N_INTER, nb1, 768, 0);

    // ---- node-level attention coefficients (one launch) ----
    {
        int nbA = cdiv(N_NEWS * NH, T), nbB = cdiv(N_INTER * NH, T);
        att_all<<<nbA + nbB, T>>>(h_news, h_inter, a_src_nn, a_dst_nn, a_dst_in, a_src_in,
                                  asrc_nn, adst_nn, adst_in, asrc_in, nbA);
    }

    // ---- fused single-pass softmax + aggregation (both edge types, no atomics) ----
    han_agg2<<<cdiv(2 * N_NEWS * 32, T), T>>>(rp_nn, csr_nn, asrc_nn, adst_nn, h_news, out_nn,
                                              rp_in, csr_in, asrc_in, adst_in, h_inter, out_in);

    // ---- semantic attention (merged dual-part) ----
    mma_gemm<<<2 * nb1, 256, SMEM_GEMM>>>(out_nn, out_in, BtK, BtK, bk, bk,
                                          accsem, accsem + 128, N_NEWS, N_NEWS, nb1, 128, 1);
    beta_kernel<<<1, 128>>>(accsem, q, beta);

    // ---- fuse + ELU + output head ----
    final_kernel<<<cdiv(N_NEWS * 32, T), T>>>(out_nn, out_in, beta, W_out, b_out, y);
}

// round 8
// speedup vs baseline: 4.0885x; 1.0921x over previous
#include <cuda_runtime.h>
#include <math.h>
#include <stdint.h>

#define N_NEWS  30000
#define N_INTER 60000
#define HID 128
#define NH  8
#define HD  16
#define E_NN_CAP 480000
#define E_IN_CAP 960000

// ---------------- scratch (static device globals; no allocation) ----------------
__device__ float g_h_news [N_NEWS  * HID];
__device__ float g_h_inter[N_INTER * HID];
__device__ float g_out_nn [N_NEWS  * HID];
__device__ float g_out_in [N_NEWS  * HID];
__device__ float g_BtN    [HID * 768];       // W_news^T, tf32-rounded bits
__device__ float g_BtI    [HID * 768];       // W_inter^T, tf32-rounded bits
__device__ float g_BtK    [HID * HID];       // Wk^T, tf32-rounded bits
__device__ float g_asrc_nn[N_NEWS  * NH];
__device__ float g_adst_nn[N_NEWS  * NH];
__device__ float g_asrc_in[N_INTER * NH];
__device__ float g_adst_in[N_NEWS  * NH];
__device__ int   g_deg_nn [N_NEWS];
__device__ int   g_deg_in [N_NEWS];
__device__ int   g_rp_nn  [N_NEWS + 1];
__device__ int   g_rp_in  [N_NEWS + 1];
__device__ int   g_cur_nn [N_NEWS];
__device__ int   g_cur_in [N_NEWS];
__device__ int   g_csr_nn [E_NN_CAP];
__device__ int   g_csr_in [E_IN_CAP];
__device__ float g_accsem[2 * HID];
__device__ float g_beta  [2];

// ---------------- helpers ----------------
static __device__ __forceinline__ uint32_t smem_u32(const void* p) {
    uint32_t r;
    asm("{ .reg .u64 t; cvta.to.shared.u64 t, %1; cvt.u32.u64 %0, t; }" : "=r"(r) : "l"(p));
    return r;
}
static __device__ __forceinline__ uint32_t f2tf(float x) {
    uint32_t r;
    asm("cvt.rna.tf32.f32 %0, %1;" : "=r"(r) : "f"(x));
    return r;
}
static __device__ __forceinline__ void mma_tf32(float* c, const uint32_t* a, const uint32_t* b) {
    asm volatile(
        "mma.sync.aligned.m16n8k8.row.col.f32.tf32.tf32.f32 "
        "{%0,%1,%2,%3},{%4,%5,%6,%7},{%8,%9},{%0,%1,%2,%3};"
        : "+f"(c[0]), "+f"(c[1]), "+f"(c[2]), "+f"(c[3])
        : "r"(a[0]), "r"(a[1]), "r"(a[2]), "r"(a[3]), "r"(b[0]), "r"(b[1]));
}
static __device__ __forceinline__ void cp16(uint32_t dst, const void* src) {
    asm volatile("cp.async.cg.shared.global [%0], [%1], 16;" :: "r"(dst), "l"(src));
}
static __device__ __forceinline__ void ldsm4(uint32_t* r, uint32_t addr) {
    asm volatile("ldmatrix.sync.aligned.m8n8.x4.shared.b16 {%0,%1,%2,%3}, [%4];"
                 : "=r"(r[0]), "=r"(r[1]), "=r"(r[2]), "=r"(r[3]) : "r"(addr));
}
__device__ __forceinline__ float lrelu02(float x) { return x > 0.f ? x : 0.2f * x; }

// ---------------- setup: zero degree counters ----------------
__global__ void zero_deg2(int* __restrict__ d1, int* __restrict__ d2, int n) {
    int i = blockIdx.x * blockDim.x + threadIdx.x;
    if (i < n) { d1[i] = 0; d2[i] = 0; }
}

// ---------------- transpose + tf32-round all weights + zero accsem ----------------
__global__ void transpose_all(const float* __restrict__ Wn, const float* __restrict__ Wi,
                              const float* __restrict__ Wk,
                              float* __restrict__ BtN, float* __restrict__ BtI,
                              float* __restrict__ BtK, float* __restrict__ accsem)
{
    int i = blockIdx.x * blockDim.x + threadIdx.x;   // over 768*128 (write-coalesced)
    if (i < 768 * 128) {
        int n = i / 768, k = i % 768;
        BtN[i] = __uint_as_float(f2tf(Wn[k * 128 + n]));
        BtI[i] = __uint_as_float(f2tf(Wi[k * 128 + n]));
    }
    if (i < 128 * 128) {
        int n = i >> 7, k = i & 127;
        BtK[i] = __uint_as_float(f2tf(Wk[k * 128 + n]));
    }
    if (i < 2 * HID) accsem[i] = 0.f;
}

// ---------------- tf32 tensor-core GEMM (dual-part merged launch) ----------------
#define LDT 36              // padded row length (floats)
#define BUF_F (128 * LDT)   // floats per (A or B) tile

__global__ __launch_bounds__(256, 2)
void mma_gemm(const float* __restrict__ A1, const float* __restrict__ A2,
              const float* __restrict__ Bt1, const float* __restrict__ Bt2,
              const float* __restrict__ bias1, const float* __restrict__ bias2,
              float* __restrict__ C1, float* __restrict__ C2,
              int M1, int M2, int nb1, int K, int semantic)
{
    extern __shared__ float smem[];     // [2][A + B] tiles
    __shared__ float s_bias[128];
    __shared__ float s_col[128];

    const int tid  = threadIdx.x;
    const int warp = tid >> 5;
    const int lane = tid & 31;
    const int group = lane >> 2, tig = lane & 3;
    const int warpM = warp & 3, warpN = warp >> 2;
    const int mbase = warpM * 32, nbase = warpN * 64;

    const float* A; const float* Bt; const float* bias; float* C; int M, m0;
    if ((int)blockIdx.x < nb1) {
        A = A1; Bt = Bt1; bias = bias1; C = C1; M = M1; m0 = blockIdx.x * 128;
    } else {
        A = A2; Bt = Bt2; bias = bias2; C = C2; M = M2; m0 = (blockIdx.x - nb1) * 128;
    }

    if (tid < 128) { s_bias[tid] = bias[tid]; s_col[tid] = 0.f; }

    float acc[2][8][4];
#pragma unroll
    for (int i = 0; i < 2; i++)
#pragma unroll
        for (int j = 0; j < 8; j++)
#pragma unroll
            for (int l = 0; l < 4; l++) acc[i][j][l] = 0.f;

    const int nchunk = K >> 5;
    const uint32_t smem_b = smem_u32(smem);

    const int rowL = tid >> 3, qL = tid & 7;
    const int blk = lane >> 3, rr = lane & 7;
    const uint32_t offA = (uint32_t)(((mbase + (blk & 1) * 8 + rr) * LDT + (blk >> 1) * 4) * 4);
    const uint32_t offB = (uint32_t)(((nbase + (blk >> 1) * 8 + rr) * LDT + (blk & 1) * 4) * 4);

    // prefetch A chunk 0 into regs
    float4 pA[4];
#pragma unroll
    for (int l = 0; l < 4; l++) {
        int m = m0 + rowL + 32 * l;
        pA[l] = (m < M) ? *reinterpret_cast<const float4*>(A + (size_t)m * K + qL * 4)
                        : make_float4(0.f, 0.f, 0.f, 0.f);
    }
    // cp.async B chunk 0 into buf 0
#pragma unroll
    for (int l = 0; l < 4; l++) {
        int row = rowL + 32 * l;
        cp16(smem_b + (uint32_t)((BUF_F + row * LDT + qL * 4) << 2),
             Bt + (size_t)row * K + qL * 4);
    }
    asm volatile("cp.async.commit_group;");

    for (int c = 0; c < nchunk; c++) {
        const uint32_t bufo = (uint32_t)((c & 1) * 2 * BUF_F) << 2;
        // store A(c): cvt to tf32 bits, STS.128
#pragma unroll
        for (int l = 0; l < 4; l++) {
            int row = rowL + 32 * l;
            float4 v = pA[l];
            float4 u = make_float4(__uint_as_float(f2tf(v.x)), __uint_as_float(f2tf(v.y)),
                                   __uint_as_float(f2tf(v.z)), __uint_as_float(f2tf(v.w)));
            *reinterpret_cast<float4*>(smem + (c & 1) * 2 * BUF_F + row * LDT + qL * 4) = u;
        }
        // issue B(c+1), ensure B(c) done
        if (c + 1 < nchunk) {
            const int kb = (c + 1) * 32;
            const uint32_t bufo2 = (uint32_t)(((c + 1) & 1) * 2 * BUF_F) << 2;
#pragma unroll
            for (int l = 0; l < 4; l++) {
                int row = rowL + 32 * l;
                cp16(smem_b + bufo2 + (uint32_t)((BUF_F + row * LDT + qL * 4) << 2),
                     Bt + (size_t)row * K + kb + qL * 4);
            }
            asm volatile("cp.async.commit_group;");
            asm volatile("cp.async.wait_group 1;");
        } else {
            asm volatile("cp.async.wait_group 0;");
        }
        __syncthreads();
        // prefetch A(c+1) into regs (latency hidden by compute)
        if (c + 1 < nchunk) {
            const int kb = (c + 1) * 32;
#pragma unroll
            for (int l = 0; l < 4; l++) {
                int m = m0 + rowL + 32 * l;
                pA[l] = (m < M) ? *reinterpret_cast<const float4*>(A + (size_t)m * K + kb + qL * 4)
                                : make_float4(0.f, 0.f, 0.f, 0.f);
            }
        }
        // compute from buf (c&1) via ldmatrix
        const uint32_t Asb = smem_b + bufo;
        const uint32_t Bsb = Asb + (uint32_t)(BUF_F << 2);
#pragma unroll
        for (int ks = 0; ks < 4; ks++) {
            uint32_t af[2][4], bf[8][2];
            ldsm4(af[0], Asb + offA + (uint32_t)((ks * 8) << 2));
            ldsm4(af[1], Asb + offA + (uint32_t)((16 * LDT + ks * 8) << 2));
#pragma unroll
            for (int na2 = 0; na2 < 8; na2 += 2) {
                uint32_t t[4];
                ldsm4(t, Bsb + offB + (uint32_t)((na2 * 8 * LDT + ks * 8) << 2));
                bf[na2][0] = t[0]; bf[na2][1] = t[1];
                bf[na2 + 1][0] = t[2]; bf[na2 + 1][1] = t[3];
            }
#pragma unroll
            for (int ma = 0; ma < 2; ma++)
#pragma unroll
                for (int na = 0; na < 8; na++)
                    mma_tf32(acc[ma][na], af[ma], bf[na]);
        }
        __syncthreads();
    }

    // -------- epilogue --------
    if (!semantic) {
#pragma unroll
        for (int ma = 0; ma < 2; ma++) {
            int row = m0 + mbase + ma * 16 + group;
#pragma unroll
            for (int na = 0; na < 8; na++) {
                int col = nbase + na * 8 + tig * 2;
                if (row < M) {
                    float2 v = { acc[ma][na][0] + s_bias[col],
                                 acc[ma][na][1] + s_bias[col + 1] };
                    *reinterpret_cast<float2*>(C + (size_t)row * 128 + col) = v;
                }
                if (row + 8 < M) {
                    float2 v = { acc[ma][na][2] + s_bias[col],
                                 acc[ma][na][3] + s_bias[col + 1] };
                    *reinterpret_cast<float2*>(C + (size_t)(row + 8) * 128 + col) = v;
                }
            }
        }
    } else {
#pragma unroll
        for (int na = 0; na < 8; na++) {
            int col = nbase + na * 8 + tig * 2;
            float p0 = 0.f, p1 = 0.f;
#pragma unroll
            for (int ma = 0; ma < 2; ma++) {
                int row = m0 + mbase + ma * 16 + group;
                if (row < M) {
                    p0 += tanhf(acc[ma][na][0] + s_bias[col]);
                    p1 += tanhf(acc[ma][na][1] + s_bias[col + 1]);
                }
                if (row + 8 < M) {
                    p0 += tanhf(acc[ma][na][2] + s_bias[col]);
                    p1 += tanhf(acc[ma][na][3] + s_bias[col + 1]);
                }
            }
            atomicAdd(&s_col[col], p0);
            atomicAdd(&s_col[col + 1], p1);
        }
        __syncthreads();
        if (tid < 128) atomicAdd(&C[tid], s_col[tid]);
    }
}

// ---------------- attention dots, both node types in one launch ----------------
__global__ void att_all(const float* __restrict__ hN, const float* __restrict__ hI,
                        const float* __restrict__ v0, const float* __restrict__ v1,
                        const float* __restrict__ v2, const float* __restrict__ v3,
                        float* __restrict__ o0, float* __restrict__ o1,
                        float* __restrict__ o2, float* __restrict__ o3, int nbA)
{
    __shared__ float sv[4][128];
    if (threadIdx.x < 128) {
        sv[0][threadIdx.x] = v0[threadIdx.x];
        sv[1][threadIdx.x] = v1[threadIdx.x];
        sv[2][threadIdx.x] = v2[threadIdx.x];
        sv[3][threadIdx.x] = v3[threadIdx.x];
    }
    __syncthreads();
    if ((int)blockIdx.x < nbA) {
        int i = blockIdx.x * blockDim.x + threadIdx.x;
        if (i < N_NEWS * NH) {
            int n = i >> 3, hh = i & 7;
            const float* hp = hN + (size_t)n * HID + hh * HD;
            float s0 = 0.f, s1 = 0.f, s2 = 0.f;
#pragma unroll
            for (int d = 0; d < HD; d++) {
                float x = hp[d];
                s0 += x * sv[0][hh * HD + d];
                s1 += x * sv[1][hh * HD + d];
                s2 += x * sv[2][hh * HD + d];
            }
            o0[i] = s0; o1[i] = s1; o2[i] = s2;
        }
    } else {
        int i = (blockIdx.x - nbA) * blockDim.x + threadIdx.x;
        if (i < N_INTER * NH) {
            int n = i >> 3, hh = i & 7;
            const float* hp = hI + (size_t)n * HID + hh * HD;
            float s = 0.f;
#pragma unroll
            for (int d = 0; d < HD; d++) s += hp[d] * sv[3][hh * HD + d];
            o3[i] = s;
        }
    }
}

// ---------------- CSR build (merged dual-edge-type kernels) ----------------
__global__ void hist2(const int* __restrict__ e1, int E1, int* __restrict__ d1,
                      const int* __restrict__ e2, int E2, int* __restrict__ d2, int nb1)
{
    if ((int)blockIdx.x < nb1) {
        int e = blockIdx.x * blockDim.x + threadIdx.x;
        if (e < E1) atomicAdd(&d1[e1[E1 + e]], 1);
    } else {
        int e = (blockIdx.x - nb1) * blockDim.x + threadIdx.x;
        if (e < E2) atomicAdd(&d2[e2[E2 + e]], 1);
    }
}

// 2 blocks; block b scans its own deg array (n<=32768).
// All global IO grid-stride coalesced via smem staging; scan itself is
// register-resident with shfl reductions.
__global__ __launch_bounds__(1024)
void scan2(const int* __restrict__ degA, int* __restrict__ rpA, int* __restrict__ curA,
           const int* __restrict__ degB, int* __restrict__ rpB, int* __restrict__ curB,
           int n)
{
    extern __shared__ int sdeg[];                  // n ints (120 KB for n=30000)
    __shared__ int wsum[32];
    const int* deg = blockIdx.x ? degB : degA;
    int* rowptr    = blockIdx.x ? rpB  : rpA;
    int* cursor    = blockIdx.x ? curB : curA;

    const int t = threadIdx.x, lane = t & 31, wid = t >> 5;
    const int chunk = (n + 1023) >> 10;            // <=32
    const int b = t * chunk;

    // coalesced load into smem
    for (int i = t; i < n; i += 1024) sdeg[i] = deg[i];
    __syncthreads();

    // per-thread local exclusive prefix from smem (blocked ownership)
    int v[32];
    int sum = 0;
#pragma unroll
    for (int i = 0; i < 32; i++) {
        if (i < chunk) {
            int idx = b + i;
            int x = (idx < n) ? sdeg[idx] : 0;
            v[i] = sum;
            sum += x;
        }
    }
    // warp-inclusive scan of per-thread sums
    int inc = sum;
#pragma unroll
    for (int off = 1; off < 32; off <<= 1) {
        int y = __shfl_up_sync(0xffffffffu, inc, off);
        if (lane >= off) inc += y;
    }
    if (lane == 31) wsum[wid] = inc;
    __syncthreads();
    if (wid == 0) {
        int ws = wsum[lane];
        int winc = ws;
#pragma unroll
        for (int off = 1; off < 32; off <<= 1) {
            int y = __shfl_up_sync(0xffffffffu, winc, off);
            if (lane >= off) winc += y;
        }
        wsum[lane] = winc - ws;                    // exclusive warp base
    }
    __syncthreads();
    const int base = wsum[wid] + (inc - sum);      // global exclusive base for this thread
    // write prefix back into smem (blocked; bank conflicts only)
#pragma unroll
    for (int i = 0; i < 32; i++) {
        if (i < chunk) {
            int idx = b + i;
            if (idx < n) sdeg[idx] = base + v[i];
        }
    }
    __syncthreads();
    // coalesced store to rowptr + cursor
    for (int i = t; i < n; i += 1024) {
        int val = sdeg[i];
        rowptr[i] = val;
        cursor[i] = val;
    }
    if (t == 1023) rowptr[n] = base + sum;         // grand total (last thread)
}

__global__ void scatter2(const int* __restrict__ e1, int E1, int* __restrict__ c1, int* __restrict__ s1,
                         const int* __restrict__ e2, int E2, int* __restrict__ c2, int* __restrict__ s2,
                         int nb1)
{
    if ((int)blockIdx.x < nb1) {
        int e = blockIdx.x * blockDim.x + threadIdx.x;
        if (e < E1) { int pos = atomicAdd(&c1[e1[E1 + e]], 1); s1[pos] = e1[e]; }
    } else {
        int e = (blockIdx.x - nb1) * blockDim.x + threadIdx.x;
        if (e < E2) { int pos = atomicAdd(&c2[e2[E2 + e]], 1); s2[pos] = e2[e]; }
    }
}

// ---------------- fused single-pass softmax-aggregation: warp per dst node ----------------
// out[d,:] = relu( (sum_e exp(e)*h_src[e,:]) / (sum_e exp(e) + eps) )
// 2-way unrolled to double gather MLP.
__global__ __launch_bounds__(256)
void han_agg2(const int* __restrict__ rp1, const int* __restrict__ csr1,
              const float* __restrict__ as1, const float* __restrict__ ad1,
              const float* __restrict__ h1, float* __restrict__ o1,
              const int* __restrict__ rp2, const int* __restrict__ csr2,
              const float* __restrict__ as2, const float* __restrict__ ad2,
              const float* __restrict__ h2, float* __restrict__ o2)
{
    int gtid = blockIdx.x * blockDim.x + threadIdx.x;
    int w = gtid >> 5;
    int lane = threadIdx.x & 31;

    const int* rowptr; const int* csr; const float* asrc; const float* adst;
    const float* hsrc; float* out; int d;
    if (w < N_NEWS) {
        d = w; rowptr = rp1; csr = csr1; asrc = as1; adst = ad1; hsrc = h1; out = o1;
    } else if (w < 2 * N_NEWS) {
        d = w - N_NEWS; rowptr = rp2; csr = csr2; asrc = as2; adst = ad2; hsrc = h2; out = o2;
    } else return;

    const int beg = rowptr[d], end = rowptr[d + 1];
    const int deg = end - beg;
    float4* o = reinterpret_cast<float4*>(out) + (size_t)d * 32 + lane;
    if (deg == 0) { *o = make_float4(0.f, 0.f, 0.f, 0.f); return; }

    const int hh = lane >> 2;
    const float adh = adst[(size_t)d * 8 + hh];
    const float4* h4 = reinterpret_cast<const float4*>(hsrc);

    float den = 0.f, a0 = 0.f, a1 = 0.f, a2 = 0.f, a3 = 0.f;
    int i = 0;
    for (; i + 2 <= deg; i += 2) {
        int sA = csr[beg + i], sB = csr[beg + i + 1];
        float avA = asrc[(size_t)sA * 8 + hh];
        float avB = asrc[(size_t)sB * 8 + hh];
        float4 hA = h4[(size_t)sA * 32 + lane];
        float4 hB = h4[(size_t)sB * 32 + lane];
        float wA = __expf(lrelu02(avA + adh));
        float wB = __expf(lrelu02(avB + adh));
        den += wA + wB;
        a0 += hA.x * wA + hB.x * wB;
        a1 += hA.y * wA + hB.y * wB;
        a2 += hA.z * wA + hB.z * wB;
        a3 += hA.w * wA + hB.w * wB;
    }
    if (i < deg) {
        int s = csr[beg + i];
        float av = asrc[(size_t)s * 8 + hh];
        float4 hv = h4[(size_t)s * 32 + lane];
        float wgt = __expf(lrelu02(av + adh));
        den += wgt;
        a0 += hv.x * wgt; a1 += hv.y * wgt;
        a2 += hv.z * wgt; a3 += hv.w * wgt;
    }
    float invd = 1.f / (den + 1e-16f);
    *o = make_float4(fmaxf(a0 * invd, 0.f), fmaxf(a1 * invd, 0.f),
                     fmaxf(a2 * invd, 0.f), fmaxf(a3 * invd, 0.f));
}

// ---------------- semantic softmax beta ----------------
__global__ void beta_kernel(const float* __restrict__ acc, const float* __restrict__ q,
                            float* __restrict__ beta)
{
    __shared__ float red[2][4];
    int t = threadIdx.x;  // 128 threads
    float s0 = q[t] * acc[t]       * (1.f / N_NEWS);
    float s1 = q[t] * acc[128 + t] * (1.f / N_NEWS);
#pragma unroll
    for (int off = 16; off; off >>= 1) {
        s0 += __shfl_down_sync(0xffffffffu, s0, off);
        s1 += __shfl_down_sync(0xffffffffu, s1, off);
    }
    if ((t & 31) == 0) { red[0][t >> 5] = s0; red[1][t >> 5] = s1; }
    __syncthreads();
    if (t == 0) {
        float sc0 = red[0][0] + red[0][1] + red[0][2] + red[0][3];
        float sc1 = red[1][0] + red[1][1] + red[1][2] + red[1][3];
        float mx = fmaxf(sc0, sc1);
        float e0 = __expf(sc0 - mx), e1 = __expf(sc1 - mx);
        float inv = 1.f / (e0 + e1);
        beta[0] = e0 * inv;
        beta[1] = e1 * inv;
    }
}

// ---------------- final: fuse + ELU + [128x4] head (warp per node) ----------------
__global__ void final_kernel(const float* __restrict__ onn, const float* __restrict__ oin,
                             const float* __restrict__ beta, const float* __restrict__ Wout,
                             const float* __restrict__ bout, float* __restrict__ y)
{
    __shared__ float sw[HID * 4];
    for (int i = threadIdx.x; i < HID * 4; i += blockDim.x) sw[i] = Wout[i];
    __syncthreads();

    int gtid = blockIdx.x * blockDim.x + threadIdx.x;
    int node = gtid >> 5;
    int lane = threadIdx.x & 31;
    if (node >= N_NEWS) return;

    float b0 = beta[0], b1 = beta[1];
    float4 a = reinterpret_cast<const float4*>(onn)[(size_t)node * 32 + lane];
    float4 b = reinterpret_cast<const float4*>(oin)[(size_t)node * 32 + lane];
    float f[4] = { b0 * a.x + b1 * b.x, b0 * a.y + b1 * b.y,
                   b0 * a.z + b1 * b.z, b0 * a.w + b1 * b.w };   // inputs already relu'd
#pragma unroll
    for (int u = 0; u < 4; u++) f[u] = f[u] > 0.f ? f[u] : (__expf(f[u]) - 1.f);

    float p[4] = { 0.f, 0.f, 0.f, 0.f };
#pragma unroll
    for (int u = 0; u < 4; u++) {
        int r = lane * 4 + u;
#pragma unroll
        for (int c = 0; c < 4; c++) p[c] += f[u] * sw[r * 4 + c];
    }
#pragma unroll
    for (int off = 16; off; off >>= 1)
#pragma unroll
        for (int c = 0; c < 4; c++) p[c] += __shfl_down_sync(0xffffffffu, p[c], off);
    if (lane == 0) {
#pragma unroll
        for (int c = 0; c < 4; c++) y[(size_t)node * 4 + c] = p[c] + bout[c];
    }
}

// ---------------- host ----------------
static inline int cdiv(int a, int b) { return (a + b - 1) / b; }

extern "C" void kernel_launch(void* const* d_in, const int* in_sizes, int n_in,
                              void* d_out, int out_size)
{
    const float* x_news   = (const float*)d_in[0];
    const float* x_inter  = (const float*)d_in[1];
    const int*   edge_nn  = (const int*)  d_in[2];
    const int*   edge_in  = (const int*)  d_in[3];
    const float* W_news   = (const float*)d_in[4];
    const float* b_news   = (const float*)d_in[5];
    const float* W_inter  = (const float*)d_in[6];
    const float* b_inter  = (const float*)d_in[7];
    const float* a_src_nn = (const float*)d_in[8];
    const float* a_dst_nn = (const float*)d_in[9];
    const float* a_src_in = (const float*)d_in[10];
    const float* a_dst_in = (const float*)d_in[11];
    const float* Wk       = (const float*)d_in[12];
    const float* bk       = (const float*)d_in[13];
    const float* q        = (const float*)d_in[14];
    const float* W_out    = (const float*)d_in[15];
    const float* b_out    = (const float*)d_in[16];
    float* y = (float*)d_out;

    const int E_nn = in_sizes[2] / 2;
    const int E_in = in_sizes[3] / 2;

    float *h_news, *h_inter, *out_nn, *out_in, *BtN, *BtI, *BtK;
    float *asrc_nn, *adst_nn, *asrc_in, *adst_in, *accsem, *beta;
    int *deg_nn, *deg_in, *rp_nn, *rp_in, *cur_nn, *cur_in, *csr_nn, *csr_in;
    cudaGetSymbolAddress((void**)&h_news,  g_h_news);
    cudaGetSymbolAddress((void**)&h_inter, g_h_inter);
    cudaGetSymbolAddress((void**)&out_nn,  g_out_nn);
    cudaGetSymbolAddress((void**)&out_in,  g_out_in);
    cudaGetSymbolAddress((void**)&BtN,     g_BtN);
    cudaGetSymbolAddress((void**)&BtI,     g_BtI);
    cudaGetSymbolAddress((void**)&BtK,     g_BtK);
    cudaGetSymbolAddress((void**)&asrc_nn, g_asrc_nn);
    cudaGetSymbolAddress((void**)&adst_nn, g_adst_nn);
    cudaGetSymbolAddress((void**)&asrc_in, g_asrc_in);
    cudaGetSymbolAddress((void**)&adst_in, g_adst_in);
    cudaGetSymbolAddress((void**)&deg_nn,  g_deg_nn);
    cudaGetSymbolAddress((void**)&deg_in,  g_deg_in);
    cudaGetSymbolAddress((void**)&rp_nn,   g_rp_nn);
    cudaGetSymbolAddress((void**)&rp_in,   g_rp_in);
    cudaGetSymbolAddress((void**)&cur_nn,  g_cur_nn);
    cudaGetSymbolAddress((void**)&cur_in,  g_cur_in);
    cudaGetSymbolAddress((void**)&csr_nn,  g_csr_nn);
    cudaGetSymbolAddress((void**)&csr_in,  g_csr_in);
    cudaGetSymbolAddress((void**)&accsem,  g_accsem);
    cudaGetSymbolAddress((void**)&beta,    g_beta);

    const int T = 256;
    const int SMEM_GEMM = 2 * 2 * BUF_F * 4;   // 73728 bytes
    const int SMEM_SCAN = N_NEWS * 4;          // 120000 bytes
    cudaFuncSetAttribute(mma_gemm, cudaFuncAttributeMaxDynamicSharedMemorySize, SMEM_GEMM);
    cudaFuncSetAttribute(scan2, cudaFuncAttributeMaxDynamicSharedMemorySize, SMEM_SCAN);

    // ---- CSR build + weight prep ----
    zero_deg2<<<cdiv(N_NEWS, T), T>>>(deg_nn, deg_in, N_NEWS);
    transpose_all<<<cdiv(768 * 128, T), T>>>(W_news, W_inter, Wk, BtN, BtI, BtK, accsem);
    {
        int nb1 = cdiv(E_nn, T), nb2 = cdiv(E_in, T);
        hist2<<<nb1 + nb2, T>>>(edge_nn, E_nn, deg_nn, edge_in, E_in, deg_in, nb1);
        scan2<<<2, 1024, SMEM_SCAN>>>(deg_nn, rp_nn, cur_nn, deg_in, rp_in, cur_in, N_NEWS);
        scatter2<<<nb1 + nb2, T>>>(edge_nn, E_nn, cur_nn, csr_nn, edge_in, E_in, cur_in, csr_in, nb1);
    }

    // ---- projections (merged dual-part tf32 mma) ----
    const int nb1 = cdiv(N_NEWS, 128), nb2 = cdiv(N_INTER, 128);
    mma_gemm<<<nb1 + nb2, 256, SMEM_GEMM>>>(x_news, x_inter, BtN, BtI, b_news, b_inter,
                                            h_news, h_inter, N_NEWS, N_INTER, nb1, 768, 0);

    // ---- node-level attention coefficients (one launch) ----
    {
        int nbA = cdiv(N_NEWS * NH, T), nbB = cdiv(N_INTER * NH, T);
        att_all<<<nbA + nbB, T>>>(h_news, h_inter, a_src_nn, a_dst_nn, a_dst_in, a_src_in,
                                  asrc_nn, adst_nn, adst_in, asrc_in, nbA);
    }

    // ---- fused single-pass softmax + aggregation (both edge types, no atomics) ----
    han_agg2<<<cdiv(2 * N_NEWS * 32, T), T>>>(rp_nn, csr_nn, asrc_nn, adst_nn, h_news, out_nn,
                                              rp_in, csr_in, asrc_in, adst_in, h_inter, out_in);

    // ---- semantic attention (merged dual-part) ----
    mma_gemm<<<2 * nb1, 256, SMEM_GEMM>>>(out_nn, out_in, BtK, BtK, bk, bk,
                                          accsem, accsem + 128, N_NEWS, N_NEWS, nb1, 128, 1);
    beta_kernel<<<1, 128>>>(accsem, q, beta);

    // ---- fuse + ELU + output head ----
    final_kernel<<<cdiv(N_NEWS * 32, T), T>>>(out_nn, out_in, beta, W_out, b_out, y);
}

// round 9
// speedup vs baseline: 4.3502x; 1.0640x over previous
#include <cuda_runtime.h>
#include <math.h>
#include <stdint.h>

#define N_NEWS  30000
#define N_INTER 60000
#define HID 128
#define NH  8
#define HD  16
#define E_NN_CAP 480000
#define E_IN_CAP 960000

// ---------------- scratch (static device globals; no allocation) ----------------
__device__ float g_h_news [N_NEWS  * HID];
__device__ float g_h_inter[N_INTER * HID];
__device__ float g_out_nn [N_NEWS  * HID];
__device__ float g_out_in [N_NEWS  * HID];
__device__ float g_BtN    [HID * 768];       // W_news^T, tf32-rounded bits
__device__ float g_BtI    [HID * 768];       // W_inter^T, tf32-rounded bits
__device__ float g_BtK    [HID * HID];       // Wk^T, tf32-rounded bits
__device__ float g_asrc_nn[N_NEWS  * NH];
__device__ float g_adst_nn[N_NEWS  * NH];
__device__ float g_asrc_in[N_INTER * NH];
__device__ float g_adst_in[N_NEWS  * NH];
__device__ int   g_deg_nn [N_NEWS];
__device__ int   g_deg_in [N_NEWS];
__device__ int   g_rp_nn  [N_NEWS + 1];
__device__ int   g_rp_in  [N_NEWS + 1];
__device__ int   g_cur_nn [N_NEWS];
__device__ int   g_cur_in [N_NEWS];
__device__ int   g_csr_nn [E_NN_CAP];
__device__ int   g_csr_in [E_IN_CAP];
__device__ float g_accsem[2 * HID];
__device__ float g_beta  [2];

// ---------------- helpers ----------------
static __device__ __forceinline__ uint32_t smem_u32(const void* p) {
    uint32_t r;
    asm("{ .reg .u64 t; cvta.to.shared.u64 t, %1; cvt.u32.u64 %0, t; }" : "=r"(r) : "l"(p));
    return r;
}
static __device__ __forceinline__ uint32_t f2tf(float x) {
    uint32_t r;
    asm("cvt.rna.tf32.f32 %0, %1;" : "=r"(r) : "f"(x));
    return r;
}
static __device__ __forceinline__ void mma_tf32(float* c, const uint32_t* a, const uint32_t* b) {
    asm volatile(
        "mma.sync.aligned.m16n8k8.row.col.f32.tf32.tf32.f32 "
        "{%0,%1,%2,%3},{%4,%5,%6,%7},{%8,%9},{%0,%1,%2,%3};"
        : "+f"(c[0]), "+f"(c[1]), "+f"(c[2]), "+f"(c[3])
        : "r"(a[0]), "r"(a[1]), "r"(a[2]), "r"(a[3]), "r"(b[0]), "r"(b[1]));
}
static __device__ __forceinline__ void cp16(uint32_t dst, const void* src) {
    asm volatile("cp.async.cg.shared.global [%0], [%1], 16;" :: "r"(dst), "l"(src));
}
static __device__ __forceinline__ void ldsm4(uint32_t* r, uint32_t addr) {
    asm volatile("ldmatrix.sync.aligned.m8n8.x4.shared.b16 {%0,%1,%2,%3}, [%4];"
                 : "=r"(r[0]), "=r"(r[1]), "=r"(r[2]), "=r"(r[3]) : "r"(addr));
}
__device__ __forceinline__ float lrelu02(float x) { return x > 0.f ? x : 0.2f * x; }

// ---------------- setup: zero degree counters ----------------
__global__ void zero_deg2(int* __restrict__ d1, int* __restrict__ d2, int n) {
    int i = blockIdx.x * blockDim.x + threadIdx.x;
    if (i < n) { d1[i] = 0; d2[i] = 0; }
}

// ---------------- transpose + tf32-round all weights + zero accsem ----------------
__global__ void transpose_all(const float* __restrict__ Wn, const float* __restrict__ Wi,
                              const float* __restrict__ Wk,
                              float* __restrict__ BtN, float* __restrict__ BtI,
                              float* __restrict__ BtK, float* __restrict__ accsem)
{
    int i = blockIdx.x * blockDim.x + threadIdx.x;   // over 768*128 (write-coalesced)
    if (i < 768 * 128) {
        int n = i / 768, k = i % 768;
        BtN[i] = __uint_as_float(f2tf(Wn[k * 128 + n]));
        BtI[i] = __uint_as_float(f2tf(Wi[k * 128 + n]));
    }
    if (i < 128 * 128) {
        int n = i >> 7, k = i & 127;
        BtK[i] = __uint_as_float(f2tf(Wk[k * 128 + n]));
    }
    if (i < 2 * HID) accsem[i] = 0.f;
}

// ---------------- tf32 tensor-core GEMM (dual-part merged launch) ----------------
#define LDT 36              // padded row length (floats)
#define BUF_F (128 * LDT)   // floats per (A or B) tile

__global__ __launch_bounds__(256, 2)
void mma_gemm(const float* __restrict__ A1, const float* __restrict__ A2,
              const float* __restrict__ Bt1, const float* __restrict__ Bt2,
              const float* __restrict__ bias1, const float* __restrict__ bias2,
              float* __restrict__ C1, float* __restrict__ C2,
              int M1, int M2, int nb1, int K, int semantic)
{
    extern __shared__ float smem[];     // [2][A + B] tiles
    __shared__ float s_bias[128];
    __shared__ float s_col[128];

    const int tid  = threadIdx.x;
    const int warp = tid >> 5;
    const int lane = tid & 31;
    const int group = lane >> 2, tig = lane & 3;
    const int warpM = warp & 3, warpN = warp >> 2;
    const int mbase = warpM * 32, nbase = warpN * 64;

    const float* A; const float* Bt; const float* bias; float* C; int M, m0;
    if ((int)blockIdx.x < nb1) {
        A = A1; Bt = Bt1; bias = bias1; C = C1; M = M1; m0 = blockIdx.x * 128;
    } else {
        A = A2; Bt = Bt2; bias = bias2; C = C2; M = M2; m0 = (blockIdx.x - nb1) * 128;
    }

    if (tid < 128) { s_bias[tid] = bias[tid]; s_col[tid] = 0.f; }

    float acc[2][8][4];
#pragma unroll
    for (int i = 0; i < 2; i++)
#pragma unroll
        for (int j = 0; j < 8; j++)
#pragma unroll
            for (int l = 0; l < 4; l++) acc[i][j][l] = 0.f;

    const int nchunk = K >> 5;
    const uint32_t smem_b = smem_u32(smem);

    const int rowL = tid >> 3, qL = tid & 7;
    const int blk = lane >> 3, rr = lane & 7;
    const uint32_t offA = (uint32_t)(((mbase + (blk & 1) * 8 + rr) * LDT + (blk >> 1) * 4) * 4);
    const uint32_t offB = (uint32_t)(((nbase + (blk >> 1) * 8 + rr) * LDT + (blk & 1) * 4) * 4);

    // prefetch A chunk 0 into regs
    float4 pA[4];
#pragma unroll
    for (int l = 0; l < 4; l++) {
        int m = m0 + rowL + 32 * l;
        pA[l] = (m < M) ? *reinterpret_cast<const float4*>(A + (size_t)m * K + qL * 4)
                        : make_float4(0.f, 0.f, 0.f, 0.f);
    }
    // cp.async B chunk 0 into buf 0
#pragma unroll
    for (int l = 0; l < 4; l++) {
        int row = rowL + 32 * l;
        cp16(smem_b + (uint32_t)((BUF_F + row * LDT + qL * 4) << 2),
             Bt + (size_t)row * K + qL * 4);
    }
    asm volatile("cp.async.commit_group;");

    for (int c = 0; c < nchunk; c++) {
        const uint32_t bufo = (uint32_t)((c & 1) * 2 * BUF_F) << 2;
        // store A(c): cvt to tf32 bits, STS.128
#pragma unroll
        for (int l = 0; l < 4; l++) {
            int row = rowL + 32 * l;
            float4 v = pA[l];
            float4 u = make_float4(__uint_as_float(f2tf(v.x)), __uint_as_float(f2tf(v.y)),
                                   __uint_as_float(f2tf(v.z)), __uint_as_float(f2tf(v.w)));
            *reinterpret_cast<float4*>(smem + (c & 1) * 2 * BUF_F + row * LDT + qL * 4) = u;
        }
        // issue B(c+1), ensure B(c) done
        if (c + 1 < nchunk) {
            const int kb = (c + 1) * 32;
            const uint32_t bufo2 = (uint32_t)(((c + 1) & 1) * 2 * BUF_F) << 2;
#pragma unroll
            for (int l = 0; l < 4; l++) {
                int row = rowL + 32 * l;
                cp16(smem_b + bufo2 + (uint32_t)((BUF_F + row * LDT + qL * 4) << 2),
                     Bt + (size_t)row * K + kb + qL * 4);
            }
            asm volatile("cp.async.commit_group;");
            asm volatile("cp.async.wait_group 1;");
        } else {
            asm volatile("cp.async.wait_group 0;");
        }
        __syncthreads();
        // prefetch A(c+1) into regs (latency hidden by compute)
        if (c + 1 < nchunk) {
            const int kb = (c + 1) * 32;
#pragma unroll
            for (int l = 0; l < 4; l++) {
                int m = m0 + rowL + 32 * l;
                pA[l] = (m < M) ? *reinterpret_cast<const float4*>(A + (size_t)m * K + kb + qL * 4)
                                : make_float4(0.f, 0.f, 0.f, 0.f);
            }
        }
        // compute from buf (c&1) via ldmatrix
        const uint32_t Asb = smem_b + bufo;
        const uint32_t Bsb = Asb + (uint32_t)(BUF_F << 2);
#pragma unroll
        for (int ks = 0; ks < 4; ks++) {
            uint32_t af[2][4], bf[8][2];
            ldsm4(af[0], Asb + offA + (uint32_t)((ks * 8) << 2));
            ldsm4(af[1], Asb + offA + (uint32_t)((16 * LDT + ks * 8) << 2));
#pragma unroll
            for (int na2 = 0; na2 < 8; na2 += 2) {
                uint32_t t[4];
                ldsm4(t, Bsb + offB + (uint32_t)((na2 * 8 * LDT + ks * 8) << 2));
                bf[na2][0] = t[0]; bf[na2][1] = t[1];
                bf[na2 + 1][0] = t[2]; bf[na2 + 1][1] = t[3];
            }
#pragma unroll
            for (int ma = 0; ma < 2; ma++)
#pragma unroll
                for (int na = 0; na < 8; na++)
                    mma_tf32(acc[ma][na], af[ma], bf[na]);
        }
        __syncthreads();
    }

    // -------- epilogue --------
    if (!semantic) {
#pragma unroll
        for (int ma = 0; ma < 2; ma++) {
            int row = m0 + mbase + ma * 16 + group;
#pragma unroll
            for (int na = 0; na < 8; na++) {
                int col = nbase + na * 8 + tig * 2;
                if (row < M) {
                    float2 v = { acc[ma][na][0] + s_bias[col],
                                 acc[ma][na][1] + s_bias[col + 1] };
                    *reinterpret_cast<float2*>(C + (size_t)row * 128 + col) = v;
                }
                if (row + 8 < M) {
                    float2 v = { acc[ma][na][2] + s_bias[col],
                                 acc[ma][na][3] + s_bias[col + 1] };
                    *reinterpret_cast<float2*>(C + (size_t)(row + 8) * 128 + col) = v;
                }
            }
        }
    } else {
#pragma unroll
        for (int na = 0; na < 8; na++) {
            int col = nbase + na * 8 + tig * 2;
            float p0 = 0.f, p1 = 0.f;
#pragma unroll
            for (int ma = 0; ma < 2; ma++) {
                int row = m0 + mbase + ma * 16 + group;
                if (row < M) {
                    p0 += tanhf(acc[ma][na][0] + s_bias[col]);
                    p1 += tanhf(acc[ma][na][1] + s_bias[col + 1]);
                }
                if (row + 8 < M) {
                    p0 += tanhf(acc[ma][na][2] + s_bias[col]);
                    p1 += tanhf(acc[ma][na][3] + s_bias[col + 1]);
                }
            }
            atomicAdd(&s_col[col], p0);
            atomicAdd(&s_col[col + 1], p1);
        }
        __syncthreads();
        if (tid < 128) atomicAdd(&C[tid], s_col[tid]);
    }
}

// ---------------- attention dots, both node types in one launch ----------------
__global__ void att_all(const float* __restrict__ hN, const float* __restrict__ hI,
                        const float* __restrict__ v0, const float* __restrict__ v1,
                        const float* __restrict__ v2, const float* __restrict__ v3,
                        float* __restrict__ o0, float* __restrict__ o1,
                        float* __restrict__ o2, float* __restrict__ o3, int nbA)
{
    __shared__ float sv[4][128];
    if (threadIdx.x < 128) {
        sv[0][threadIdx.x] = v0[threadIdx.x];
        sv[1][threadIdx.x] = v1[threadIdx.x];
        sv[2][threadIdx.x] = v2[threadIdx.x];
        sv[3][threadIdx.x] = v3[threadIdx.x];
    }
    __syncthreads();
    if ((int)blockIdx.x < nbA) {
        int i = blockIdx.x * blockDim.x + threadIdx.x;
        if (i < N_NEWS * NH) {
            int n = i >> 3, hh = i & 7;
            const float* hp = hN + (size_t)n * HID + hh * HD;
            float s0 = 0.f, s1 = 0.f, s2 = 0.f;
#pragma unroll
            for (int d = 0; d < HD; d++) {
                float x = hp[d];
                s0 += x * sv[0][hh * HD + d];
                s1 += x * sv[1][hh * HD + d];
                s2 += x * sv[2][hh * HD + d];
            }
            o0[i] = s0; o1[i] = s1; o2[i] = s2;
        }
    } else {
        int i = (blockIdx.x - nbA) * blockDim.x + threadIdx.x;
        if (i < N_INTER * NH) {
            int n = i >> 3, hh = i & 7;
            const float* hp = hI + (size_t)n * HID + hh * HD;
            float s = 0.f;
#pragma unroll
            for (int d = 0; d < HD; d++) s += hp[d] * sv[3][hh * HD + d];
            o3[i] = s;
        }
    }
}

// ---------------- CSR build (merged dual-edge-type kernels) ----------------
__global__ void hist2(const int* __restrict__ e1, int E1, int* __restrict__ d1,
                      const int* __restrict__ e2, int E2, int* __restrict__ d2, int nb1)
{
    if ((int)blockIdx.x < nb1) {
        int e = blockIdx.x * blockDim.x + threadIdx.x;
        if (e < E1) atomicAdd(&d1[e1[E1 + e]], 1);
    } else {
        int e = (blockIdx.x - nb1) * blockDim.x + threadIdx.x;
        if (e < E2) atomicAdd(&d2[e2[E2 + e]], 1);
    }
}

// 2 blocks; block b scans its own deg array (n<=32768).
__global__ __launch_bounds__(1024)
void scan2(const int* __restrict__ degA, int* __restrict__ rpA, int* __restrict__ curA,
           const int* __restrict__ degB, int* __restrict__ rpB, int* __restrict__ curB,
           int n)
{
    extern __shared__ int sdeg[];                  // n ints (120 KB for n=30000)
    __shared__ int wsum[32];
    const int* deg = blockIdx.x ? degB : degA;
    int* rowptr    = blockIdx.x ? rpB  : rpA;
    int* cursor    = blockIdx.x ? curB : curA;

    const int t = threadIdx.x, lane = t & 31, wid = t >> 5;
    const int chunk = (n + 1023) >> 10;            // <=32
    const int b = t * chunk;

    // coalesced load into smem
    for (int i = t; i < n; i += 1024) sdeg[i] = deg[i];
    __syncthreads();

    // per-thread local exclusive prefix from smem (blocked ownership)
    int v[32];
    int sum = 0;
#pragma unroll
    for (int i = 0; i < 32; i++) {
        if (i < chunk) {
            int idx = b + i;
            int x = (idx < n) ? sdeg[idx] : 0;
            v[i] = sum;
            sum += x;
        }
    }
    // warp-inclusive scan of per-thread sums
    int inc = sum;
#pragma unroll
    for (int off = 1; off < 32; off <<= 1) {
        int y = __shfl_up_sync(0xffffffffu, inc, off);
        if (lane >= off) inc += y;
    }
    if (lane == 31) wsum[wid] = inc;
    __syncthreads();
    if (wid == 0) {
        int ws = wsum[lane];
        int winc = ws;
#pragma unroll
        for (int off = 1; off < 32; off <<= 1) {
            int y = __shfl_up_sync(0xffffffffu, winc, off);
            if (lane >= off) winc += y;
        }
        wsum[lane] = winc - ws;                    // exclusive warp base
    }
    __syncthreads();
    const int base = wsum[wid] + (inc - sum);      // global exclusive base for this thread
#pragma unroll
    for (int i = 0; i < 32; i++) {
        if (i < chunk) {
            int idx = b + i;
            if (idx < n) sdeg[idx] = base + v[i];
        }
    }
    __syncthreads();
    // coalesced store to rowptr + cursor
    for (int i = t; i < n; i += 1024) {
        int val = sdeg[i];
        rowptr[i] = val;
        cursor[i] = val;
    }
    if (t == 1023) rowptr[n] = base + sum;         // grand total (last thread)
}

__global__ void scatter2(const int* __restrict__ e1, int E1, int* __restrict__ c1, int* __restrict__ s1,
                         const int* __restrict__ e2, int E2, int* __restrict__ c2, int* __restrict__ s2,
                         int nb1)
{
    if ((int)blockIdx.x < nb1) {
        int e = blockIdx.x * blockDim.x + threadIdx.x;
        if (e < E1) { int pos = atomicAdd(&c1[e1[E1 + e]], 1); s1[pos] = e1[e]; }
    } else {
        int e = (blockIdx.x - nb1) * blockDim.x + threadIdx.x;
        if (e < E2) { int pos = atomicAdd(&c2[e2[E2 + e]], 1); s2[pos] = e2[e]; }
    }
}

// ---------------- fused single-pass softmax-aggregation: warp per dst node ----------------
// out[d,:] = relu( (sum_e exp(e)*h_src[e,:]) / (sum_e exp(e) + eps) )
// 4-way unrolled to maximize gather MLP.
__global__ __launch_bounds__(256)
void han_agg2(const int* __restrict__ rp1, const int* __restrict__ csr1,
              const float* __restrict__ as1, const float* __restrict__ ad1,
              const float* __restrict__ h1, float* __restrict__ o1,
              const int* __restrict__ rp2, const int* __restrict__ csr2,
              const float* __restrict__ as2, const float* __restrict__ ad2,
              const float* __restrict__ h2, float* __restrict__ o2)
{
    int gtid = blockIdx.x * blockDim.x + threadIdx.x;
    int w = gtid >> 5;
    int lane = threadIdx.x & 31;

    const int* rowptr; const int* csr; const float* asrc; const float* adst;
    const float* hsrc; float* out; int d;
    if (w < N_NEWS) {
        d = w; rowptr = rp1; csr = csr1; asrc = as1; adst = ad1; hsrc = h1; out = o1;
    } else if (w < 2 * N_NEWS) {
        d = w - N_NEWS; rowptr = rp2; csr = csr2; asrc = as2; adst = ad2; hsrc = h2; out = o2;
    } else return;

    const int beg = rowptr[d], end = rowptr[d + 1];
    const int deg = end - beg;
    float4* o = reinterpret_cast<float4*>(out) + (size_t)d * 32 + lane;
    if (deg == 0) { *o = make_float4(0.f, 0.f, 0.f, 0.f); return; }

    const int hh = lane >> 2;
    const float adh = adst[(size_t)d * 8 + hh];
    const float4* h4 = reinterpret_cast<const float4*>(hsrc);

    float den = 0.f, a0 = 0.f, a1 = 0.f, a2 = 0.f, a3 = 0.f;
    int i = 0;
    for (; i + 4 <= deg; i += 4) {
        int sA = csr[beg + i],     sB = csr[beg + i + 1];
        int sC = csr[beg + i + 2], sD = csr[beg + i + 3];
        float avA = asrc[(size_t)sA * 8 + hh];
        float avB = asrc[(size_t)sB * 8 + hh];
        float avC = asrc[(size_t)sC * 8 + hh];
        float avD = asrc[(size_t)sD * 8 + hh];
        float4 hA = h4[(size_t)sA * 32 + lane];
        float4 hB = h4[(size_t)sB * 32 + lane];
        float4 hC = h4[(size_t)sC * 32 + lane];
        float4 hD = h4[(size_t)sD * 32 + lane];
        float wA = __expf(lrelu02(avA + adh));
        float wB = __expf(lrelu02(avB + adh));
        float wC = __expf(lrelu02(avC + adh));
        float wD = __expf(lrelu02(avD + adh));
        den += (wA + wB) + (wC + wD);
        a0 += hA.x * wA + hB.x * wB + hC.x * wC + hD.x * wD;
        a1 += hA.y * wA + hB.y * wB + hC.y * wC + hD.y * wD;
        a2 += hA.z * wA + hB.z * wB + hC.z * wC + hD.z * wD;
        a3 += hA.w * wA + hB.w * wB + hC.w * wC + hD.w * wD;
    }
    for (; i < deg; i++) {
        int s = csr[beg + i];
        float av = asrc[(size_t)s * 8 + hh];
        float4 hv = h4[(size_t)s * 32 + lane];
        float wgt = __expf(lrelu02(av + adh));
        den += wgt;
        a0 += hv.x * wgt; a1 += hv.y * wgt;
        a2 += hv.z * wgt; a3 += hv.w * wgt;
    }
    float invd = 1.f / (den + 1e-16f);
    *o = make_float4(fmaxf(a0 * invd, 0.f), fmaxf(a1 * invd, 0.f),
                     fmaxf(a2 * invd, 0.f), fmaxf(a3 * invd, 0.f));
}

// ---------------- semantic softmax beta ----------------
__global__ void beta_kernel(const float* __restrict__ acc, const float* __restrict__ q,
                            float* __restrict__ beta)
{
    __shared__ float red[2][4];
    int t = threadIdx.x;  // 128 threads
    float s0 = q[t] * acc[t]       * (1.f / N_NEWS);
    float s1 = q[t] * acc[128 + t] * (1.f / N_NEWS);
#pragma unroll
    for (int off = 16; off; off >>= 1) {
        s0 += __shfl_down_sync(0xffffffffu, s0, off);
        s1 += __shfl_down_sync(0xffffffffu, s1, off);
    }
    if ((t & 31) == 0) { red[0][t >> 5] = s0; red[1][t >> 5] = s1; }
    __syncthreads();
    if (t == 0) {
        float sc0 = red[0][0] + red[0][1] + red[0][2] + red[0][3];
        float sc1 = red[1][0] + red[1][1] + red[1][2] + red[1][3];
        float mx = fmaxf(sc0, sc1);
        float e0 = __expf(sc0 - mx), e1 = __expf(sc1 - mx);
        float inv = 1.f / (e0 + e1);
        beta[0] = e0 * inv;
        beta[1] = e1 * inv;
    }
}

// ---------------- final: fuse + ELU + [128x4] head (warp per node) ----------------
__global__ void final_kernel(const float* __restrict__ onn, const float* __restrict__ oin,
                             const float* __restrict__ beta, const float* __restrict__ Wout,
                             const float* __restrict__ bout, float* __restrict__ y)
{
    __shared__ float sw[HID * 4];
    for (int i = threadIdx.x; i < HID * 4; i += blockDim.x) sw[i] = Wout[i];
    __syncthreads();

    int gtid = blockIdx.x * blockDim.x + threadIdx.x;
    int node = gtid >> 5;
    int lane = threadIdx.x & 31;
    if (node >= N_NEWS) return;

    float b0 = beta[0], b1 = beta[1];
    float4 a = reinterpret_cast<const float4*>(onn)[(size_t)node * 32 + lane];
    float4 b = reinterpret_cast<const float4*>(oin)[(size_t)node * 32 + lane];
    float f[4] = { b0 * a.x + b1 * b.x, b0 * a.y + b1 * b.y,
                   b0 * a.z + b1 * b.z, b0 * a.w + b1 * b.w };   // inputs already relu'd
#pragma unroll
    for (int u = 0; u < 4; u++) f[u] = f[u] > 0.f ? f[u] : (__expf(f[u]) - 1.f);

    float p[4] = { 0.f, 0.f, 0.f, 0.f };
#pragma unroll
    for (int u = 0; u < 4; u++) {
        int r = lane * 4 + u;
#pragma unroll
        for (int c = 0; c < 4; c++) p[c] += f[u] * sw[r * 4 + c];
    }
#pragma unroll
    for (int off = 16; off; off >>= 1)
#pragma unroll
        for (int c = 0; c < 4; c++) p[c] += __shfl_down_sync(0xffffffffu, p[c], off);
    if (lane == 0) {
#pragma unroll
        for (int c = 0; c < 4; c++) y[(size_t)node * 4 + c] = p[c] + bout[c];
    }
}

// ---------------- host ----------------
static inline int cdiv(int a, int b) { return (a + b - 1) / b; }

extern "C" void kernel_launch(void* const* d_in, const int* in_sizes, int n_in,
                              void* d_out, int out_size)
{
    const float* x_news   = (const float*)d_in[0];
    const float* x_inter  = (const float*)d_in[1];
    const int*   edge_nn  = (const int*)  d_in[2];
    const int*   edge_in  = (const int*)  d_in[3];
    const float* W_news   = (const float*)d_in[4];
    const float* b_news   = (const float*)d_in[5];
    const float* W_inter  = (const float*)d_in[6];
    const float* b_inter  = (const float*)d_in[7];
    const float* a_src_nn = (const float*)d_in[8];
    const float* a_dst_nn = (const float*)d_in[9];
    const float* a_src_in = (const float*)d_in[10];
    const float* a_dst_in = (const float*)d_in[11];
    const float* Wk       = (const float*)d_in[12];
    const float* bk       = (const float*)d_in[13];
    const float* q        = (const float*)d_in[14];
    const float* W_out    = (const float*)d_in[15];
    const float* b_out    = (const float*)d_in[16];
    float* y = (float*)d_out;

    const int E_nn = in_sizes[2] / 2;
    const int E_in = in_sizes[3] / 2;

    float *h_news, *h_inter, *out_nn, *out_in, *BtN, *BtI, *BtK;
    float *asrc_nn, *adst_nn, *asrc_in, *adst_in, *accsem, *beta;
    int *deg_nn, *deg_in, *rp_nn, *rp_in, *cur_nn, *cur_in, *csr_nn, *csr_in;
    cudaGetSymbolAddress((void**)&h_news,  g_h_news);
    cudaGetSymbolAddress((void**)&h_inter, g_h_inter);
    cudaGetSymbolAddress((void**)&out_nn,  g_out_nn);
    cudaGetSymbolAddress((void**)&out_in,  g_out_in);
    cudaGetSymbolAddress((void**)&BtN,     g_BtN);
    cudaGetSymbolAddress((void**)&BtI,     g_BtI);
    cudaGetSymbolAddress((void**)&BtK,     g_BtK);
    cudaGetSymbolAddress((void**)&asrc_nn, g_asrc_nn);
    cudaGetSymbolAddress((void**)&adst_nn, g_adst_nn);
    cudaGetSymbolAddress((void**)&asrc_in, g_asrc_in);
    cudaGetSymbolAddress((void**)&adst_in, g_adst_in);
    cudaGetSymbolAddress((void**)&deg_nn,  g_deg_nn);
    cudaGetSymbolAddress((void**)&deg_in,  g_deg_in);
    cudaGetSymbolAddress((void**)&rp_nn,   g_rp_nn);
    cudaGetSymbolAddress((void**)&rp_in,   g_rp_in);
    cudaGetSymbolAddress((void**)&cur_nn,  g_cur_nn);
    cudaGetSymbolAddress((void**)&cur_in,  g_cur_in);
    cudaGetSymbolAddress((void**)&csr_nn,  g_csr_nn);
    cudaGetSymbolAddress((void**)&csr_in,  g_csr_in);
    cudaGetSymbolAddress((void**)&accsem,  g_accsem);
    cudaGetSymbolAddress((void**)&beta,    g_beta);

    // lazy one-time side stream + fork/join events (created on the uncaptured
    // correctness call; no device-memory allocation involved)
    static cudaStream_t s_side = nullptr;
    static cudaEvent_t  s_fork = nullptr, s_join = nullptr;
    if (!s_side) {
        cudaStreamCreateWithFlags(&s_side, cudaStreamNonBlocking);
        cudaEventCreateWithFlags(&s_fork, cudaEventDisableTiming);
        cudaEventCreateWithFlags(&s_join, cudaEventDisableTiming);
    }

    const int T = 256;
    const int SMEM_GEMM = 2 * 2 * BUF_F * 4;   // 73728 bytes
    const int SMEM_SCAN = N_NEWS * 4;          // 120000 bytes
    cudaFuncSetAttribute(mma_gemm, cudaFuncAttributeMaxDynamicSharedMemorySize, SMEM_GEMM);
    cudaFuncSetAttribute(scan2, cudaFuncAttributeMaxDynamicSharedMemorySize, SMEM_SCAN);

    // ---- fork: CSR build on side stream, GEMM chain on main stream ----
    cudaEventRecord(s_fork, 0);
    cudaStreamWaitEvent(s_side, s_fork, 0);

    {   // CSR build (side stream)
        int nbe1 = cdiv(E_nn, T), nbe2 = cdiv(E_in, T);
        zero_deg2<<<cdiv(N_NEWS, T), T, 0, s_side>>>(deg_nn, deg_in, N_NEWS);
        hist2<<<nbe1 + nbe2, T, 0, s_side>>>(edge_nn, E_nn, deg_nn, edge_in, E_in, deg_in, nbe1);
        scan2<<<2, 1024, SMEM_SCAN, s_side>>>(deg_nn, rp_nn, cur_nn, deg_in, rp_in, cur_in, N_NEWS);
        scatter2<<<nbe1 + nbe2, T, 0, s_side>>>(edge_nn, E_nn, cur_nn, csr_nn,
                                                edge_in, E_in, cur_in, csr_in, nbe1);
        cudaEventRecord(s_join, s_side);
    }

    // ---- main stream: weight prep + projections + attention dots ----
    transpose_all<<<cdiv(768 * 128, T), T>>>(W_news, W_inter, Wk, BtN, BtI, BtK, accsem);
    const int nb1 = cdiv(N_NEWS, 128), nb2 = cdiv(N_INTER, 128);
    mma_gemm<<<nb1 + nb2, 256, SMEM_GEMM>>>(x_news, x_inter, BtN, BtI, b_news, b_inter,
                                            h_news, h_inter, N_NEWS, N_INTER, nb1, 768, 0);
    {
        int nbA = cdiv(N_NEWS * NH, T), nbB = cdiv(N_INTER * NH, T);
        att_all<<<nbA + nbB, T>>>(h_news, h_inter, a_src_nn, a_dst_nn, a_dst_in, a_src_in,
                                  asrc_nn, adst_nn, adst_in, asrc_in, nbA);
    }

    // ---- join: aggregation needs CSR + h + att ----
    cudaStreamWaitEvent(0, s_join, 0);
    han_agg2<<<cdiv(2 * N_NEWS * 32, T), T>>>(rp_nn, csr_nn, asrc_nn, adst_nn, h_news, out_nn,
                                              rp_in, csr_in, asrc_in, adst_in, h_inter, out_in);

    // ---- semantic attention (merged dual-part) ----
    mma_gemm<<<2 * nb1, 256, SMEM_GEMM>>>(out_nn, out_in, BtK, BtK, bk, bk,
                                          accsem, accsem + 128, N_NEWS, N_NEWS, nb1, 128, 1);
    beta_kernel<<<1, 128>>>(accsem, q, beta);

    // ---- fuse + ELU + output head ----
    final_kernel<<<cdiv(N_NEWS * 32, T), T>>>(out_nn, out_in, beta, W_out, b_out, y);
}